// round 1
// baseline (speedup 1.0000x reference)
#include <cuda_runtime.h>

// Problem constants
#define B_   32
#define T_   256
#define N_   4096
#define D_   256
#define M_   (B_ * T_)        // 8192 rows (b,t)
#define EPSF 1e-6f
#define DECF 0.97f

// ---------------- scratch (device globals; no allocation) ----------------
__device__ float g_X [(long long)M_ * N_];   // P then xhat then y   (134 MB)
__device__ float g_CS[M_];                   // per-(b,t) column sums of P
__device__ float g_Cc[M_];                   // 1/(s_t + eps)
__device__ float g_U [M_ * D_];              // LN(v_prev)
__device__ float g_S [(long long)B_ * T_ * T_]; // decayed scores
__device__ float g_A [M_ * D_];              // a_star
__device__ float g_O [M_ * D_];              // y @ E^T before final LN
__device__ float g_DEC[T_];                  // 0.97^L, built iteratively

// ---------------- helpers ----------------
__device__ __forceinline__ float blockReduceSum256(float v) {
    __shared__ float sh[8];
    __syncthreads();  // protect shared reuse across calls
    int lane = threadIdx.x & 31;
    int w    = threadIdx.x >> 5;
#pragma unroll
    for (int o = 16; o > 0; o >>= 1) v += __shfl_down_sync(0xffffffffu, v, o);
    if (lane == 0) sh[w] = v;
    __syncthreads();
    if (w == 0) {
        float t = (lane < 8) ? sh[lane] : 0.f;
#pragma unroll
        for (int o = 4; o > 0; o >>= 1) t += __shfl_down_sync(0xffffffffu, t, o);
        if (lane == 0) sh[0] = t;
    }
    __syncthreads();
    return sh[0];
}

__global__ void init_dec_kernel() {
    // iterative product to match the reference's repeated *0.97 rounding
    float d = 1.f;
    for (int i = 0; i < T_; i++) { g_DEC[i] = d; d *= DECF; }
}

// ---------------- generic NT GEMM: C[m,n] = sum_k A[m,k]*B[n,k] ----------------
// Block tile 128x64, BK=16, 256 threads, 8x4 per-thread microtile.
#define GBM 128
#define GBN 64
#define GBK 16
#define GTM 8
#define GTN 4

enum { EPI_NONE = 0, EPI_RELU = 1, EPI_RELUMULX = 2, EPI_DECAY = 3 };

template <bool GATHER, int EPI>
__global__ __launch_bounds__(256)
void gemm_nt(const float* __restrict__ A, const float* __restrict__ B,
             float* __restrict__ C, int M, int Nd, int K,
             long batchA, long batchB, long batchC,
             const int* __restrict__ gidx, const float* __restrict__ Xmul)
{
    const int bz = blockIdx.z;
    A += (long)bz * batchA;
    B += (long)bz * batchB;
    C += (long)bz * batchC;
    const float* xm = (EPI == EPI_RELUMULX) ? (Xmul + (long)bz * batchC) : nullptr;

    const int bm = blockIdx.y * GBM;
    const int bn = blockIdx.x * GBN;

    __shared__ __align__(16) float As[GBK][GBM + 4];
    __shared__ __align__(16) float Bs[GBK][GBN + 4];

    const int tid = threadIdx.x;
    const int tx  = tid & 15;   // 16 col-groups
    const int ty  = tid >> 4;   // 16 row-groups

    float acc[GTM][GTN];
#pragma unroll
    for (int i = 0; i < GTM; i++)
#pragma unroll
        for (int j = 0; j < GTN; j++) acc[i][j] = 0.f;

    // strict-lower-triangular score tiles fully above diagonal: all-zero, skip K loop
    bool skip = (EPI == EPI_DECAY) && (bn >= bm + GBM - 1);

    if (!skip) {
        const int lr = tid >> 2;        // 0..63
        const int lk = (tid & 3) * 4;   // 0,4,8,12
        for (int k0 = 0; k0 < K; k0 += GBK) {
#pragma unroll
            for (int i = 0; i < 2; i++) {
                int r = lr + i * 64;
                long arow = GATHER ? (long)gidx[bm + r] : (long)(bm + r);
                float4 v = *reinterpret_cast<const float4*>(A + arow * K + k0 + lk);
                As[lk + 0][r] = v.x; As[lk + 1][r] = v.y;
                As[lk + 2][r] = v.z; As[lk + 3][r] = v.w;
            }
            {
                float4 v = *reinterpret_cast<const float4*>(B + (long)(bn + lr) * K + k0 + lk);
                Bs[lk + 0][lr] = v.x; Bs[lk + 1][lr] = v.y;
                Bs[lk + 2][lr] = v.z; Bs[lk + 3][lr] = v.w;
            }
            __syncthreads();
#pragma unroll
            for (int kk = 0; kk < GBK; kk++) {
                float af[GTM], bf[GTN];
#pragma unroll
                for (int i = 0; i < GTM; i++) af[i] = As[kk][ty * GTM + i];
#pragma unroll
                for (int j = 0; j < GTN; j++) bf[j] = Bs[kk][tx * GTN + j];
#pragma unroll
                for (int i = 0; i < GTM; i++)
#pragma unroll
                    for (int j = 0; j < GTN; j++)
                        acc[i][j] = fmaf(af[i], bf[j], acc[i][j]);
            }
            __syncthreads();
        }
    }

    // epilogue
#pragma unroll
    for (int i = 0; i < GTM; i++) {
        int row = bm + ty * GTM + i;
        long cbase = (long)row * Nd + bn + tx * GTN;
        float4 o;
        float* po = &o.x;
#pragma unroll
        for (int j = 0; j < GTN; j++) {
            float v = acc[i][j];
            if (EPI == EPI_RELU) {
                v = fmaxf(v, 0.f);
            } else if (EPI == EPI_DECAY) {
                int s = bn + tx * GTN + j;
                int L = row - s;
                v = (L > 0) ? v * g_DEC[L] : 0.f;
            }
            po[j] = v;
        }
        if (EPI == EPI_RELUMULX) {
            float4 xv = *reinterpret_cast<const float4*>(xm + cbase);
            o.x = fmaxf(o.x, 0.f) * xv.x;
            o.y = fmaxf(o.y, 0.f) * xv.y;
            o.z = fmaxf(o.z, 0.f) * xv.z;
            o.w = fmaxf(o.w, 0.f) * xv.w;
        }
        *reinterpret_cast<float4*>(C + cbase) = o;
    }
}

// ---------------- NN GEMM: C[m,n] = sum_k A[m,k]*B[k,n]  (for a* = S @ U) ----------------
__global__ __launch_bounds__(256)
void gemm_nn(const float* __restrict__ A, const float* __restrict__ B,
             float* __restrict__ C, int M, int Nd, int K,
             long batchA, long batchB, long batchC)
{
    const int bz = blockIdx.z;
    A += (long)bz * batchA;
    B += (long)bz * batchB;
    C += (long)bz * batchC;

    const int bm = blockIdx.y * GBM;
    const int bn = blockIdx.x * GBN;

    __shared__ __align__(16) float As[GBK][GBM + 4];
    __shared__ __align__(16) float Bs[GBK][GBN + 4];

    const int tid = threadIdx.x;
    const int tx  = tid & 15;
    const int ty  = tid >> 4;

    float acc[GTM][GTN];
#pragma unroll
    for (int i = 0; i < GTM; i++)
#pragma unroll
        for (int j = 0; j < GTN; j++) acc[i][j] = 0.f;

    const int lr = tid >> 2;
    const int lk = (tid & 3) * 4;
    const int brow = tid >> 4;        // 0..15 (k index)
    const int bcol = (tid & 15) * 4;  // 0..60

    for (int k0 = 0; k0 < K; k0 += GBK) {
#pragma unroll
        for (int i = 0; i < 2; i++) {
            int r = lr + i * 64;
            float4 v = *reinterpret_cast<const float4*>(A + (long)(bm + r) * K + k0 + lk);
            As[lk + 0][r] = v.x; As[lk + 1][r] = v.y;
            As[lk + 2][r] = v.z; As[lk + 3][r] = v.w;
        }
        {
            float4 v = *reinterpret_cast<const float4*>(B + (long)(k0 + brow) * Nd + bn + bcol);
            Bs[brow][bcol + 0] = v.x; Bs[brow][bcol + 1] = v.y;
            Bs[brow][bcol + 2] = v.z; Bs[brow][bcol + 3] = v.w;
        }
        __syncthreads();
#pragma unroll
        for (int kk = 0; kk < GBK; kk++) {
            float af[GTM], bf[GTN];
#pragma unroll
            for (int i = 0; i < GTM; i++) af[i] = As[kk][ty * GTM + i];
#pragma unroll
            for (int j = 0; j < GTN; j++) bf[j] = Bs[kk][tx * GTN + j];
#pragma unroll
            for (int i = 0; i < GTM; i++)
#pragma unroll
                for (int j = 0; j < GTN; j++)
                    acc[i][j] = fmaf(af[i], bf[j], acc[i][j]);
        }
        __syncthreads();
    }

#pragma unroll
    for (int i = 0; i < GTM; i++) {
        int row = bm + ty * GTM + i;
        long cbase = (long)row * Nd + bn + tx * GTN;
        float4 o = make_float4(acc[i][0], acc[i][1], acc[i][2], acc[i][3]);
        *reinterpret_cast<float4*>(C + cbase) = o;
    }
}

// ---------------- elementwise / scan kernels ----------------
__global__ void colsum_kernel() {
    int m = blockIdx.x;
    const float* row = g_X + (long)m * N_;
    float s = 0.f;
    for (int i = threadIdx.x; i < N_; i += 256) s += row[i];
    s = blockReduceSum256(s);
    if (threadIdx.x == 0) g_CS[m] = s;
}

__global__ void screc_kernel() {
    int b = threadIdx.x;
    if (b >= B_) return;
    float sprev = 0.f;
    for (int t = 0; t < T_; t++) {
        float sumx = sprev / (sprev + EPSF);           // sum of normalized x_{t-1}
        float s = DECF * sumx + g_CS[b * T_ + t];      // L1 norm of z_t (all nonneg)
        g_Cc[b * T_ + t] = 1.f / (s + EPSF);
        sprev = s;
    }
}

__global__ void xrecur_kernel() {
    int b = blockIdx.y;
    int n = blockIdx.x * 256 + threadIdx.x;
    __shared__ float sc[T_];
    sc[threadIdx.x] = g_Cc[b * T_ + threadIdx.x];
    __syncthreads();
    float x = 0.f;
    long base = (long)b * T_ * N_ + n;
    for (int t = 0; t < T_; t++) {
        float p = g_X[base + (long)t * N_];
        x = (DECF * x + p) * sc[t];
        g_X[base + (long)t * N_] = x;
    }
}

// LN over rows of length 256 (ddof=1, /(std+eps)); optional row gather on input
__global__ void ln_rows_kernel(const float* __restrict__ in, float* __restrict__ out,
                               const int* __restrict__ gidx)
{
    int m = blockIdx.x;
    long r = gidx ? (long)gidx[m] : (long)m;
    float z = in[r * D_ + threadIdx.x];
    float mean = blockReduceSum256(z) * (1.f / D_);
    float d = z - mean;
    float var = blockReduceSum256(d * d) * (1.f / (D_ - 1));
    out[(long)m * D_ + threadIdx.x] = d / (sqrtf(var) + EPSF);
}

// ---------------- launch ----------------
extern "C" void kernel_launch(void* const* d_in, const int* in_sizes, int n_in,
                              void* d_out, int out_size)
{
    (void)in_sizes; (void)n_in; (void)out_size;
    const int*   idx  = (const int*)d_in[0];
    const float* temb = (const float*)d_in[1];
    const float* E    = (const float*)d_in[2];
    const float* Dx   = (const float*)d_in[3];
    const float* Dy   = (const float*)d_in[4];
    float* out = (float*)d_out;

    float *pX, *pU, *pS, *pA, *pO;
    cudaGetSymbolAddress((void**)&pX, g_X);
    cudaGetSymbolAddress((void**)&pU, g_U);
    cudaGetSymbolAddress((void**)&pS, g_S);
    cudaGetSymbolAddress((void**)&pA, g_A);
    cudaGetSymbolAddress((void**)&pO, g_O);

    init_dec_kernel<<<1, 1>>>();

    // G1: P = relu(emb[idx] @ Dx^T)  -> g_X   (M=8192, N=4096, K=256)
    gemm_nt<true, EPI_RELU><<<dim3(N_ / GBN, M_ / GBM, 1), 256>>>(
        temb, Dx, pX, M_, N_, D_, 0, 0, 0, idx, nullptr);

    // per-(b,t) column sums, scalar L1 recurrence, parallel x scan (in-place on g_X)
    colsum_kernel<<<M_, 256>>>();
    screc_kernel<<<1, 32>>>();
    xrecur_kernel<<<dim3(N_ / 256, B_, 1), 256>>>();

    // U = LN(emb[idx])
    ln_rows_kernel<<<M_, 256>>>(temb, pU, idx);

    // Scores: S[b,t,s] = 0.97^(t-s) * <x_s, x_t>, s < t   (batched, K=4096)
    gemm_nt<false, EPI_DECAY><<<dim3(T_ / GBN, T_ / GBM, B_), 256>>>(
        pX, pX, pS, T_, T_, N_,
        (long)T_ * N_, (long)T_ * N_, (long)T_ * T_, nullptr, nullptr);

    // a* = S @ U   (batched NN, 256x256x256)
    gemm_nn<<<dim3(D_ / GBN, T_ / GBM, B_), 256>>>(
        pS, pU, pA, T_, D_, T_,
        (long)T_ * T_, (long)T_ * D_, (long)T_ * D_);

    // a* <- LN(a*)
    ln_rows_kernel<<<M_, 256>>>(pA, pA, nullptr);

    // G2: y = relu(LN(a*) @ Dy^T) * x   (in-place into g_X)
    gemm_nt<false, EPI_RELUMULX><<<dim3(N_ / GBN, M_ / GBM, 1), 256>>>(
        pA, Dy, pX, M_, N_, D_, 0, 0, 0, nullptr, pX);

    // G3: o = y @ E^T   (M=8192, N=256, K=4096)
    gemm_nt<false, EPI_NONE><<<dim3(D_ / GBN, M_ / GBM, 1), 256>>>(
        pX, E, pO, M_, D_, N_, 0, 0, 0, nullptr, nullptr);

    // out = LN(o)
    ln_rows_kernel<<<M_, 256>>>(pO, out, nullptr);
}

// round 3
// speedup vs baseline: 1.7807x; 1.7807x over previous
#include <cuda_runtime.h>
#include <cuda_bf16.h>
#include <cstdint>

#define B_   32
#define T_   256
#define N_   4096
#define D_   256
#define M_   (B_ * T_)
#define EPSF 1e-6f
#define DECF 0.97f

// ---------------- scratch (device globals; no allocation) ----------------
__device__ float g_X [(long long)M_ * N_];      // P (fp32 scan domain)
__device__ float g_CS[M_];
__device__ float g_Cc[M_];
__device__ float g_U [M_ * D_];
__device__ float g_S [(long long)B_ * T_ * T_];
__device__ float g_A [M_ * D_];
__device__ float g_O [M_ * D_];
__device__ float g_DEC[T_];

// bf16 hi/lo split operands
__device__ __nv_bfloat16 g_Vh [M_ * D_],  g_Vl [M_ * D_];     // emb[idx]
__device__ __nv_bfloat16 g_Dxh[N_ * D_],  g_Dxl[N_ * D_];
__device__ __nv_bfloat16 g_Dyh[N_ * D_],  g_Dyl[N_ * D_];
__device__ __nv_bfloat16 g_Eh [D_ * N_],  g_El [D_ * N_];
__device__ __nv_bfloat16 g_Xh [(long long)M_ * N_], g_Xl[(long long)M_ * N_];
__device__ __nv_bfloat16 g_Ah [M_ * D_],  g_Al [M_ * D_];
__device__ __nv_bfloat16 g_Yh [(long long)M_ * N_], g_Yl[(long long)M_ * N_];

// ---------------- PTX helpers (baseline ISA only: sm_80-era) ----------------
__device__ __forceinline__ uint32_t smem_u32(const void* p) {
    uint32_t a;
    asm("{ .reg .u64 t; cvta.to.shared.u64 t, %1; cvt.u32.u64 %0, t; }" : "=r"(a) : "l"(p));
    return a;
}
__device__ __forceinline__ void cp16(uint32_t so, const void* g) {
    asm volatile("cp.async.cg.shared.global [%0], [%1], 16;" :: "r"(so), "l"(g));
}
__device__ __forceinline__ void cp_commit() {
    asm volatile("cp.async.commit_group;" ::: "memory");
}
template <int NN>
__device__ __forceinline__ void cp_wait() {
    asm volatile("cp.async.wait_group %0;" :: "n"(NN) : "memory");
}
__device__ __forceinline__ void ldsm_x4(uint32_t* f, uint32_t a) {
    asm volatile("ldmatrix.sync.aligned.m8n8.x4.shared.b16 {%0,%1,%2,%3}, [%4];"
        : "=r"(f[0]), "=r"(f[1]), "=r"(f[2]), "=r"(f[3]) : "r"(a));
}
__device__ __forceinline__ void ldsm_x2(uint32_t* f, uint32_t a) {
    asm volatile("ldmatrix.sync.aligned.m8n8.x2.shared.b16 {%0,%1}, [%2];"
        : "=r"(f[0]), "=r"(f[1]) : "r"(a));
}
__device__ __forceinline__ void mma16816(float* c, const uint32_t* a, const uint32_t* b) {
    asm volatile("mma.sync.aligned.m16n8k16.row.col.f32.bf16.bf16.f32 "
        "{%0,%1,%2,%3}, {%4,%5,%6,%7}, {%8,%9}, {%0,%1,%2,%3};"
        : "+f"(c[0]), "+f"(c[1]), "+f"(c[2]), "+f"(c[3])
        : "r"(a[0]), "r"(a[1]), "r"(a[2]), "r"(a[3]), "r"(b[0]), "r"(b[1]));
}

// ---------------- HMMA NT GEMM: C[m,n] = sum_k A[m,k]*B[n,k], hi/lo 3-pass ----------------
enum { EPI_NONE = 0, EPI_RELU = 1, EPI_RELUMULX = 2, EPI_DECAY = 3 };

#define ROWB    80                      // padded row stride bytes (32 bf16 + 8 pad)
#define TILE_B  (128 * ROWB)            // 10240
#define STAGE_B (4 * TILE_B)            // Ah, Al, Bh, Bl = 40960
#define SMEM_SZ (2 * STAGE_B)           // 81920

template <int EPI>
__global__ void __launch_bounds__(256, 1) mma_nt(
    const __nv_bfloat16* __restrict__ Ah, const __nv_bfloat16* __restrict__ Al,
    const __nv_bfloat16* __restrict__ Bh, const __nv_bfloat16* __restrict__ Bl,
    float* __restrict__ Cf, __nv_bfloat16* __restrict__ Ch, __nv_bfloat16* __restrict__ Cl,
    const __nv_bfloat16* __restrict__ Xh, const __nv_bfloat16* __restrict__ Xl,
    int Nd, int K, long sA, long sB, long sC)
{
    extern __shared__ char smem[];
    const uint32_t sb = smem_u32(smem);
    const int tid  = threadIdx.x;
    const int lane = tid & 31;
    const int wid  = tid >> 5;
    const int wm   = wid >> 2;          // 0..1  -> m offset wm*64
    const int wn   = wid & 3;           // 0..3  -> n offset wn*32
    const int bz = blockIdx.z;
    const int bm = blockIdx.y * 128;
    const int bn = blockIdx.x * 128;
    const bool skip = (EPI == EPI_DECAY) && (bn >= bm + 128);

    float acc[4][4][4];
#pragma unroll
    for (int i = 0; i < 4; i++)
#pragma unroll
        for (int j = 0; j < 4; j++)
#pragma unroll
            for (int v = 0; v < 4; v++) acc[i][j][v] = 0.f;

    if (!skip) {
        const __nv_bfloat16* Ahp = Ah + (long)bz * sA + (long)bm * K;
        const __nv_bfloat16* Alp = Al + (long)bz * sA + (long)bm * K;
        const __nv_bfloat16* Bhp = Bh + (long)bz * sB + (long)bn * K;
        const __nv_bfloat16* Blp = Bl + (long)bz * sB + (long)bn * K;

        const int qr0 = tid >> 2;             // row for chunk0 (0..63)
        const int qc0 = tid & 3;              // 16B group
        auto stage_load = [&](int stg, int k0) {
            const __nv_bfloat16* srcs[4] = {Ahp, Alp, Bhp, Blp};
#pragma unroll
            for (int t = 0; t < 4; t++) {
                uint32_t tbase = sb + stg * STAGE_B + t * TILE_B;
#pragma unroll
                for (int i = 0; i < 2; i++) {
                    int r = qr0 + i * 64;
                    cp16(tbase + r * ROWB + qc0 * 16,
                         srcs[t] + (long)r * K + k0 + qc0 * 8);
                }
            }
            cp_commit();
        };

        const int nC = K / 32;
        stage_load(0, 0);

        // per-lane ldmatrix pointers (byte offsets within a stage)
        const uint32_t aRow = (uint32_t)(wm * 64 + (lane & 15));
        const uint32_t aCol = (uint32_t)((lane >> 4) * 8);
        const uint32_t bRow = (uint32_t)(wn * 32 + (lane & 7));
        const uint32_t bCol = (uint32_t)(((lane >> 3) & 1) * 8);

        for (int c = 0; c < nC; c++) {
            const int cur = c & 1;
            if (c + 1 < nC) stage_load(cur ^ 1, (c + 1) * 32);
            if (c + 1 < nC) cp_wait<1>(); else cp_wait<0>();
            __syncthreads();

            const uint32_t st = sb + cur * STAGE_B;
#pragma unroll
            for (int ks = 0; ks < 2; ks++) {
                uint32_t fAh[4][4], fBh[4][2], fAl[4][4], fBl[4][2];
#pragma unroll
                for (int ma = 0; ma < 4; ma++)
                    ldsm_x4(fAh[ma], st + (aRow + ma * 16) * ROWB + (ks * 16 + aCol) * 2);
#pragma unroll
                for (int na = 0; na < 4; na++)
                    ldsm_x2(fBh[na], st + 2 * TILE_B + (bRow + na * 8) * ROWB + (ks * 16 + bCol) * 2);
#pragma unroll
                for (int ma = 0; ma < 4; ma++)
#pragma unroll
                    for (int na = 0; na < 4; na++)
                        mma16816(acc[ma][na], fAh[ma], fBh[na]);
#pragma unroll
                for (int ma = 0; ma < 4; ma++)
                    ldsm_x4(fAl[ma], st + TILE_B + (aRow + ma * 16) * ROWB + (ks * 16 + aCol) * 2);
#pragma unroll
                for (int ma = 0; ma < 4; ma++)
#pragma unroll
                    for (int na = 0; na < 4; na++)
                        mma16816(acc[ma][na], fAl[ma], fBh[na]);
#pragma unroll
                for (int na = 0; na < 4; na++)
                    ldsm_x2(fBl[na], st + 3 * TILE_B + (bRow + na * 8) * ROWB + (ks * 16 + bCol) * 2);
#pragma unroll
                for (int ma = 0; ma < 4; ma++)
#pragma unroll
                    for (int na = 0; na < 4; na++)
                        mma16816(acc[ma][na], fAh[ma], fBl[na]);
            }
            __syncthreads();
        }
    }

    // ---- epilogue ----
    const int gr = lane >> 2;          // 0..7
    const int gc = (lane & 3) * 2;
#pragma unroll
    for (int ma = 0; ma < 4; ma++) {
#pragma unroll
        for (int half = 0; half < 2; half++) {
            const int row = bm + wm * 64 + ma * 16 + gr + half * 8;
#pragma unroll
            for (int na = 0; na < 4; na++) {
                const int col = bn + wn * 32 + na * 8 + gc;
                float v0 = acc[ma][na][half * 2 + 0];
                float v1 = acc[ma][na][half * 2 + 1];
                long off = (long)row * Nd + col;
                if (EPI == EPI_RELUMULX) {
                    ushort2 xh = *reinterpret_cast<const ushort2*>(Xh + off);
                    ushort2 xl = *reinterpret_cast<const ushort2*>(Xl + off);
                    float x0 = __bfloat162float(__ushort_as_bfloat16(xh.x)) +
                               __bfloat162float(__ushort_as_bfloat16(xl.x));
                    float x1 = __bfloat162float(__ushort_as_bfloat16(xh.y)) +
                               __bfloat162float(__ushort_as_bfloat16(xl.y));
                    v0 = fmaxf(v0, 0.f) * x0;
                    v1 = fmaxf(v1, 0.f) * x1;
                    __nv_bfloat16 h0 = __float2bfloat16(v0), h1 = __float2bfloat16(v1);
                    __nv_bfloat16 l0 = __float2bfloat16(v0 - __bfloat162float(h0));
                    __nv_bfloat16 l1 = __float2bfloat16(v1 - __bfloat162float(h1));
                    *reinterpret_cast<ushort2*>(Ch + off) =
                        make_ushort2(__bfloat16_as_ushort(h0), __bfloat16_as_ushort(h1));
                    *reinterpret_cast<ushort2*>(Cl + off) =
                        make_ushort2(__bfloat16_as_ushort(l0), __bfloat16_as_ushort(l1));
                } else {
                    if (EPI == EPI_RELU) { v0 = fmaxf(v0, 0.f); v1 = fmaxf(v1, 0.f); }
                    else if (EPI == EPI_DECAY) {
                        int L0 = row - col, L1 = row - col - 1;
                        v0 = (L0 > 0) ? v0 * g_DEC[L0] : 0.f;
                        v1 = (L1 > 0) ? v1 * g_DEC[L1] : 0.f;
                    }
                    *reinterpret_cast<float2*>(Cf + (long)bz * sC + off) = make_float2(v0, v1);
                }
            }
        }
    }
}

// ---------------- SIMT NN GEMM (a* = S @ U, small) ----------------
#define GBM 128
#define GBN 64
#define GBK 16
#define GTM 8
#define GTN 4

__global__ __launch_bounds__(256)
void gemm_nn(const float* __restrict__ A, const float* __restrict__ B,
             float* __restrict__ C, int M, int Nd, int K,
             long batchA, long batchB, long batchC)
{
    const int bz = blockIdx.z;
    A += (long)bz * batchA;
    B += (long)bz * batchB;
    C += (long)bz * batchC;
    const int bm = blockIdx.y * GBM;
    const int bn = blockIdx.x * GBN;

    __shared__ __align__(16) float As[GBK][GBM + 4];
    __shared__ __align__(16) float Bs[GBK][GBN + 4];

    const int tid = threadIdx.x;
    const int tx = tid & 15;
    const int ty = tid >> 4;

    float acc[GTM][GTN];
#pragma unroll
    for (int i = 0; i < GTM; i++)
#pragma unroll
        for (int j = 0; j < GTN; j++) acc[i][j] = 0.f;

    const int lr = tid >> 2;
    const int lk = (tid & 3) * 4;
    const int brow = tid >> 4;
    const int bcol = (tid & 15) * 4;

    for (int k0 = 0; k0 < K; k0 += GBK) {
#pragma unroll
        for (int i = 0; i < 2; i++) {
            int r = lr + i * 64;
            float4 v = *reinterpret_cast<const float4*>(A + (long)(bm + r) * K + k0 + lk);
            As[lk + 0][r] = v.x; As[lk + 1][r] = v.y;
            As[lk + 2][r] = v.z; As[lk + 3][r] = v.w;
        }
        {
            float4 v = *reinterpret_cast<const float4*>(B + (long)(k0 + brow) * Nd + bn + bcol);
            Bs[brow][bcol + 0] = v.x; Bs[brow][bcol + 1] = v.y;
            Bs[brow][bcol + 2] = v.z; Bs[brow][bcol + 3] = v.w;
        }
        __syncthreads();
#pragma unroll
        for (int kk = 0; kk < GBK; kk++) {
            float af[GTM], bf[GTN];
#pragma unroll
            for (int i = 0; i < GTM; i++) af[i] = As[kk][ty * GTM + i];
#pragma unroll
            for (int j = 0; j < GTN; j++) bf[j] = Bs[kk][tx * GTN + j];
#pragma unroll
            for (int i = 0; i < GTM; i++)
#pragma unroll
                for (int j = 0; j < GTN; j++)
                    acc[i][j] = fmaf(af[i], bf[j], acc[i][j]);
        }
        __syncthreads();
    }
#pragma unroll
    for (int i = 0; i < GTM; i++) {
        int row = bm + ty * GTM + i;
        long cbase = (long)row * Nd + bn + tx * GTN;
        *reinterpret_cast<float4*>(C + cbase) = make_float4(acc[i][0], acc[i][1], acc[i][2], acc[i][3]);
    }
}

// ---------------- elementwise / scan / LN kernels ----------------
__device__ __forceinline__ float blockReduceSum256(float v) {
    __shared__ float sh[8];
    __syncthreads();
    int lane = threadIdx.x & 31;
    int w = threadIdx.x >> 5;
#pragma unroll
    for (int o = 16; o > 0; o >>= 1) v += __shfl_down_sync(0xffffffffu, v, o);
    if (lane == 0) sh[w] = v;
    __syncthreads();
    if (w == 0) {
        float t = (lane < 8) ? sh[lane] : 0.f;
#pragma unroll
        for (int o = 4; o > 0; o >>= 1) t += __shfl_down_sync(0xffffffffu, t, o);
        if (lane == 0) sh[0] = t;
    }
    __syncthreads();
    return sh[0];
}

__global__ void init_dec_kernel() {
    float d = 1.f;
    for (int i = 0; i < T_; i++) { g_DEC[i] = d; d *= DECF; }
}

__global__ void colsum_kernel() {
    int m = blockIdx.x;
    const float* row = g_X + (long)m * N_;
    float s = 0.f;
    for (int i = threadIdx.x; i < N_; i += 256) s += row[i];
    s = blockReduceSum256(s);
    if (threadIdx.x == 0) g_CS[m] = s;
}

__global__ void screc_kernel() {
    int b = threadIdx.x;
    if (b >= B_) return;
    float sprev = 0.f;
    for (int t = 0; t < T_; t++) {
        float sumx = sprev / (sprev + EPSF);
        float s = DECF * sumx + g_CS[b * T_ + t];
        g_Cc[b * T_ + t] = 1.f / (s + EPSF);
        sprev = s;
    }
}

__global__ void xrecur_kernel() {
    int b = blockIdx.y;
    int n = blockIdx.x * 256 + threadIdx.x;
    __shared__ float sc[T_];
    sc[threadIdx.x] = g_Cc[b * T_ + threadIdx.x];
    __syncthreads();
    float x = 0.f;
    long base = (long)b * T_ * N_ + n;
    for (int t = 0; t < T_; t++) {
        float p = g_X[base + (long)t * N_];
        x = (DECF * x + p) * sc[t];
        __nv_bfloat16 h = __float2bfloat16(x);
        g_Xh[base + (long)t * N_] = h;
        g_Xl[base + (long)t * N_] = __float2bfloat16(x - __bfloat162float(h));
    }
}

__global__ void ln_rows_kernel(const float* __restrict__ in, float* __restrict__ out,
                               const int* __restrict__ gidx)
{
    int m = blockIdx.x;
    long r = gidx ? (long)gidx[m] : (long)m;
    float z = in[r * D_ + threadIdx.x];
    float mean = blockReduceSum256(z) * (1.f / D_);
    float d = z - mean;
    float var = blockReduceSum256(d * d) * (1.f / (D_ - 1));
    out[(long)m * D_ + threadIdx.x] = d / (sqrtf(var) + EPSF);
}

__global__ void conv_hilo_kernel(const float* __restrict__ in,
                                 __nv_bfloat16* __restrict__ hi,
                                 __nv_bfloat16* __restrict__ lo, long n4)
{
    long i = (long)blockIdx.x * blockDim.x + threadIdx.x;
    if (i >= n4) return;
    float4 v = reinterpret_cast<const float4*>(in)[i];
    float vv[4] = {v.x, v.y, v.z, v.w};
    unsigned short hs[4], ls[4];
#pragma unroll
    for (int j = 0; j < 4; j++) {
        __nv_bfloat16 h = __float2bfloat16(vv[j]);
        __nv_bfloat16 l = __float2bfloat16(vv[j] - __bfloat162float(h));
        hs[j] = __bfloat16_as_ushort(h);
        ls[j] = __bfloat16_as_ushort(l);
    }
    reinterpret_cast<ushort4*>(hi)[i] = make_ushort4(hs[0], hs[1], hs[2], hs[3]);
    reinterpret_cast<ushort4*>(lo)[i] = make_ushort4(ls[0], ls[1], ls[2], ls[3]);
}

__global__ void gatherconv_kernel(const float* __restrict__ emb, const int* __restrict__ idx,
                                  __nv_bfloat16* __restrict__ hi, __nv_bfloat16* __restrict__ lo)
{
    int m = blockIdx.x;
    int t = threadIdx.x;   // 64 threads, float4 each
    float4 v = *reinterpret_cast<const float4*>(emb + (long)idx[m] * D_ + t * 4);
    float vv[4] = {v.x, v.y, v.z, v.w};
    unsigned short hs[4], ls[4];
#pragma unroll
    for (int j = 0; j < 4; j++) {
        __nv_bfloat16 h = __float2bfloat16(vv[j]);
        __nv_bfloat16 l = __float2bfloat16(vv[j] - __bfloat162float(h));
        hs[j] = __bfloat16_as_ushort(h);
        ls[j] = __bfloat16_as_ushort(l);
    }
    long o4 = (long)m * (D_ / 4) + t;
    reinterpret_cast<ushort4*>(hi)[o4] = make_ushort4(hs[0], hs[1], hs[2], hs[3]);
    reinterpret_cast<ushort4*>(lo)[o4] = make_ushort4(ls[0], ls[1], ls[2], ls[3]);
}

// ---------------- launch ----------------
extern "C" void kernel_launch(void* const* d_in, const int* in_sizes, int n_in,
                              void* d_out, int out_size)
{
    (void)in_sizes; (void)n_in; (void)out_size;
    const int*   idx  = (const int*)d_in[0];
    const float* temb = (const float*)d_in[1];
    const float* E    = (const float*)d_in[2];
    const float* Dx   = (const float*)d_in[3];
    const float* Dy   = (const float*)d_in[4];
    float* out = (float*)d_out;

    float *pX, *pU, *pS, *pA, *pO;
    __nv_bfloat16 *pVh, *pVl, *pDxh, *pDxl, *pDyh, *pDyl, *pEh, *pEl;
    __nv_bfloat16 *pXh, *pXl, *pAh, *pAl, *pYh, *pYl;
    cudaGetSymbolAddress((void**)&pX,  g_X);
    cudaGetSymbolAddress((void**)&pU,  g_U);
    cudaGetSymbolAddress((void**)&pS,  g_S);
    cudaGetSymbolAddress((void**)&pA,  g_A);
    cudaGetSymbolAddress((void**)&pO,  g_O);
    cudaGetSymbolAddress((void**)&pVh, g_Vh);  cudaGetSymbolAddress((void**)&pVl, g_Vl);
    cudaGetSymbolAddress((void**)&pDxh, g_Dxh); cudaGetSymbolAddress((void**)&pDxl, g_Dxl);
    cudaGetSymbolAddress((void**)&pDyh, g_Dyh); cudaGetSymbolAddress((void**)&pDyl, g_Dyl);
    cudaGetSymbolAddress((void**)&pEh, g_Eh);  cudaGetSymbolAddress((void**)&pEl, g_El);
    cudaGetSymbolAddress((void**)&pXh, g_Xh);  cudaGetSymbolAddress((void**)&pXl, g_Xl);
    cudaGetSymbolAddress((void**)&pAh, g_Ah);  cudaGetSymbolAddress((void**)&pAl, g_Al);
    cudaGetSymbolAddress((void**)&pYh, g_Yh);  cudaGetSymbolAddress((void**)&pYl, g_Yl);

    cudaFuncSetAttribute(mma_nt<EPI_RELU>,     cudaFuncAttributeMaxDynamicSharedMemorySize, SMEM_SZ);
    cudaFuncSetAttribute(mma_nt<EPI_DECAY>,    cudaFuncAttributeMaxDynamicSharedMemorySize, SMEM_SZ);
    cudaFuncSetAttribute(mma_nt<EPI_RELUMULX>, cudaFuncAttributeMaxDynamicSharedMemorySize, SMEM_SZ);
    cudaFuncSetAttribute(mma_nt<EPI_NONE>,     cudaFuncAttributeMaxDynamicSharedMemorySize, SMEM_SZ);

    init_dec_kernel<<<1, 1>>>();

    // weight + embedding conversions to bf16 hi/lo
    conv_hilo_kernel<<<(N_ * D_ / 4 + 255) / 256, 256>>>(Dx, pDxh, pDxl, N_ * D_ / 4);
    conv_hilo_kernel<<<(N_ * D_ / 4 + 255) / 256, 256>>>(Dy, pDyh, pDyl, N_ * D_ / 4);
    conv_hilo_kernel<<<(D_ * N_ / 4 + 255) / 256, 256>>>(E,  pEh,  pEl,  D_ * N_ / 4);
    gatherconv_kernel<<<M_, 64>>>(temb, idx, pVh, pVl);

    // G1: P = relu(emb[idx] @ Dx^T) -> g_X (fp32)
    mma_nt<EPI_RELU><<<dim3(N_ / 128, M_ / 128, 1), 256, SMEM_SZ>>>(
        pVh, pVl, pDxh, pDxl, pX, nullptr, nullptr, nullptr, nullptr, N_, D_, 0, 0, 0);

    // scalar L1 recurrence + parallel x scan; emits x as bf16 hi/lo directly
    colsum_kernel<<<M_, 256>>>();
    screc_kernel<<<1, 32>>>();
    xrecur_kernel<<<dim3(N_ / 256, B_, 1), 256>>>();

    // U = LN(emb[idx])
    ln_rows_kernel<<<M_, 256>>>(temb, pU, idx);

    // scores: S[b,t,s] = 0.97^(t-s) * <x_t, x_s>, s < t
    mma_nt<EPI_DECAY><<<dim3(T_ / 128, T_ / 128, B_), 256, SMEM_SZ>>>(
        pXh, pXl, pXh, pXl, pS, nullptr, nullptr, nullptr, nullptr, T_, N_,
        (long)T_ * N_, (long)T_ * N_, (long)T_ * T_);

    // a* = S @ U  (SIMT, small)
    gemm_nn<<<dim3(D_ / GBN, T_ / GBM, B_), 256>>>(
        pS, pU, pA, T_, D_, T_, (long)T_ * T_, (long)T_ * D_, (long)T_ * D_);

    // a* <- LN(a*), convert to bf16 hi/lo
    ln_rows_kernel<<<M_, 256>>>(pA, pA, nullptr);
    conv_hilo_kernel<<<(M_ * D_ / 4 + 255) / 256, 256>>>(pA, pAh, pAl, M_ * D_ / 4);

    // G2: y = relu(LN(a*) @ Dy^T) * x -> bf16 hi/lo directly
    mma_nt<EPI_RELUMULX><<<dim3(N_ / 128, M_ / 128, 1), 256, SMEM_SZ>>>(
        pAh, pAl, pDyh, pDyl, nullptr, pYh, pYl, pXh, pXl, N_, D_, 0, 0, 0);

    // G3: o = y @ E^T -> g_O
    mma_nt<EPI_NONE><<<dim3(D_ / 128, M_ / 128, 1), 256, SMEM_SZ>>>(
        pYh, pYl, pEh, pEl, pO, nullptr, nullptr, nullptr, nullptr, D_, N_, 0, 0, 0);

    // out = LN(o)
    ln_rows_kernel<<<M_, 256>>>(pO, out, nullptr);
}

// round 4
// speedup vs baseline: 2.2872x; 1.2844x over previous
#include <cuda_runtime.h>
#include <cuda_bf16.h>
#include <cstdint>

#define B_   32
#define T_   256
#define N_   4096
#define D_   256
#define M_   (B_ * T_)
#define EPSF 1e-6f
#define DECF 0.97f

// ---------------- scratch (device globals; no allocation) ----------------
__device__ float g_X [(long long)M_ * N_];      // P (fp32 scan domain)
__device__ float g_CS[M_];
__device__ float g_Cc[M_];
__device__ float g_U [M_ * D_];
__device__ float g_S [(long long)B_ * T_ * T_];
__device__ float g_A [M_ * D_];
__device__ float g_O [M_ * D_];
__device__ float g_DEC[T_];

// bf16 hi/lo split operands
__device__ __nv_bfloat16 g_Vh [M_ * D_],  g_Vl [M_ * D_];     // emb[idx]
__device__ __nv_bfloat16 g_Dxh[N_ * D_],  g_Dxl[N_ * D_];
__device__ __nv_bfloat16 g_Dyh[N_ * D_],  g_Dyl[N_ * D_];
__device__ __nv_bfloat16 g_Eh [D_ * N_],  g_El [D_ * N_];
__device__ __nv_bfloat16 g_Xh [(long long)M_ * N_], g_Xl[(long long)M_ * N_];
__device__ __nv_bfloat16 g_Ah [M_ * D_],  g_Al [M_ * D_];
__device__ __nv_bfloat16 g_Yh [(long long)M_ * N_], g_Yl[(long long)M_ * N_];

// ---------------- PTX helpers (baseline ISA only: sm_80-era) ----------------
__device__ __forceinline__ uint32_t smem_u32(const void* p) {
    uint32_t a;
    asm("{ .reg .u64 t; cvta.to.shared.u64 t, %1; cvt.u32.u64 %0, t; }" : "=r"(a) : "l"(p));
    return a;
}
__device__ __forceinline__ void cp16(uint32_t so, const void* g) {
    asm volatile("cp.async.cg.shared.global [%0], [%1], 16;" :: "r"(so), "l"(g));
}
__device__ __forceinline__ void cp_commit() {
    asm volatile("cp.async.commit_group;" ::: "memory");
}
template <int NN>
__device__ __forceinline__ void cp_wait() {
    asm volatile("cp.async.wait_group %0;" :: "n"(NN) : "memory");
}
__device__ __forceinline__ void ldsm_x4(uint32_t* f, uint32_t a) {
    asm volatile("ldmatrix.sync.aligned.m8n8.x4.shared.b16 {%0,%1,%2,%3}, [%4];"
        : "=r"(f[0]), "=r"(f[1]), "=r"(f[2]), "=r"(f[3]) : "r"(a));
}
__device__ __forceinline__ void mma16816(float* c, const uint32_t* a, const uint32_t* b) {
    asm volatile("mma.sync.aligned.m16n8k16.row.col.f32.bf16.bf16.f32 "
        "{%0,%1,%2,%3}, {%4,%5,%6,%7}, {%8,%9}, {%0,%1,%2,%3};"
        : "+f"(c[0]), "+f"(c[1]), "+f"(c[2]), "+f"(c[3])
        : "r"(a[0]), "r"(a[1]), "r"(a[2]), "r"(a[3]), "r"(b[0]), "r"(b[1]));
}

// ---------------- HMMA NT GEMM: C[m,n] = sum_k A[m,k]*B[n,k] ----------------
enum { EPI_NONE = 0, EPI_RELU = 1, EPI_RELUMULX = 2, EPI_DECAY = 3 };

#define ROWB    80                      // padded row stride bytes (32 bf16 + 8 pad)
#define TILE_B  (128 * ROWB)            // 10240
#define STAGE_B (4 * TILE_B)            // Ah, Al, Bh, Bl = 40960
#define SMEM_SZ (2 * STAGE_B)           // 81920

template <int EPI, int NPASS>
__global__ void __launch_bounds__(256, 2) mma_nt(
    const __nv_bfloat16* __restrict__ Ah, const __nv_bfloat16* __restrict__ Al,
    const __nv_bfloat16* __restrict__ Bh, const __nv_bfloat16* __restrict__ Bl,
    float* __restrict__ Cf, __nv_bfloat16* __restrict__ Ch, __nv_bfloat16* __restrict__ Cl,
    const __nv_bfloat16* __restrict__ Xh, const __nv_bfloat16* __restrict__ Xl,
    int Nd, int K, long sA, long sB, long sC)
{
    extern __shared__ char smem[];
    const uint32_t sb = smem_u32(smem);
    const int tid  = threadIdx.x;
    const int lane = tid & 31;
    const int wid  = tid >> 5;
    const int wm   = wid >> 2;          // 0..1  -> m offset wm*64
    const int wn   = wid & 3;           // 0..3  -> n offset wn*32
    const int bz = blockIdx.z;
    const int bm = blockIdx.y * 128;
    const int bn = blockIdx.x * 128;
    const bool skip = (EPI == EPI_DECAY) && (bn >= bm + 128);

    float acc[4][4][4];
#pragma unroll
    for (int i = 0; i < 4; i++)
#pragma unroll
        for (int j = 0; j < 4; j++)
#pragma unroll
            for (int v = 0; v < 4; v++) acc[i][j][v] = 0.f;

    if (!skip) {
        const __nv_bfloat16* Ahp = Ah + (long)bz * sA + (long)bm * K;
        const __nv_bfloat16* Alp = Al + (long)bz * sA + (long)bm * K;
        const __nv_bfloat16* Bhp = Bh + (long)bz * sB + (long)bn * K;
        const __nv_bfloat16* Blp = Bl + (long)bz * sB + (long)bn * K;

        const int qr0 = tid >> 2;             // row (0..63)
        const int qc0 = tid & 3;              // 16B group
        auto stage_load = [&](int stg, int k0) {
            const __nv_bfloat16* srcs[4] = {Ahp, Alp, Bhp, Blp};
#pragma unroll
            for (int t = 0; t < 4; t++) {
                if (NPASS == 1 && (t & 1)) continue;     // skip Al/Bl tiles
                uint32_t tbase = sb + stg * STAGE_B + t * TILE_B;
#pragma unroll
                for (int i = 0; i < 2; i++) {
                    int r = qr0 + i * 64;
                    cp16(tbase + r * ROWB + qc0 * 16,
                         srcs[t] + (long)r * K + k0 + qc0 * 8);
                }
            }
            cp_commit();
        };

        const int nC = K / 32;
        stage_load(0, 0);

        // per-lane ldmatrix base offsets
        const uint32_t aRow = (uint32_t)(wm * 64 + (lane & 15));
        const uint32_t aCol = (uint32_t)((lane >> 4) * 8);
        // B x4: matrices {na=2p,k0-7},{na=2p,k8-15},{na=2p+1,k0-7},{na=2p+1,k8-15}
        const uint32_t bRowB = (uint32_t)(wn * 32 + ((lane >> 4) << 3) + (lane & 7));
        const uint32_t bCol  = (uint32_t)(((lane >> 3) & 1) * 8);

        for (int c = 0; c < nC; c++) {
            const int cur = c & 1;
            if (c + 1 < nC) { stage_load(cur ^ 1, (c + 1) * 32); cp_wait<1>(); }
            else            { cp_wait<0>(); }
            __syncthreads();

            const uint32_t st = sb + cur * STAGE_B;
#pragma unroll
            for (int ks = 0; ks < 2; ks++) {
                uint32_t fA[4][4], fB[2][4];
#pragma unroll
                for (int ma = 0; ma < 4; ma++)
                    ldsm_x4(fA[ma], st + (aRow + ma * 16) * ROWB + (ks * 16 + aCol) * 2);
#pragma unroll
                for (int p = 0; p < 2; p++)
                    ldsm_x4(fB[p], st + 2 * TILE_B + (bRowB + p * 16) * ROWB + (ks * 16 + bCol) * 2);
#pragma unroll
                for (int ma = 0; ma < 4; ma++)
#pragma unroll
                    for (int na = 0; na < 4; na++)
                        mma16816(acc[ma][na], fA[ma], &fB[na >> 1][2 * (na & 1)]);
                if (NPASS == 3) {
                    uint32_t fB2[2][4];
#pragma unroll
                    for (int p = 0; p < 2; p++)
                        ldsm_x4(fB2[p], st + 3 * TILE_B + (bRowB + p * 16) * ROWB + (ks * 16 + bCol) * 2);
#pragma unroll
                    for (int ma = 0; ma < 4; ma++)
#pragma unroll
                        for (int na = 0; na < 4; na++)
                            mma16816(acc[ma][na], fA[ma], &fB2[na >> 1][2 * (na & 1)]);
                    // reuse fA for Al; fB still holds Bh
#pragma unroll
                    for (int ma = 0; ma < 4; ma++)
                        ldsm_x4(fA[ma], st + TILE_B + (aRow + ma * 16) * ROWB + (ks * 16 + aCol) * 2);
#pragma unroll
                    for (int ma = 0; ma < 4; ma++)
#pragma unroll
                        for (int na = 0; na < 4; na++)
                            mma16816(acc[ma][na], fA[ma], &fB[na >> 1][2 * (na & 1)]);
                }
            }
            __syncthreads();
        }
    }

    // ---- epilogue ----
    const int gr = lane >> 2;          // 0..7
    const int gc = (lane & 3) * 2;
#pragma unroll
    for (int ma = 0; ma < 4; ma++) {
#pragma unroll
        for (int half = 0; half < 2; half++) {
            const int row = bm + wm * 64 + ma * 16 + gr + half * 8;
            float rs = 0.f;
#pragma unroll
            for (int na = 0; na < 4; na++) {
                const int col = bn + wn * 32 + na * 8 + gc;
                float v0 = acc[ma][na][half * 2 + 0];
                float v1 = acc[ma][na][half * 2 + 1];
                long off = (long)row * Nd + col;
                if (EPI == EPI_RELUMULX) {
                    ushort2 xh = *reinterpret_cast<const ushort2*>(Xh + off);
                    ushort2 xl = *reinterpret_cast<const ushort2*>(Xl + off);
                    float x0 = __bfloat162float(__ushort_as_bfloat16(xh.x)) +
                               __bfloat162float(__ushort_as_bfloat16(xl.x));
                    float x1 = __bfloat162float(__ushort_as_bfloat16(xh.y)) +
                               __bfloat162float(__ushort_as_bfloat16(xl.y));
                    v0 = fmaxf(v0, 0.f) * x0;
                    v1 = fmaxf(v1, 0.f) * x1;
                    __nv_bfloat16 h0 = __float2bfloat16(v0), h1 = __float2bfloat16(v1);
                    __nv_bfloat16 l0 = __float2bfloat16(v0 - __bfloat162float(h0));
                    __nv_bfloat16 l1 = __float2bfloat16(v1 - __bfloat162float(h1));
                    *reinterpret_cast<ushort2*>(Ch + off) =
                        make_ushort2(__bfloat16_as_ushort(h0), __bfloat16_as_ushort(h1));
                    *reinterpret_cast<ushort2*>(Cl + off) =
                        make_ushort2(__bfloat16_as_ushort(l0), __bfloat16_as_ushort(l1));
                } else {
                    if (EPI == EPI_RELU) {
                        v0 = fmaxf(v0, 0.f); v1 = fmaxf(v1, 0.f);
                        rs += v0 + v1;
                    } else if (EPI == EPI_DECAY) {
                        int L0 = row - col, L1 = row - col - 1;
                        v0 = (L0 > 0) ? v0 * g_DEC[L0] : 0.f;
                        v1 = (L1 > 0) ? v1 * g_DEC[L1] : 0.f;
                    }
                    *reinterpret_cast<float2*>(Cf + (long)bz * sC + off) = make_float2(v0, v1);
                }
            }
            if (EPI == EPI_RELU) {   // fused partial row-sum for L1 norm
                rs += __shfl_xor_sync(0xffffffffu, rs, 1);
                rs += __shfl_xor_sync(0xffffffffu, rs, 2);
                if ((lane & 3) == 0) atomicAdd(&g_CS[row], rs);
            }
        }
    }
}

// ---------------- SIMT NN GEMM (a* = S @ U, small) ----------------
#define GBM 128
#define GBN 64
#define GBK 16
#define GTM 8
#define GTN 4

__global__ __launch_bounds__(256)
void gemm_nn(const float* __restrict__ A, const float* __restrict__ B,
             float* __restrict__ C, int M, int Nd, int K,
             long batchA, long batchB, long batchC)
{
    const int bz = blockIdx.z;
    A += (long)bz * batchA;
    B += (long)bz * batchB;
    C += (long)bz * batchC;
    const int bm = blockIdx.y * GBM;
    const int bn = blockIdx.x * GBN;

    __shared__ __align__(16) float As[GBK][GBM + 4];
    __shared__ __align__(16) float Bs[GBK][GBN + 4];

    const int tid = threadIdx.x;
    const int tx = tid & 15;
    const int ty = tid >> 4;

    float acc[GTM][GTN];
#pragma unroll
    for (int i = 0; i < GTM; i++)
#pragma unroll
        for (int j = 0; j < GTN; j++) acc[i][j] = 0.f;

    const int lr = tid >> 2;
    const int lk = (tid & 3) * 4;
    const int brow = tid >> 4;
    const int bcol = (tid & 15) * 4;

    for (int k0 = 0; k0 < K; k0 += GBK) {
#pragma unroll
        for (int i = 0; i < 2; i++) {
            int r = lr + i * 64;
            float4 v = *reinterpret_cast<const float4*>(A + (long)(bm + r) * K + k0 + lk);
            As[lk + 0][r] = v.x; As[lk + 1][r] = v.y;
            As[lk + 2][r] = v.z; As[lk + 3][r] = v.w;
        }
        {
            float4 v = *reinterpret_cast<const float4*>(B + (long)(k0 + brow) * Nd + bn + bcol);
            Bs[brow][bcol + 0] = v.x; Bs[brow][bcol + 1] = v.y;
            Bs[brow][bcol + 2] = v.z; Bs[brow][bcol + 3] = v.w;
        }
        __syncthreads();
#pragma unroll
        for (int kk = 0; kk < GBK; kk++) {
            float af[GTM], bf[GTN];
#pragma unroll
            for (int i = 0; i < GTM; i++) af[i] = As[kk][ty * GTM + i];
#pragma unroll
            for (int j = 0; j < GTN; j++) bf[j] = Bs[kk][tx * GTN + j];
#pragma unroll
            for (int i = 0; i < GTM; i++)
#pragma unroll
                for (int j = 0; j < GTN; j++)
                    acc[i][j] = fmaf(af[i], bf[j], acc[i][j]);
        }
        __syncthreads();
    }
#pragma unroll
    for (int i = 0; i < GTM; i++) {
        int row = bm + ty * GTM + i;
        long cbase = (long)row * Nd + bn + tx * GTN;
        *reinterpret_cast<float4*>(C + cbase) = make_float4(acc[i][0], acc[i][1], acc[i][2], acc[i][3]);
    }
}

// ---------------- elementwise / scan / LN kernels ----------------
__device__ __forceinline__ float blockReduceSum256(float v) {
    __shared__ float sh[8];
    __syncthreads();
    int lane = threadIdx.x & 31;
    int w = threadIdx.x >> 5;
#pragma unroll
    for (int o = 16; o > 0; o >>= 1) v += __shfl_down_sync(0xffffffffu, v, o);
    if (lane == 0) sh[w] = v;
    __syncthreads();
    if (w == 0) {
        float t = (lane < 8) ? sh[lane] : 0.f;
#pragma unroll
        for (int o = 4; o > 0; o >>= 1) t += __shfl_down_sync(0xffffffffu, t, o);
        if (lane == 0) sh[0] = t;
    }
    __syncthreads();
    return sh[0];
}

__global__ void init_dec_kernel() {
    float d = 1.f;
    for (int i = 0; i < T_; i++) { g_DEC[i] = d; d *= DECF; }
}

__global__ void zero_cs_kernel() {
    g_CS[blockIdx.x * 256 + threadIdx.x] = 0.f;
}

__global__ void screc_kernel() {
    int b = threadIdx.x;
    if (b >= B_) return;
    float sprev = 0.f;
    for (int t = 0; t < T_; t++) {
        float sumx = sprev / (sprev + EPSF);
        float s = DECF * sumx + g_CS[b * T_ + t];
        g_Cc[b * T_ + t] = 1.f / (s + EPSF);
        sprev = s;
    }
}

__global__ void xrecur_kernel() {
    int b = blockIdx.y;
    int n = blockIdx.x * 256 + threadIdx.x;
    __shared__ float sc[T_];
    sc[threadIdx.x] = g_Cc[b * T_ + threadIdx.x];
    __syncthreads();
    float x = 0.f;
    long base = (long)b * T_ * N_ + n;
    for (int t = 0; t < T_; t++) {
        float p = g_X[base + (long)t * N_];
        x = (DECF * x + p) * sc[t];
        __nv_bfloat16 h = __float2bfloat16(x);
        g_Xh[base + (long)t * N_] = h;
        g_Xl[base + (long)t * N_] = __float2bfloat16(x - __bfloat162float(h));
    }
}

template <int HILO>
__global__ void ln_rows(const float* __restrict__ in, float* __restrict__ outf,
                        __nv_bfloat16* __restrict__ oh, __nv_bfloat16* __restrict__ ol,
                        const int* __restrict__ gidx)
{
    int m = blockIdx.x;
    long r = gidx ? (long)gidx[m] : (long)m;
    float z = in[r * D_ + threadIdx.x];
    float mean = blockReduceSum256(z) * (1.f / D_);
    float d = z - mean;
    float var = blockReduceSum256(d * d) * (1.f / (D_ - 1));
    float v = d / (sqrtf(var) + EPSF);
    long o = (long)m * D_ + threadIdx.x;
    if (HILO) {
        __nv_bfloat16 h = __float2bfloat16(v);
        oh[o] = h;
        ol[o] = __float2bfloat16(v - __bfloat162float(h));
    } else {
        outf[o] = v;
    }
}

__global__ void conv_hilo_kernel(const float* __restrict__ in,
                                 __nv_bfloat16* __restrict__ hi,
                                 __nv_bfloat16* __restrict__ lo, long n4)
{
    long i = (long)blockIdx.x * blockDim.x + threadIdx.x;
    if (i >= n4) return;
    float4 v = reinterpret_cast<const float4*>(in)[i];
    float vv[4] = {v.x, v.y, v.z, v.w};
    unsigned short hs[4], ls[4];
#pragma unroll
    for (int j = 0; j < 4; j++) {
        __nv_bfloat16 h = __float2bfloat16(vv[j]);
        __nv_bfloat16 l = __float2bfloat16(vv[j] - __bfloat162float(h));
        hs[j] = __bfloat16_as_ushort(h);
        ls[j] = __bfloat16_as_ushort(l);
    }
    reinterpret_cast<ushort4*>(hi)[i] = make_ushort4(hs[0], hs[1], hs[2], hs[3]);
    reinterpret_cast<ushort4*>(lo)[i] = make_ushort4(ls[0], ls[1], ls[2], ls[3]);
}

__global__ void gatherconv_kernel(const float* __restrict__ emb, const int* __restrict__ idx,
                                  __nv_bfloat16* __restrict__ hi, __nv_bfloat16* __restrict__ lo)
{
    int m = blockIdx.x;
    int t = threadIdx.x;   // 64 threads, float4 each
    float4 v = *reinterpret_cast<const float4*>(emb + (long)idx[m] * D_ + t * 4);
    float vv[4] = {v.x, v.y, v.z, v.w};
    unsigned short hs[4], ls[4];
#pragma unroll
    for (int j = 0; j < 4; j++) {
        __nv_bfloat16 h = __float2bfloat16(vv[j]);
        __nv_bfloat16 l = __float2bfloat16(vv[j] - __bfloat162float(h));
        hs[j] = __bfloat16_as_ushort(h);
        ls[j] = __bfloat16_as_ushort(l);
    }
    long o4 = (long)m * (D_ / 4) + t;
    reinterpret_cast<ushort4*>(hi)[o4] = make_ushort4(hs[0], hs[1], hs[2], hs[3]);
    reinterpret_cast<ushort4*>(lo)[o4] = make_ushort4(ls[0], ls[1], ls[2], ls[3]);
}

// ---------------- launch ----------------
extern "C" void kernel_launch(void* const* d_in, const int* in_sizes, int n_in,
                              void* d_out, int out_size)
{
    (void)in_sizes; (void)n_in; (void)out_size;
    const int*   idx  = (const int*)d_in[0];
    const float* temb = (const float*)d_in[1];
    const float* E    = (const float*)d_in[2];
    const float* Dx   = (const float*)d_in[3];
    const float* Dy   = (const float*)d_in[4];
    float* out = (float*)d_out;

    float *pX, *pU, *pS, *pA, *pO;
    __nv_bfloat16 *pVh, *pVl, *pDxh, *pDxl, *pDyh, *pDyl, *pEh, *pEl;
    __nv_bfloat16 *pXh, *pXl, *pAh, *pAl, *pYh, *pYl;
    cudaGetSymbolAddress((void**)&pX,  g_X);
    cudaGetSymbolAddress((void**)&pU,  g_U);
    cudaGetSymbolAddress((void**)&pS,  g_S);
    cudaGetSymbolAddress((void**)&pA,  g_A);
    cudaGetSymbolAddress((void**)&pO,  g_O);
    cudaGetSymbolAddress((void**)&pVh, g_Vh);  cudaGetSymbolAddress((void**)&pVl, g_Vl);
    cudaGetSymbolAddress((void**)&pDxh, g_Dxh); cudaGetSymbolAddress((void**)&pDxl, g_Dxl);
    cudaGetSymbolAddress((void**)&pDyh, g_Dyh); cudaGetSymbolAddress((void**)&pDyl, g_Dyl);
    cudaGetSymbolAddress((void**)&pEh, g_Eh);  cudaGetSymbolAddress((void**)&pEl, g_El);
    cudaGetSymbolAddress((void**)&pXh, g_Xh);  cudaGetSymbolAddress((void**)&pXl, g_Xl);
    cudaGetSymbolAddress((void**)&pAh, g_Ah);  cudaGetSymbolAddress((void**)&pAl, g_Al);
    cudaGetSymbolAddress((void**)&pYh, g_Yh);  cudaGetSymbolAddress((void**)&pYl, g_Yl);

    cudaFuncSetAttribute(mma_nt<EPI_RELU, 3>,     cudaFuncAttributeMaxDynamicSharedMemorySize, SMEM_SZ);
    cudaFuncSetAttribute(mma_nt<EPI_DECAY, 1>,    cudaFuncAttributeMaxDynamicSharedMemorySize, SMEM_SZ);
    cudaFuncSetAttribute(mma_nt<EPI_RELUMULX, 3>, cudaFuncAttributeMaxDynamicSharedMemorySize, SMEM_SZ);
    cudaFuncSetAttribute(mma_nt<EPI_NONE, 3>,     cudaFuncAttributeMaxDynamicSharedMemorySize, SMEM_SZ);

    init_dec_kernel<<<1, 1>>>();

    // weight + embedding conversions to bf16 hi/lo
    conv_hilo_kernel<<<(N_ * D_ / 4 + 255) / 256, 256>>>(Dx, pDxh, pDxl, N_ * D_ / 4);
    conv_hilo_kernel<<<(N_ * D_ / 4 + 255) / 256, 256>>>(Dy, pDyh, pDyl, N_ * D_ / 4);
    conv_hilo_kernel<<<(D_ * N_ / 4 + 255) / 256, 256>>>(E,  pEh,  pEl,  D_ * N_ / 4);
    gatherconv_kernel<<<M_, 64>>>(temb, idx, pVh, pVl);
    zero_cs_kernel<<<M_ / 256, 256>>>();

    // G1: P = relu(emb[idx] @ Dx^T) -> g_X (fp32), fused row-sum -> g_CS
    mma_nt<EPI_RELU, 3><<<dim3(N_ / 128, M_ / 128, 1), 256, SMEM_SZ>>>(
        pVh, pVl, pDxh, pDxl, pX, nullptr, nullptr, nullptr, nullptr, N_, D_, 0, 0, 0);

    // scalar L1 recurrence + parallel x scan; emits x as bf16 hi/lo directly
    screc_kernel<<<1, 32>>>();
    xrecur_kernel<<<dim3(N_ / 256, B_, 1), 256>>>();

    // U = LN(emb[idx])
    ln_rows<0><<<M_, 256>>>(temb, pU, nullptr, nullptr, idx);

    // scores: S[b,t,s] = 0.97^(t-s) * <x_t, x_s>, s < t  (single-pass bf16: positive sums)
    mma_nt<EPI_DECAY, 1><<<dim3(T_ / 128, T_ / 128, B_), 256, SMEM_SZ>>>(
        pXh, pXh, pXh, pXh, pS, nullptr, nullptr, nullptr, nullptr, T_, N_,
        (long)T_ * N_, (long)T_ * N_, (long)T_ * T_);

    // a* = S @ U  (SIMT, small)
    gemm_nn<<<dim3(D_ / GBN, T_ / GBM, B_), 256>>>(
        pS, pU, pA, T_, D_, T_, (long)T_ * T_, (long)T_ * D_, (long)T_ * D_);

    // a* <- LN(a*) -> bf16 hi/lo directly
    ln_rows<1><<<M_, 256>>>(pA, nullptr, pAh, pAl, nullptr);

    // G2: y = relu(LN(a*) @ Dy^T) * x -> bf16 hi/lo directly
    mma_nt<EPI_RELUMULX, 3><<<dim3(N_ / 128, M_ / 128, 1), 256, SMEM_SZ>>>(
        pAh, pAl, pDyh, pDyl, nullptr, pYh, pYl, pXh, pXl, N_, D_, 0, 0, 0);

    // G3: o = y @ E^T -> g_O
    mma_nt<EPI_NONE, 3><<<dim3(D_ / 128, M_ / 128, 1), 256, SMEM_SZ>>>(
        pYh, pYl, pEh, pEl, pO, nullptr, nullptr, nullptr, nullptr, D_, N_, 0, 0, 0);

    // out = LN(o)
    ln_rows<0><<<M_, 256>>>(pO, out, nullptr, nullptr, nullptr);
}

// round 5
// speedup vs baseline: 2.5094x; 1.0971x over previous
#include <cuda_runtime.h>
#include <cuda_bf16.h>
#include <cstdint>

#define B_   32
#define T_   256
#define N_   4096
#define D_   256
#define M_   (B_ * T_)
#define EPSF 1e-6f
#define DECF 0.97f

// ---------------- scratch (device globals; no allocation) ----------------
__device__ float g_X [(long long)M_ * N_];      // P (fp32 scan domain)
__device__ float g_CS[M_];
__device__ float g_Cc[M_];
__device__ float g_U [M_ * D_];
__device__ float g_S [(long long)B_ * T_ * T_];
__device__ float g_A [M_ * D_];
__device__ float g_O [M_ * D_];
__device__ float g_DEC[T_];

// bf16 hi/lo split operands
__device__ __nv_bfloat16 g_Vh [M_ * D_],  g_Vl [M_ * D_];     // emb[idx]
__device__ __nv_bfloat16 g_Dxh[N_ * D_],  g_Dxl[N_ * D_];
__device__ __nv_bfloat16 g_Dyh[N_ * D_],  g_Dyl[N_ * D_];
__device__ __nv_bfloat16 g_Eh [D_ * N_],  g_El [D_ * N_];
__device__ __nv_bfloat16 g_Xh [(long long)M_ * N_], g_Xl[(long long)M_ * N_];
__device__ __nv_bfloat16 g_Ah [M_ * D_],  g_Al [M_ * D_];
__device__ __nv_bfloat16 g_Yh [(long long)M_ * N_], g_Yl[(long long)M_ * N_];

// ---------------- PTX helpers (baseline ISA only) ----------------
__device__ __forceinline__ uint32_t smem_u32(const void* p) {
    uint32_t a;
    asm("{ .reg .u64 t; cvta.to.shared.u64 t, %1; cvt.u32.u64 %0, t; }" : "=r"(a) : "l"(p));
    return a;
}
__device__ __forceinline__ void cp16(uint32_t so, const void* g) {
    asm volatile("cp.async.cg.shared.global [%0], [%1], 16;" :: "r"(so), "l"(g));
}
__device__ __forceinline__ void cp_commit() {
    asm volatile("cp.async.commit_group;" ::: "memory");
}
template <int NN>
__device__ __forceinline__ void cp_wait() {
    asm volatile("cp.async.wait_group %0;" :: "n"(NN) : "memory");
}
__device__ __forceinline__ void ldsm_x4(uint32_t* f, uint32_t a) {
    asm volatile("ldmatrix.sync.aligned.m8n8.x4.shared.b16 {%0,%1,%2,%3}, [%4];"
        : "=r"(f[0]), "=r"(f[1]), "=r"(f[2]), "=r"(f[3]) : "r"(a));
}
__device__ __forceinline__ void mma16816(float* c, const uint32_t* a, const uint32_t* b) {
    asm volatile("mma.sync.aligned.m16n8k16.row.col.f32.bf16.bf16.f32 "
        "{%0,%1,%2,%3}, {%4,%5,%6,%7}, {%8,%9}, {%0,%1,%2,%3};"
        : "+f"(c[0]), "+f"(c[1]), "+f"(c[2]), "+f"(c[3])
        : "r"(a[0]), "r"(a[1]), "r"(a[2]), "r"(a[3]), "r"(b[0]), "r"(b[1]));
}

// ---------------- HMMA NT GEMM: C[m,n] = sum_k A[m,k]*B[n,k] ----------------
enum { EPI_NONE = 0, EPI_RELU = 1, EPI_RELUMULX = 2, EPI_DECAY = 3 };

// swizzled tile: 128 rows x 64B (32 bf16); phys 16B-slot = g ^ ((r>>1)&3)
#define TILE_B 8192

template <int EPI, int NPASS>
__global__ void __launch_bounds__(256, 2) mma_nt(
    const __nv_bfloat16* __restrict__ Ah, const __nv_bfloat16* __restrict__ Al,
    const __nv_bfloat16* __restrict__ Bh, const __nv_bfloat16* __restrict__ Bl,
    float* __restrict__ Cf, __nv_bfloat16* __restrict__ Ch, __nv_bfloat16* __restrict__ Cl,
    const __nv_bfloat16* __restrict__ Xh, const __nv_bfloat16* __restrict__ Xl,
    int Nd, int K, long sA, long sB, long sC)
{
    constexpr int NTILES  = (NPASS == 3) ? 4 : 2;
    constexpr int STAGE_B = NTILES * TILE_B;

    extern __shared__ char smem[];
    const uint32_t sb = smem_u32(smem);
    const int tid  = threadIdx.x;
    const int lane = tid & 31;
    const int wid  = tid >> 5;
    const int wm   = wid >> 2;          // 0..1  -> m offset wm*64
    const int wn   = wid & 3;           // 0..3  -> n offset wn*32
    const int bz = blockIdx.z;
    const int bm = blockIdx.y * 128;
    const int bn = blockIdx.x * 128;
    const bool skip = (EPI == EPI_DECAY) && (bn >= bm + 128);

    float acc[4][4][4];
#pragma unroll
    for (int i = 0; i < 4; i++)
#pragma unroll
        for (int j = 0; j < 4; j++)
#pragma unroll
            for (int v = 0; v < 4; v++) acc[i][j][v] = 0.f;

    if (!skip) {
        const __nv_bfloat16* Ahp = Ah + (long)bz * sA + (long)bm * K;
        const __nv_bfloat16* Alp = Al + (long)bz * sA + (long)bm * K;
        const __nv_bfloat16* Bhp = Bh + (long)bz * sB + (long)bn * K;
        const __nv_bfloat16* Blp = Bl + (long)bz * sB + (long)bn * K;

        const int qr0 = tid >> 2;             // row (0..63)
        const int qc0 = tid & 3;              // 16B group
        auto stage_load = [&](int stg, int k0) {
            uint32_t base = sb + stg * STAGE_B;
#pragma unroll
            for (int i = 0; i < 2; i++) {
                int r = qr0 + i * 64;
                uint32_t so = (uint32_t)(r * 64 + ((qc0 ^ ((r >> 1) & 3)) * 16));
                long gofs = (long)r * K + k0 + qc0 * 8;
                cp16(base + so,              Ahp + gofs);
                cp16(base + TILE_B + so,     Bhp + gofs);
                if (NPASS == 3) {
                    cp16(base + 2 * TILE_B + so, Alp + gofs);
                    cp16(base + 3 * TILE_B + so, Blp + gofs);
                }
            }
            cp_commit();
        };

        const int nC = K / 32;
        stage_load(0, 0);
        stage_load(1, 32);

        // per-lane ldsm logical positions
        const uint32_t aRow  = (uint32_t)(wm * 64 + (lane & 15));
        const uint32_t aColG = (uint32_t)(lane >> 4);                         // 0..1
        const uint32_t bRow  = (uint32_t)(wn * 32 + ((lane >> 4) << 3) + (lane & 7));
        const uint32_t bColG = (uint32_t)((lane >> 3) & 1);
        const uint32_t sa = (aRow >> 1) & 3;
        const uint32_t sbw = (bRow >> 1) & 3;
        uint32_t aoff[2], boff[2];
#pragma unroll
        for (int ks = 0; ks < 2; ks++) {
            aoff[ks] = aRow * 64 + (((ks * 2 + aColG) ^ sa) * 16);
            boff[ks] = bRow * 64 + (((ks * 2 + bColG) ^ sbw) * 16);
        }

        int stg = 0;
        for (int c = 0; c < nC; c++) {
            cp_wait<1>();
            __syncthreads();
            if (c + 2 < nC) {
                int ns = stg + 2; if (ns >= 3) ns -= 3;
                stage_load(ns, (c + 2) * 32);
            } else {
                cp_commit();   // empty group keeps wait<1> accounting uniform
            }

            const uint32_t st = sb + stg * STAGE_B;
#pragma unroll
            for (int ks = 0; ks < 2; ks++) {
                uint32_t fA[4][4], fB[2][4];
                // pass 1: Ah . Bh
#pragma unroll
                for (int ma = 0; ma < 4; ma++)
                    ldsm_x4(fA[ma], st + aoff[ks] + ma * 1024);
#pragma unroll
                for (int p = 0; p < 2; p++)
                    ldsm_x4(fB[p], st + TILE_B + boff[ks] + p * 1024);
#pragma unroll
                for (int ma = 0; ma < 4; ma++)
#pragma unroll
                    for (int na = 0; na < 4; na++)
                        mma16816(acc[ma][na], fA[ma], &fB[na >> 1][2 * (na & 1)]);
                if (NPASS == 3) {
                    // pass 2: Al . Bh (reuse fB)
#pragma unroll
                    for (int ma = 0; ma < 4; ma++)
                        ldsm_x4(fA[ma], st + 2 * TILE_B + aoff[ks] + ma * 1024);
#pragma unroll
                    for (int ma = 0; ma < 4; ma++)
#pragma unroll
                        for (int na = 0; na < 4; na++)
                            mma16816(acc[ma][na], fA[ma], &fB[na >> 1][2 * (na & 1)]);
                    // pass 3: Ah . Bl (reload fA, overwrite fB)
#pragma unroll
                    for (int ma = 0; ma < 4; ma++)
                        ldsm_x4(fA[ma], st + aoff[ks] + ma * 1024);
#pragma unroll
                    for (int p = 0; p < 2; p++)
                        ldsm_x4(fB[p], st + 3 * TILE_B + boff[ks] + p * 1024);
#pragma unroll
                    for (int ma = 0; ma < 4; ma++)
#pragma unroll
                        for (int na = 0; na < 4; na++)
                            mma16816(acc[ma][na], fA[ma], &fB[na >> 1][2 * (na & 1)]);
                }
            }
            stg = (stg == 2) ? 0 : stg + 1;
        }
    }

    // ---- epilogue ----
    const int gr = lane >> 2;          // 0..7
    const int gc = (lane & 3) * 2;
#pragma unroll
    for (int ma = 0; ma < 4; ma++) {
#pragma unroll
        for (int half = 0; half < 2; half++) {
            const int row = bm + wm * 64 + ma * 16 + gr + half * 8;
            float rs = 0.f;
#pragma unroll
            for (int na = 0; na < 4; na++) {
                const int col = bn + wn * 32 + na * 8 + gc;
                float v0 = acc[ma][na][half * 2 + 0];
                float v1 = acc[ma][na][half * 2 + 1];
                long off = (long)row * Nd + col;
                if (EPI == EPI_RELUMULX) {
                    ushort2 xh = *reinterpret_cast<const ushort2*>(Xh + off);
                    ushort2 xl = *reinterpret_cast<const ushort2*>(Xl + off);
                    float x0 = __bfloat162float(__ushort_as_bfloat16(xh.x)) +
                               __bfloat162float(__ushort_as_bfloat16(xl.x));
                    float x1 = __bfloat162float(__ushort_as_bfloat16(xh.y)) +
                               __bfloat162float(__ushort_as_bfloat16(xl.y));
                    v0 = fmaxf(v0, 0.f) * x0;
                    v1 = fmaxf(v1, 0.f) * x1;
                    __nv_bfloat16 h0 = __float2bfloat16(v0), h1 = __float2bfloat16(v1);
                    __nv_bfloat16 l0 = __float2bfloat16(v0 - __bfloat162float(h0));
                    __nv_bfloat16 l1 = __float2bfloat16(v1 - __bfloat162float(h1));
                    *reinterpret_cast<ushort2*>(Ch + off) =
                        make_ushort2(__bfloat16_as_ushort(h0), __bfloat16_as_ushort(h1));
                    *reinterpret_cast<ushort2*>(Cl + off) =
                        make_ushort2(__bfloat16_as_ushort(l0), __bfloat16_as_ushort(l1));
                } else {
                    if (EPI == EPI_RELU) {
                        v0 = fmaxf(v0, 0.f); v1 = fmaxf(v1, 0.f);
                        rs += v0 + v1;
                    } else if (EPI == EPI_DECAY) {
                        int L0 = row - col, L1 = row - col - 1;
                        v0 = (L0 > 0) ? v0 * g_DEC[L0] : 0.f;
                        v1 = (L1 > 0) ? v1 * g_DEC[L1] : 0.f;
                    }
                    *reinterpret_cast<float2*>(Cf + (long)bz * sC + off) = make_float2(v0, v1);
                }
            }
            if (EPI == EPI_RELU) {   // fused partial row-sum for L1 norm
                rs += __shfl_xor_sync(0xffffffffu, rs, 1);
                rs += __shfl_xor_sync(0xffffffffu, rs, 2);
                if ((lane & 3) == 0) atomicAdd(&g_CS[row], rs);
            }
        }
    }
}

// ---------------- SIMT NN GEMM (a* = S @ U, small) ----------------
#define GBM 128
#define GBN 64
#define GBK 16
#define GTM 8
#define GTN 4

__global__ __launch_bounds__(256)
void gemm_nn(const float* __restrict__ A, const float* __restrict__ B,
             float* __restrict__ C, int M, int Nd, int K,
             long batchA, long batchB, long batchC)
{
    const int bz = blockIdx.z;
    A += (long)bz * batchA;
    B += (long)bz * batchB;
    C += (long)bz * batchC;
    const int bm = blockIdx.y * GBM;
    const int bn = blockIdx.x * GBN;

    __shared__ __align__(16) float As[GBK][GBM + 4];
    __shared__ __align__(16) float Bs[GBK][GBN + 4];

    const int tid = threadIdx.x;
    const int tx = tid & 15;
    const int ty = tid >> 4;

    float acc[GTM][GTN];
#pragma unroll
    for (int i = 0; i < GTM; i++)
#pragma unroll
        for (int j = 0; j < GTN; j++) acc[i][j] = 0.f;

    const int lr = tid >> 2;
    const int lk = (tid & 3) * 4;
    const int brow = tid >> 4;
    const int bcol = (tid & 15) * 4;

    for (int k0 = 0; k0 < K; k0 += GBK) {
#pragma unroll
        for (int i = 0; i < 2; i++) {
            int r = lr + i * 64;
            float4 v = *reinterpret_cast<const float4*>(A + (long)(bm + r) * K + k0 + lk);
            As[lk + 0][r] = v.x; As[lk + 1][r] = v.y;
            As[lk + 2][r] = v.z; As[lk + 3][r] = v.w;
        }
        {
            float4 v = *reinterpret_cast<const float4*>(B + (long)(k0 + brow) * Nd + bn + bcol);
            Bs[brow][bcol + 0] = v.x; Bs[brow][bcol + 1] = v.y;
            Bs[brow][bcol + 2] = v.z; Bs[brow][bcol + 3] = v.w;
        }
        __syncthreads();
#pragma unroll
        for (int kk = 0; kk < GBK; kk++) {
            float af[GTM], bf[GTN];
#pragma unroll
            for (int i = 0; i < GTM; i++) af[i] = As[kk][ty * GTM + i];
#pragma unroll
            for (int j = 0; j < GTN; j++) bf[j] = Bs[kk][tx * GTN + j];
#pragma unroll
            for (int i = 0; i < GTM; i++)
#pragma unroll
                for (int j = 0; j < GTN; j++)
                    acc[i][j] = fmaf(af[i], bf[j], acc[i][j]);
        }
        __syncthreads();
    }
#pragma unroll
    for (int i = 0; i < GTM; i++) {
        int row = bm + ty * GTM + i;
        long cbase = (long)row * Nd + bn + tx * GTN;
        *reinterpret_cast<float4*>(C + cbase) = make_float4(acc[i][0], acc[i][1], acc[i][2], acc[i][3]);
    }
}

// ---------------- elementwise / scan / LN kernels ----------------
__device__ __forceinline__ float blockReduceSum256(float v) {
    __shared__ float sh[8];
    __syncthreads();
    int lane = threadIdx.x & 31;
    int w = threadIdx.x >> 5;
#pragma unroll
    for (int o = 16; o > 0; o >>= 1) v += __shfl_down_sync(0xffffffffu, v, o);
    if (lane == 0) sh[w] = v;
    __syncthreads();
    if (w == 0) {
        float t = (lane < 8) ? sh[lane] : 0.f;
#pragma unroll
        for (int o = 4; o > 0; o >>= 1) t += __shfl_down_sync(0xffffffffu, t, o);
        if (lane == 0) sh[0] = t;
    }
    __syncthreads();
    return sh[0];
}

__global__ void init_dec_kernel() {
    float d = 1.f;
    for (int i = 0; i < T_; i++) { g_DEC[i] = d; d *= DECF; }
}

__global__ void zero_cs_kernel() {
    g_CS[blockIdx.x * 256 + threadIdx.x] = 0.f;
}

__global__ void screc_kernel() {
    int b = threadIdx.x;
    if (b >= B_) return;
    float sprev = 0.f;
    for (int t = 0; t < T_; t++) {
        float sumx = __fdividef(sprev, sprev + EPSF);
        float s = DECF * sumx + g_CS[b * T_ + t];
        g_Cc[b * T_ + t] = __fdividef(1.f, s + EPSF);
        sprev = s;
    }
}

__global__ void xrecur_kernel() {
    int b = blockIdx.y;
    int n = blockIdx.x * 256 + threadIdx.x;
    __shared__ float sc[T_];
    sc[threadIdx.x] = g_Cc[b * T_ + threadIdx.x];
    __syncthreads();
    float x = 0.f;
    long base = (long)b * T_ * N_ + n;
    for (int t = 0; t < T_; t++) {
        float p = g_X[base + (long)t * N_];
        x = (DECF * x + p) * sc[t];
        __nv_bfloat16 h = __float2bfloat16(x);
        g_Xh[base + (long)t * N_] = h;
        g_Xl[base + (long)t * N_] = __float2bfloat16(x - __bfloat162float(h));
    }
}

template <int HILO>
__global__ void ln_rows(const float* __restrict__ in, float* __restrict__ outf,
                        __nv_bfloat16* __restrict__ oh, __nv_bfloat16* __restrict__ ol,
                        const int* __restrict__ gidx)
{
    int m = blockIdx.x;
    long r = gidx ? (long)gidx[m] : (long)m;
    float z = in[r * D_ + threadIdx.x];
    float mean = blockReduceSum256(z) * (1.f / D_);
    float d = z - mean;
    float var = blockReduceSum256(d * d) * (1.f / (D_ - 1));
    float v = d / (sqrtf(var) + EPSF);
    long o = (long)m * D_ + threadIdx.x;
    if (HILO) {
        __nv_bfloat16 h = __float2bfloat16(v);
        oh[o] = h;
        ol[o] = __float2bfloat16(v - __bfloat162float(h));
    } else {
        outf[o] = v;
    }
}

__global__ void conv_hilo_kernel(const float* __restrict__ in,
                                 __nv_bfloat16* __restrict__ hi,
                                 __nv_bfloat16* __restrict__ lo, long n4)
{
    long i = (long)blockIdx.x * blockDim.x + threadIdx.x;
    if (i >= n4) return;
    float4 v = reinterpret_cast<const float4*>(in)[i];
    float vv[4] = {v.x, v.y, v.z, v.w};
    unsigned short hs[4], ls[4];
#pragma unroll
    for (int j = 0; j < 4; j++) {
        __nv_bfloat16 h = __float2bfloat16(vv[j]);
        __nv_bfloat16 l = __float2bfloat16(vv[j] - __bfloat162float(h));
        hs[j] = __bfloat16_as_ushort(h);
        ls[j] = __bfloat16_as_ushort(l);
    }
    reinterpret_cast<ushort4*>(hi)[i] = make_ushort4(hs[0], hs[1], hs[2], hs[3]);
    reinterpret_cast<ushort4*>(lo)[i] = make_ushort4(ls[0], ls[1], ls[2], ls[3]);
}

__global__ void gatherconv_kernel(const float* __restrict__ emb, const int* __restrict__ idx,
                                  __nv_bfloat16* __restrict__ hi, __nv_bfloat16* __restrict__ lo)
{
    int m = blockIdx.x;
    int t = threadIdx.x;   // 64 threads, float4 each
    float4 v = *reinterpret_cast<const float4*>(emb + (long)idx[m] * D_ + t * 4);
    float vv[4] = {v.x, v.y, v.z, v.w};
    unsigned short hs[4], ls[4];
#pragma unroll
    for (int j = 0; j < 4; j++) {
        __nv_bfloat16 h = __float2bfloat16(vv[j]);
        __nv_bfloat16 l = __float2bfloat16(vv[j] - __bfloat162float(h));
        hs[j] = __bfloat16_as_ushort(h);
        ls[j] = __bfloat16_as_ushort(l);
    }
    long o4 = (long)m * (D_ / 4) + t;
    reinterpret_cast<ushort4*>(hi)[o4] = make_ushort4(hs[0], hs[1], hs[2], hs[3]);
    reinterpret_cast<ushort4*>(lo)[o4] = make_ushort4(ls[0], ls[1], ls[2], ls[3]);
}

// ---------------- launch ----------------
extern "C" void kernel_launch(void* const* d_in, const int* in_sizes, int n_in,
                              void* d_out, int out_size)
{
    (void)in_sizes; (void)n_in; (void)out_size;
    const int*   idx  = (const int*)d_in[0];
    const float* temb = (const float*)d_in[1];
    const float* E    = (const float*)d_in[2];
    const float* Dx   = (const float*)d_in[3];
    const float* Dy   = (const float*)d_in[4];
    float* out = (float*)d_out;

    float *pX, *pU, *pS, *pA, *pO;
    __nv_bfloat16 *pVh, *pVl, *pDxh, *pDxl, *pDyh, *pDyl, *pEh, *pEl;
    __nv_bfloat16 *pXh, *pXl, *pAh, *pAl, *pYh, *pYl;
    cudaGetSymbolAddress((void**)&pX,  g_X);
    cudaGetSymbolAddress((void**)&pU,  g_U);
    cudaGetSymbolAddress((void**)&pS,  g_S);
    cudaGetSymbolAddress((void**)&pA,  g_A);
    cudaGetSymbolAddress((void**)&pO,  g_O);
    cudaGetSymbolAddress((void**)&pVh, g_Vh);  cudaGetSymbolAddress((void**)&pVl, g_Vl);
    cudaGetSymbolAddress((void**)&pDxh, g_Dxh); cudaGetSymbolAddress((void**)&pDxl, g_Dxl);
    cudaGetSymbolAddress((void**)&pDyh, g_Dyh); cudaGetSymbolAddress((void**)&pDyl, g_Dyl);
    cudaGetSymbolAddress((void**)&pEh, g_Eh);  cudaGetSymbolAddress((void**)&pEl, g_El);
    cudaGetSymbolAddress((void**)&pXh, g_Xh);  cudaGetSymbolAddress((void**)&pXl, g_Xl);
    cudaGetSymbolAddress((void**)&pAh, g_Ah);  cudaGetSymbolAddress((void**)&pAl, g_Al);
    cudaGetSymbolAddress((void**)&pYh, g_Yh);  cudaGetSymbolAddress((void**)&pYl, g_Yl);

    const int SM3 = 3 * 4 * TILE_B;   // 98304
    const int SM1 = 3 * 2 * TILE_B;   // 49152
    cudaFuncSetAttribute(mma_nt<EPI_RELU, 3>,     cudaFuncAttributeMaxDynamicSharedMemorySize, SM3);
    cudaFuncSetAttribute(mma_nt<EPI_DECAY, 1>,    cudaFuncAttributeMaxDynamicSharedMemorySize, SM1);
    cudaFuncSetAttribute(mma_nt<EPI_RELUMULX, 3>, cudaFuncAttributeMaxDynamicSharedMemorySize, SM3);
    cudaFuncSetAttribute(mma_nt<EPI_NONE, 3>,     cudaFuncAttributeMaxDynamicSharedMemorySize, SM3);

    init_dec_kernel<<<1, 1>>>();

    // weight + embedding conversions to bf16 hi/lo
    conv_hilo_kernel<<<(N_ * D_ / 4 + 255) / 256, 256>>>(Dx, pDxh, pDxl, N_ * D_ / 4);
    conv_hilo_kernel<<<(N_ * D_ / 4 + 255) / 256, 256>>>(Dy, pDyh, pDyl, N_ * D_ / 4);
    conv_hilo_kernel<<<(D_ * N_ / 4 + 255) / 256, 256>>>(E,  pEh,  pEl,  D_ * N_ / 4);
    gatherconv_kernel<<<M_, 64>>>(temb, idx, pVh, pVl);
    zero_cs_kernel<<<M_ / 256, 256>>>();

    // G1: P = relu(emb[idx] @ Dx^T) -> g_X (fp32), fused row-sum -> g_CS
    mma_nt<EPI_RELU, 3><<<dim3(N_ / 128, M_ / 128, 1), 256, SM3>>>(
        pVh, pVl, pDxh, pDxl, pX, nullptr, nullptr, nullptr, nullptr, N_, D_, 0, 0, 0);

    // scalar L1 recurrence + parallel x scan; emits x as bf16 hi/lo directly
    screc_kernel<<<1, 32>>>();
    xrecur_kernel<<<dim3(N_ / 256, B_, 1), 256>>>();

    // U = LN(emb[idx])
    ln_rows<0><<<M_, 256>>>(temb, pU, nullptr, nullptr, idx);

    // scores: S[b,t,s] = 0.97^(t-s) * <x_t, x_s>, s < t  (single-pass bf16: positive sums)
    mma_nt<EPI_DECAY, 1><<<dim3(T_ / 128, T_ / 128, B_), 256, SM1>>>(
        pXh, pXh, pXh, pXh, pS, nullptr, nullptr, nullptr, nullptr, T_, N_,
        (long)T_ * N_, (long)T_ * N_, (long)T_ * T_);

    // a* = S @ U  (SIMT, small)
    gemm_nn<<<dim3(D_ / GBN, T_ / GBM, B_), 256>>>(
        pS, pU, pA, T_, D_, T_, (long)T_ * T_, (long)T_ * D_, (long)T_ * D_);

    // a* <- LN(a*) -> bf16 hi/lo directly
    ln_rows<1><<<M_, 256>>>(pA, nullptr, pAh, pAl, nullptr);

    // G2: y = relu(LN(a*) @ Dy^T) * x -> bf16 hi/lo directly
    mma_nt<EPI_RELUMULX, 3><<<dim3(N_ / 128, M_ / 128, 1), 256, SM3>>>(
        pAh, pAl, pDyh, pDyl, nullptr, pYh, pYl, pXh, pXl, N_, D_, 0, 0, 0);

    // G3: o = y @ E^T -> g_O
    mma_nt<EPI_NONE, 3><<<dim3(D_ / 128, M_ / 128, 1), 256, SM3>>>(
        pYh, pYl, pEh, pEl, pO, nullptr, nullptr, nullptr, nullptr, D_, N_, 0, 0, 0);

    // out = LN(o)
    ln_rows<0><<<M_, 256>>>(pO, out, nullptr, nullptr, nullptr);
}

// round 6
// speedup vs baseline: 2.6359x; 1.0504x over previous
#include <cuda_runtime.h>
#include <cuda_bf16.h>
#include <cstdint>

#define B_   32
#define T_   256
#define N_   4096
#define D_   256
#define M_   (B_ * T_)
#define EPSF 1e-6f
#define DECF 0.97f

// ---------------- scratch (device globals; no allocation) ----------------
__device__ float g_X [(long long)M_ * N_];      // P (fp32 scan domain)
__device__ float g_CS[M_];
__device__ float g_Cc[M_];
__device__ float g_U [M_ * D_];
__device__ float g_S [(long long)B_ * T_ * T_];
__device__ float g_A [M_ * D_];
__device__ float g_O [M_ * D_];
__device__ float g_DEC[T_];

// bf16 hi/lo split operands
__device__ __nv_bfloat16 g_Vh [M_ * D_],  g_Vl [M_ * D_];     // emb[idx]
__device__ __nv_bfloat16 g_Dxh[N_ * D_],  g_Dxl[N_ * D_];
__device__ __nv_bfloat16 g_Dyh[N_ * D_],  g_Dyl[N_ * D_];
__device__ __nv_bfloat16 g_Eh [D_ * N_],  g_El [D_ * N_];
__device__ __nv_bfloat16 g_Xh [(long long)M_ * N_], g_Xl[(long long)M_ * N_];
__device__ __nv_bfloat16 g_Ah [M_ * D_],  g_Al [M_ * D_];
__device__ __nv_bfloat16 g_Yh [(long long)M_ * N_], g_Yl[(long long)M_ * N_];

// ---------------- PTX helpers (baseline ISA only) ----------------
__device__ __forceinline__ uint32_t smem_u32(const void* p) {
    uint32_t a;
    asm("{ .reg .u64 t; cvta.to.shared.u64 t, %1; cvt.u32.u64 %0, t; }" : "=r"(a) : "l"(p));
    return a;
}
__device__ __forceinline__ void cp16(uint32_t so, const void* g) {
    asm volatile("cp.async.cg.shared.global [%0], [%1], 16;" :: "r"(so), "l"(g));
}
__device__ __forceinline__ void cp_commit() {
    asm volatile("cp.async.commit_group;" ::: "memory");
}
template <int NN>
__device__ __forceinline__ void cp_wait() {
    asm volatile("cp.async.wait_group %0;" :: "n"(NN) : "memory");
}
__device__ __forceinline__ void ldsm_x4(uint32_t* f, uint32_t a) {
    asm volatile("ldmatrix.sync.aligned.m8n8.x4.shared.b16 {%0,%1,%2,%3}, [%4];"
        : "=r"(f[0]), "=r"(f[1]), "=r"(f[2]), "=r"(f[3]) : "r"(a));
}
__device__ __forceinline__ void mma16816(float* c, const uint32_t* a, const uint32_t* b) {
    asm volatile("mma.sync.aligned.m16n8k16.row.col.f32.bf16.bf16.f32 "
        "{%0,%1,%2,%3}, {%4,%5,%6,%7}, {%8,%9}, {%0,%1,%2,%3};"
        : "+f"(c[0]), "+f"(c[1]), "+f"(c[2]), "+f"(c[3])
        : "r"(a[0]), "r"(a[1]), "r"(a[2]), "r"(a[3]), "r"(b[0]), "r"(b[1]));
}

// ---------------- HMMA NT GEMM: C[m,n] = sum_k A[m,k]*B[n,k] ----------------
enum { EPI_NONE = 0, EPI_RELU = 1, EPI_RELUMULX = 2, EPI_DECAY = 3 };

// swizzled tile: 128 rows x 64B (32 bf16); phys 16B-slot = g ^ ((r>>1)&3)
#define TILE_B 8192

template <int EPI, int NPASS>
__global__ void __launch_bounds__(256, 2) mma_nt(
    const __nv_bfloat16* __restrict__ Ah, const __nv_bfloat16* __restrict__ Al,
    const __nv_bfloat16* __restrict__ Bh, const __nv_bfloat16* __restrict__ Bl,
    float* __restrict__ Cf, __nv_bfloat16* __restrict__ Ch, __nv_bfloat16* __restrict__ Cl,
    const __nv_bfloat16* __restrict__ Xh, const __nv_bfloat16* __restrict__ Xl,
    int Nd, int K, long sA, long sB, long sC)
{
    constexpr int NTILES  = (NPASS == 3) ? 4 : 2;
    constexpr int STAGE_B = NTILES * TILE_B;

    extern __shared__ char smem[];
    const uint32_t sb = smem_u32(smem);
    const int tid  = threadIdx.x;
    const int lane = tid & 31;
    const int wid  = tid >> 5;
    const int wm   = wid >> 2;          // 0..1  -> m offset wm*64
    const int wn   = wid & 3;           // 0..3  -> n offset wn*32
    const int bz = blockIdx.z;
    const int bm = blockIdx.y * 128;
    const int bn = blockIdx.x * 128;
    const bool skip = (EPI == EPI_DECAY) && (bn >= bm + 128);

    float acc[4][4][4];
#pragma unroll
    for (int i = 0; i < 4; i++)
#pragma unroll
        for (int j = 0; j < 4; j++)
#pragma unroll
            for (int v = 0; v < 4; v++) acc[i][j][v] = 0.f;

    if (!skip) {
        const __nv_bfloat16* Ahp = Ah + (long)bz * sA + (long)bm * K;
        const __nv_bfloat16* Alp = Al + (long)bz * sA + (long)bm * K;
        const __nv_bfloat16* Bhp = Bh + (long)bz * sB + (long)bn * K;
        const __nv_bfloat16* Blp = Bl + (long)bz * sB + (long)bn * K;

        const int qr0 = tid >> 2;             // row (0..63)
        const int qc0 = tid & 3;              // 16B group
        auto stage_load = [&](int stg, int k0) {
            uint32_t base = sb + stg * STAGE_B;
#pragma unroll
            for (int i = 0; i < 2; i++) {
                int r = qr0 + i * 64;
                uint32_t so = (uint32_t)(r * 64 + ((qc0 ^ ((r >> 1) & 3)) * 16));
                long gofs = (long)r * K + k0 + qc0 * 8;
                cp16(base + so,              Ahp + gofs);
                cp16(base + TILE_B + so,     Bhp + gofs);
                if (NPASS == 3) {
                    cp16(base + 2 * TILE_B + so, Alp + gofs);
                    cp16(base + 3 * TILE_B + so, Blp + gofs);
                }
            }
            cp_commit();
        };

        const int nC = K / 32;
        stage_load(0, 0);
        stage_load(1, 32);

        // per-lane ldsm logical positions
        const uint32_t aRow  = (uint32_t)(wm * 64 + (lane & 15));
        const uint32_t aColG = (uint32_t)(lane >> 4);                         // 0..1
        const uint32_t bRow  = (uint32_t)(wn * 32 + ((lane >> 4) << 3) + (lane & 7));
        const uint32_t bColG = (uint32_t)((lane >> 3) & 1);
        const uint32_t sa = (aRow >> 1) & 3;
        const uint32_t sbw = (bRow >> 1) & 3;
        uint32_t aoff[2], boff[2];
#pragma unroll
        for (int ks = 0; ks < 2; ks++) {
            aoff[ks] = aRow * 64 + (((ks * 2 + aColG) ^ sa) * 16);
            boff[ks] = bRow * 64 + (((ks * 2 + bColG) ^ sbw) * 16);
        }

        int stg = 0;
        for (int c = 0; c < nC; c++) {
            cp_wait<1>();
            __syncthreads();
            if (c + 2 < nC) {
                int ns = stg + 2; if (ns >= 3) ns -= 3;
                stage_load(ns, (c + 2) * 32);
            } else {
                cp_commit();   // empty group keeps wait<1> accounting uniform
            }

            const uint32_t st = sb + stg * STAGE_B;
#pragma unroll
            for (int ks = 0; ks < 2; ks++) {
                uint32_t fA[4][4], fB[2][4], fB2[2][4];
                // pass 1: Ah . Bh
#pragma unroll
                for (int ma = 0; ma < 4; ma++)
                    ldsm_x4(fA[ma], st + aoff[ks] + ma * 1024);
#pragma unroll
                for (int p = 0; p < 2; p++)
                    ldsm_x4(fB[p], st + TILE_B + boff[ks] + p * 1024);
#pragma unroll
                for (int ma = 0; ma < 4; ma++)
#pragma unroll
                    for (int na = 0; na < 4; na++)
                        mma16816(acc[ma][na], fA[ma], &fB[na >> 1][2 * (na & 1)]);
                if (NPASS == 3) {
                    // pass 2: Ah . Bl (Ah stays live)
#pragma unroll
                    for (int p = 0; p < 2; p++)
                        ldsm_x4(fB2[p], st + 3 * TILE_B + boff[ks] + p * 1024);
#pragma unroll
                    for (int ma = 0; ma < 4; ma++)
#pragma unroll
                        for (int na = 0; na < 4; na++)
                            mma16816(acc[ma][na], fA[ma], &fB2[na >> 1][2 * (na & 1)]);
                    // pass 3: Al . Bh (overwrite fA with Al; Bh still live)
#pragma unroll
                    for (int ma = 0; ma < 4; ma++)
                        ldsm_x4(fA[ma], st + 2 * TILE_B + aoff[ks] + ma * 1024);
#pragma unroll
                    for (int ma = 0; ma < 4; ma++)
#pragma unroll
                        for (int na = 0; na < 4; na++)
                            mma16816(acc[ma][na], fA[ma], &fB[na >> 1][2 * (na & 1)]);
                }
            }
            stg = (stg == 2) ? 0 : stg + 1;
        }
    }

    // ---- epilogue ----
    const int gr = lane >> 2;          // 0..7
    const int gc = (lane & 3) * 2;
#pragma unroll
    for (int ma = 0; ma < 4; ma++) {
#pragma unroll
        for (int half = 0; half < 2; half++) {
            const int row = bm + wm * 64 + ma * 16 + gr + half * 8;
            float rs = 0.f;
#pragma unroll
            for (int na = 0; na < 4; na++) {
                const int col = bn + wn * 32 + na * 8 + gc;
                float v0 = acc[ma][na][half * 2 + 0];
                float v1 = acc[ma][na][half * 2 + 1];
                long off = (long)row * Nd + col;
                if (EPI == EPI_RELUMULX) {
                    ushort2 xh = *reinterpret_cast<const ushort2*>(Xh + off);
                    ushort2 xl = *reinterpret_cast<const ushort2*>(Xl + off);
                    float x0 = __bfloat162float(__ushort_as_bfloat16(xh.x)) +
                               __bfloat162float(__ushort_as_bfloat16(xl.x));
                    float x1 = __bfloat162float(__ushort_as_bfloat16(xh.y)) +
                               __bfloat162float(__ushort_as_bfloat16(xl.y));
                    v0 = fmaxf(v0, 0.f) * x0;
                    v1 = fmaxf(v1, 0.f) * x1;
                    __nv_bfloat16 h0 = __float2bfloat16(v0), h1 = __float2bfloat16(v1);
                    __nv_bfloat16 l0 = __float2bfloat16(v0 - __bfloat162float(h0));
                    __nv_bfloat16 l1 = __float2bfloat16(v1 - __bfloat162float(h1));
                    *reinterpret_cast<ushort2*>(Ch + off) =
                        make_ushort2(__bfloat16_as_ushort(h0), __bfloat16_as_ushort(h1));
                    *reinterpret_cast<ushort2*>(Cl + off) =
                        make_ushort2(__bfloat16_as_ushort(l0), __bfloat16_as_ushort(l1));
                } else {
                    if (EPI == EPI_RELU) {
                        v0 = fmaxf(v0, 0.f); v1 = fmaxf(v1, 0.f);
                        rs += v0 + v1;
                    } else if (EPI == EPI_DECAY) {
                        int L0 = row - col, L1 = row - col - 1;
                        v0 = (L0 > 0) ? v0 * g_DEC[L0] : 0.f;
                        v1 = (L1 > 0) ? v1 * g_DEC[L1] : 0.f;
                    }
                    *reinterpret_cast<float2*>(Cf + (long)bz * sC + off) = make_float2(v0, v1);
                }
            }
            if (EPI == EPI_RELU) {   // fused partial row-sum for L1 norm
                rs += __shfl_xor_sync(0xffffffffu, rs, 1);
                rs += __shfl_xor_sync(0xffffffffu, rs, 2);
                if ((lane & 3) == 0) atomicAdd(&g_CS[row], rs);
            }
        }
    }
}

// ---------------- SIMT NN GEMM (a* = S @ U, small) ----------------
#define GBM 128
#define GBN 64
#define GBK 16
#define GTM 8
#define GTN 4

__global__ __launch_bounds__(256)
void gemm_nn(const float* __restrict__ A, const float* __restrict__ B,
             float* __restrict__ C, int M, int Nd, int K,
             long batchA, long batchB, long batchC)
{
    const int bz = blockIdx.z;
    A += (long)bz * batchA;
    B += (long)bz * batchB;
    C += (long)bz * batchC;
    const int bm = blockIdx.y * GBM;
    const int bn = blockIdx.x * GBN;

    __shared__ __align__(16) float As[GBK][GBM + 4];
    __shared__ __align__(16) float Bs[GBK][GBN + 4];

    const int tid = threadIdx.x;
    const int tx = tid & 15;
    const int ty = tid >> 4;

    float acc[GTM][GTN];
#pragma unroll
    for (int i = 0; i < GTM; i++)
#pragma unroll
        for (int j = 0; j < GTN; j++) acc[i][j] = 0.f;

    const int lr = tid >> 2;
    const int lk = (tid & 3) * 4;
    const int brow = tid >> 4;
    const int bcol = (tid & 15) * 4;

    for (int k0 = 0; k0 < K; k0 += GBK) {
#pragma unroll
        for (int i = 0; i < 2; i++) {
            int r = lr + i * 64;
            float4 v = *reinterpret_cast<const float4*>(A + (long)(bm + r) * K + k0 + lk);
            As[lk + 0][r] = v.x; As[lk + 1][r] = v.y;
            As[lk + 2][r] = v.z; As[lk + 3][r] = v.w;
        }
        {
            float4 v = *reinterpret_cast<const float4*>(B + (long)(k0 + brow) * Nd + bn + bcol);
            Bs[brow][bcol + 0] = v.x; Bs[brow][bcol + 1] = v.y;
            Bs[brow][bcol + 2] = v.z; Bs[brow][bcol + 3] = v.w;
        }
        __syncthreads();
#pragma unroll
        for (int kk = 0; kk < GBK; kk++) {
            float af[GTM], bf[GTN];
#pragma unroll
            for (int i = 0; i < GTM; i++) af[i] = As[kk][ty * GTM + i];
#pragma unroll
            for (int j = 0; j < GTN; j++) bf[j] = Bs[kk][tx * GTN + j];
#pragma unroll
            for (int i = 0; i < GTM; i++)
#pragma unroll
                for (int j = 0; j < GTN; j++)
                    acc[i][j] = fmaf(af[i], bf[j], acc[i][j]);
        }
        __syncthreads();
    }
#pragma unroll
    for (int i = 0; i < GTM; i++) {
        int row = bm + ty * GTM + i;
        long cbase = (long)row * Nd + bn + tx * GTN;
        *reinterpret_cast<float4*>(C + cbase) = make_float4(acc[i][0], acc[i][1], acc[i][2], acc[i][3]);
    }
}

// ---------------- elementwise / scan / LN kernels ----------------
__device__ __forceinline__ float blockReduceSum256(float v) {
    __shared__ float sh[8];
    __syncthreads();
    int lane = threadIdx.x & 31;
    int w = threadIdx.x >> 5;
#pragma unroll
    for (int o = 16; o > 0; o >>= 1) v += __shfl_down_sync(0xffffffffu, v, o);
    if (lane == 0) sh[w] = v;
    __syncthreads();
    if (w == 0) {
        float t = (lane < 8) ? sh[lane] : 0.f;
#pragma unroll
        for (int o = 4; o > 0; o >>= 1) t += __shfl_down_sync(0xffffffffu, t, o);
        if (lane == 0) sh[0] = t;
    }
    __syncthreads();
    return sh[0];
}

// fused conversion of Dx, Dy, E + g_DEC init (single launch)
__global__ void conv_all_kernel(const float* __restrict__ Dx, const float* __restrict__ Dy,
                                const float* __restrict__ E)
{
    int blk = blockIdx.x;
    const float* src;
    __nv_bfloat16 *hi, *lo;
    int local;
    if (blk < 1024)      { src = Dx; hi = g_Dxh; lo = g_Dxl; local = blk; }
    else if (blk < 2048) { src = Dy; hi = g_Dyh; lo = g_Dyl; local = blk - 1024; }
    else                 { src = E;  hi = g_Eh;  lo = g_El;  local = blk - 2048; }
    long i = (long)local * 256 + threadIdx.x;
    float4 v = reinterpret_cast<const float4*>(src)[i];
    float vv[4] = {v.x, v.y, v.z, v.w};
    unsigned short hs[4], ls[4];
#pragma unroll
    for (int j = 0; j < 4; j++) {
        __nv_bfloat16 h = __float2bfloat16(vv[j]);
        __nv_bfloat16 l = __float2bfloat16(vv[j] - __bfloat162float(h));
        hs[j] = __bfloat16_as_ushort(h);
        ls[j] = __bfloat16_as_ushort(l);
    }
    reinterpret_cast<ushort4*>(hi)[i] = make_ushort4(hs[0], hs[1], hs[2], hs[3]);
    reinterpret_cast<ushort4*>(lo)[i] = make_ushort4(ls[0], ls[1], ls[2], ls[3]);
    if (blk == 0 && threadIdx.x == 0) {
        float d = 1.f;
        for (int t = 0; t < T_; t++) { g_DEC[t] = d; d *= DECF; }
    }
}

// gather emb[idx] -> bf16 hi/lo, and zero g_CS
__global__ void gatherconv_kernel(const float* __restrict__ emb, const int* __restrict__ idx)
{
    int m = blockIdx.x;
    int t = threadIdx.x;   // 64 threads, float4 each
    if (t == 0) g_CS[m] = 0.f;
    float4 v = *reinterpret_cast<const float4*>(emb + (long)idx[m] * D_ + t * 4);
    float vv[4] = {v.x, v.y, v.z, v.w};
    unsigned short hs[4], ls[4];
#pragma unroll
    for (int j = 0; j < 4; j++) {
        __nv_bfloat16 h = __float2bfloat16(vv[j]);
        __nv_bfloat16 l = __float2bfloat16(vv[j] - __bfloat162float(h));
        hs[j] = __bfloat16_as_ushort(h);
        ls[j] = __bfloat16_as_ushort(l);
    }
    long o4 = (long)m * (D_ / 4) + t;
    reinterpret_cast<ushort4*>(g_Vh)[o4] = make_ushort4(hs[0], hs[1], hs[2], hs[3]);
    reinterpret_cast<ushort4*>(g_Vl)[o4] = make_ushort4(ls[0], ls[1], ls[2], ls[3]);
}

__global__ void screc_kernel() {
    int b = threadIdx.x;
    if (b >= B_) return;
    float sprev = 0.f;
    for (int t = 0; t < T_; t++) {
        float sumx = __fdividef(sprev, sprev + EPSF);
        float s = DECF * sumx + g_CS[b * T_ + t];
        g_Cc[b * T_ + t] = __fdividef(1.f, s + EPSF);
        sprev = s;
    }
}

__global__ void xrecur_kernel() {
    int b = blockIdx.y;
    int n = blockIdx.x * 256 + threadIdx.x;
    __shared__ float sc[T_];
    sc[threadIdx.x] = g_Cc[b * T_ + threadIdx.x];
    __syncthreads();
    float x = 0.f;
    long base = (long)b * T_ * N_ + n;
    for (int t = 0; t < T_; t++) {
        float p = g_X[base + (long)t * N_];
        x = (DECF * x + p) * sc[t];
        __nv_bfloat16 h = __float2bfloat16(x);
        g_Xh[base + (long)t * N_] = h;
        g_Xl[base + (long)t * N_] = __float2bfloat16(x - __bfloat162float(h));
    }
}

template <int HILO>
__global__ void ln_rows(const float* __restrict__ in, float* __restrict__ outf,
                        __nv_bfloat16* __restrict__ oh, __nv_bfloat16* __restrict__ ol,
                        const int* __restrict__ gidx)
{
    int m = blockIdx.x;
    long r = gidx ? (long)gidx[m] : (long)m;
    float z = in[r * D_ + threadIdx.x];
    float mean = blockReduceSum256(z) * (1.f / D_);
    float d = z - mean;
    float var = blockReduceSum256(d * d) * (1.f / (D_ - 1));
    float v = d / (sqrtf(var) + EPSF);
    long o = (long)m * D_ + threadIdx.x;
    if (HILO) {
        __nv_bfloat16 h = __float2bfloat16(v);
        oh[o] = h;
        ol[o] = __float2bfloat16(v - __bfloat162float(h));
    } else {
        outf[o] = v;
    }
}

// ---------------- launch ----------------
extern "C" void kernel_launch(void* const* d_in, const int* in_sizes, int n_in,
                              void* d_out, int out_size)
{
    (void)in_sizes; (void)n_in; (void)out_size;
    const int*   idx  = (const int*)d_in[0];
    const float* temb = (const float*)d_in[1];
    const float* E    = (const float*)d_in[2];
    const float* Dx   = (const float*)d_in[3];
    const float* Dy   = (const float*)d_in[4];
    float* out = (float*)d_out;

    float *pX, *pU, *pS, *pA, *pO;
    __nv_bfloat16 *pVh, *pVl, *pDxh, *pDxl, *pDyh, *pDyl, *pEh, *pEl;
    __nv_bfloat16 *pXh, *pXl, *pAh, *pAl, *pYh, *pYl;
    cudaGetSymbolAddress((void**)&pX,  g_X);
    cudaGetSymbolAddress((void**)&pU,  g_U);
    cudaGetSymbolAddress((void**)&pS,  g_S);
    cudaGetSymbolAddress((void**)&pA,  g_A);
    cudaGetSymbolAddress((void**)&pO,  g_O);
    cudaGetSymbolAddress((void**)&pVh, g_Vh);  cudaGetSymbolAddress((void**)&pVl, g_Vl);
    cudaGetSymbolAddress((void**)&pDxh, g_Dxh); cudaGetSymbolAddress((void**)&pDxl, g_Dxl);
    cudaGetSymbolAddress((void**)&pDyh, g_Dyh); cudaGetSymbolAddress((void**)&pDyl, g_Dyl);
    cudaGetSymbolAddress((void**)&pEh, g_Eh);  cudaGetSymbolAddress((void**)&pEl, g_El);
    cudaGetSymbolAddress((void**)&pXh, g_Xh);  cudaGetSymbolAddress((void**)&pXl, g_Xl);
    cudaGetSymbolAddress((void**)&pAh, g_Ah);  cudaGetSymbolAddress((void**)&pAl, g_Al);
    cudaGetSymbolAddress((void**)&pYh, g_Yh);  cudaGetSymbolAddress((void**)&pYl, g_Yl);

    const int SM3 = 3 * 4 * TILE_B;   // 98304
    const int SM1 = 3 * 2 * TILE_B;   // 49152
    cudaFuncSetAttribute(mma_nt<EPI_RELU, 3>,     cudaFuncAttributeMaxDynamicSharedMemorySize, SM3);
    cudaFuncSetAttribute(mma_nt<EPI_DECAY, 1>,    cudaFuncAttributeMaxDynamicSharedMemorySize, SM1);
    cudaFuncSetAttribute(mma_nt<EPI_RELUMULX, 3>, cudaFuncAttributeMaxDynamicSharedMemorySize, SM3);
    cudaFuncSetAttribute(mma_nt<EPI_NONE, 3>,     cudaFuncAttributeMaxDynamicSharedMemorySize, SM3);

    // launch 0: fused weight conversions (+g_DEC)
    conv_all_kernel<<<3072, 256>>>(Dx, Dy, E);
    // launch 1: embedding gather/convert (+g_CS zero)
    gatherconv_kernel<<<M_, 64>>>(temb, idx);
    // launch 2: U = LN(emb[idx])  (independent of G1; placed here so G1 is launch #3)
    ln_rows<0><<<M_, 256>>>(temb, pU, nullptr, nullptr, idx);

    // launch 3: G1: P = relu(emb[idx] @ Dx^T) -> g_X (fp32), fused row-sum -> g_CS
    mma_nt<EPI_RELU, 3><<<dim3(N_ / 128, M_ / 128, 1), 256, SM3>>>(
        pVh, pVl, pDxh, pDxl, pX, nullptr, nullptr, nullptr, nullptr, N_, D_, 0, 0, 0);

    // scalar L1 recurrence + parallel x scan; emits x as bf16 hi/lo directly
    screc_kernel<<<1, 32>>>();
    xrecur_kernel<<<dim3(N_ / 256, B_, 1), 256>>>();

    // scores: S[b,t,s] = 0.97^(t-s) * <x_t, x_s>, s < t  (single-pass bf16: positive sums)
    mma_nt<EPI_DECAY, 1><<<dim3(T_ / 128, T_ / 128, B_), 256, SM1>>>(
        pXh, pXh, pXh, pXh, pS, nullptr, nullptr, nullptr, nullptr, T_, N_,
        (long)T_ * N_, (long)T_ * N_, (long)T_ * T_);

    // a* = S @ U  (SIMT, small)
    gemm_nn<<<dim3(D_ / GBN, T_ / GBM, B_), 256>>>(
        pS, pU, pA, T_, D_, T_, (long)T_ * T_, (long)T_ * D_, (long)T_ * D_);

    // a* <- LN(a*) -> bf16 hi/lo directly
    ln_rows<1><<<M_, 256>>>(pA, nullptr, pAh, pAl, nullptr);

    // G2: y = relu(LN(a*) @ Dy^T) * x -> bf16 hi/lo directly
    mma_nt<EPI_RELUMULX, 3><<<dim3(N_ / 128, M_ / 128, 1), 256, SM3>>>(
        pAh, pAl, pDyh, pDyl, nullptr, pYh, pYl, pXh, pXl, N_, D_, 0, 0, 0);

    // G3: o = y @ E^T -> g_O
    mma_nt<EPI_NONE, 3><<<dim3(D_ / 128, M_ / 128, 1), 256, SM3>>>(
        pYh, pYl, pEh, pEl, pO, nullptr, nullptr, nullptr, nullptr, D_, N_, 0, 0, 0);

    // out = LN(o)
    ln_rows<0><<<M_, 256>>>(pO, out, nullptr, nullptr, nullptr);
}

// round 7
// speedup vs baseline: 2.7004x; 1.0245x over previous
#include <cuda_runtime.h>
#include <cuda_bf16.h>
#include <cstdint>

#define B_   32
#define T_   256
#define N_   4096
#define D_   256
#define M_   (B_ * T_)
#define EPSF 1e-6f
#define DECF 0.97f

// ---------------- scratch (device globals; no allocation) ----------------
__device__ float g_X [(long long)M_ * N_];      // P (fp32 scan domain)
__device__ float g_CS[M_];
__device__ float g_Cc[M_];
__device__ float g_U [M_ * D_];
__device__ float g_S [2LL * B_ * T_ * T_];      // 2 split-K partials of raw scores
__device__ float g_A [M_ * D_];
__device__ float g_O [4LL * M_ * D_];           // 4 split-K partials of G3
__device__ float g_DEC[T_];

// bf16 hi/lo split operands
__device__ __nv_bfloat16 g_Vh [M_ * D_],  g_Vl [M_ * D_];     // emb[idx]
__device__ __nv_bfloat16 g_Dxh[N_ * D_],  g_Dxl[N_ * D_];
__device__ __nv_bfloat16 g_Dyh[N_ * D_],  g_Dyl[N_ * D_];
__device__ __nv_bfloat16 g_Eh [D_ * N_],  g_El [D_ * N_];
__device__ __nv_bfloat16 g_Xh [(long long)M_ * N_], g_Xl[(long long)M_ * N_];
__device__ __nv_bfloat16 g_Ah [M_ * D_],  g_Al [M_ * D_];
__device__ __nv_bfloat16 g_Yh [(long long)M_ * N_], g_Yl[(long long)M_ * N_];

// ---------------- PTX helpers (baseline ISA only) ----------------
__device__ __forceinline__ uint32_t smem_u32(const void* p) {
    uint32_t a;
    asm("{ .reg .u64 t; cvta.to.shared.u64 t, %1; cvt.u32.u64 %0, t; }" : "=r"(a) : "l"(p));
    return a;
}
__device__ __forceinline__ void cp16(uint32_t so, const void* g) {
    asm volatile("cp.async.cg.shared.global [%0], [%1], 16;" :: "r"(so), "l"(g));
}
__device__ __forceinline__ void cp_commit() {
    asm volatile("cp.async.commit_group;" ::: "memory");
}
template <int NN>
__device__ __forceinline__ void cp_wait() {
    asm volatile("cp.async.wait_group %0;" :: "n"(NN) : "memory");
}
__device__ __forceinline__ void ldsm_x4(uint32_t* f, uint32_t a) {
    asm volatile("ldmatrix.sync.aligned.m8n8.x4.shared.b16 {%0,%1,%2,%3}, [%4];"
        : "=r"(f[0]), "=r"(f[1]), "=r"(f[2]), "=r"(f[3]) : "r"(a));
}
__device__ __forceinline__ void mma16816(float* c, const uint32_t* a, const uint32_t* b) {
    asm volatile("mma.sync.aligned.m16n8k16.row.col.f32.bf16.bf16.f32 "
        "{%0,%1,%2,%3}, {%4,%5,%6,%7}, {%8,%9}, {%0,%1,%2,%3};"
        : "+f"(c[0]), "+f"(c[1]), "+f"(c[2]), "+f"(c[3])
        : "r"(a[0]), "r"(a[1]), "r"(a[2]), "r"(a[3]), "r"(b[0]), "r"(b[1]));
}

// ---------------- HMMA NT GEMM: C[m,n] = sum_k A[m,k]*B[n,k] ----------------
enum { EPI_NONE = 0, EPI_RELU = 1, EPI_RELUMULX = 2 };

// swizzled tile: 128 rows x 64B (32 bf16); phys 16B-slot = g ^ ((r>>1)&3)
#define TILE_B 8192

template <int EPI, int NPASS, bool TRISKIP>
__global__ void __launch_bounds__(256, 2) mma_nt(
    const __nv_bfloat16* __restrict__ Ah, const __nv_bfloat16* __restrict__ Al,
    const __nv_bfloat16* __restrict__ Bh, const __nv_bfloat16* __restrict__ Bl,
    float* __restrict__ Cf, __nv_bfloat16* __restrict__ Ch, __nv_bfloat16* __restrict__ Cl,
    const __nv_bfloat16* __restrict__ Xh, const __nv_bfloat16* __restrict__ Xl,
    int Nd, int K, int kLen, long sA, long sB, long sC, long splitStride, int batches)
{
    constexpr int NTILES  = (NPASS == 3) ? 4 : 2;
    constexpr int STAGE_B = NTILES * TILE_B;

    extern __shared__ char smem[];
    const uint32_t sb = smem_u32(smem);
    const int tid  = threadIdx.x;
    const int lane = tid & 31;
    const int wid  = tid >> 5;
    const int wm   = wid >> 2;          // 0..1  -> m offset wm*64
    const int wn   = wid & 3;           // 0..3  -> n offset wn*32
    const int zz   = blockIdx.z;
    const int split = zz / batches;
    const int bz    = zz - split * batches;
    const long kOff = (long)split * kLen;
    const int bm = blockIdx.y * 128;
    const int bn = blockIdx.x * 128;
    const bool skip = TRISKIP && (bn >= bm + 128);

    float acc[4][4][4];
#pragma unroll
    for (int i = 0; i < 4; i++)
#pragma unroll
        for (int j = 0; j < 4; j++)
#pragma unroll
            for (int v = 0; v < 4; v++) acc[i][j][v] = 0.f;

    if (!skip) {
        const __nv_bfloat16* Ahp = Ah + (long)bz * sA + (long)bm * K + kOff;
        const __nv_bfloat16* Alp = Al + (long)bz * sA + (long)bm * K + kOff;
        const __nv_bfloat16* Bhp = Bh + (long)bz * sB + (long)bn * K + kOff;
        const __nv_bfloat16* Blp = Bl + (long)bz * sB + (long)bn * K + kOff;

        const int qr0 = tid >> 2;             // row (0..63)
        const int qc0 = tid & 3;              // 16B group
        auto stage_load = [&](int stg, int k0) {
            uint32_t base = sb + stg * STAGE_B;
#pragma unroll
            for (int i = 0; i < 2; i++) {
                int r = qr0 + i * 64;
                uint32_t so = (uint32_t)(r * 64 + ((qc0 ^ ((r >> 1) & 3)) * 16));
                long gofs = (long)r * K + k0 + qc0 * 8;
                cp16(base + so,              Ahp + gofs);
                cp16(base + TILE_B + so,     Bhp + gofs);
                if (NPASS == 3) {
                    cp16(base + 2 * TILE_B + so, Alp + gofs);
                    cp16(base + 3 * TILE_B + so, Blp + gofs);
                }
            }
            cp_commit();
        };

        const int nC = kLen / 32;
        stage_load(0, 0);
        stage_load(1, 32);

        // per-lane ldsm logical positions
        const uint32_t aRow  = (uint32_t)(wm * 64 + (lane & 15));
        const uint32_t aColG = (uint32_t)(lane >> 4);                         // 0..1
        const uint32_t bRow  = (uint32_t)(wn * 32 + ((lane >> 4) << 3) + (lane & 7));
        const uint32_t bColG = (uint32_t)((lane >> 3) & 1);
        const uint32_t sa = (aRow >> 1) & 3;
        const uint32_t sbw = (bRow >> 1) & 3;
        uint32_t aoff[2], boff[2];
#pragma unroll
        for (int ks = 0; ks < 2; ks++) {
            aoff[ks] = aRow * 64 + (((ks * 2 + aColG) ^ sa) * 16);
            boff[ks] = bRow * 64 + (((ks * 2 + bColG) ^ sbw) * 16);
        }

        int stg = 0;
        for (int c = 0; c < nC; c++) {
            cp_wait<1>();
            __syncthreads();
            if (c + 2 < nC) {
                int ns = stg + 2; if (ns >= 3) ns -= 3;
                stage_load(ns, (c + 2) * 32);
            } else {
                cp_commit();   // empty group keeps wait<1> accounting uniform
            }

            const uint32_t st = sb + stg * STAGE_B;
#pragma unroll
            for (int ks = 0; ks < 2; ks++) {
                uint32_t fA[4][4], fB[2][4], fB2[2][4];
                // pass 1: Ah . Bh
#pragma unroll
                for (int ma = 0; ma < 4; ma++)
                    ldsm_x4(fA[ma], st + aoff[ks] + ma * 1024);
#pragma unroll
                for (int p = 0; p < 2; p++)
                    ldsm_x4(fB[p], st + TILE_B + boff[ks] + p * 1024);
#pragma unroll
                for (int ma = 0; ma < 4; ma++)
#pragma unroll
                    for (int na = 0; na < 4; na++)
                        mma16816(acc[ma][na], fA[ma], &fB[na >> 1][2 * (na & 1)]);
                if (NPASS == 3) {
                    // pass 2: Ah . Bl (Ah stays live)
#pragma unroll
                    for (int p = 0; p < 2; p++)
                        ldsm_x4(fB2[p], st + 3 * TILE_B + boff[ks] + p * 1024);
#pragma unroll
                    for (int ma = 0; ma < 4; ma++)
#pragma unroll
                        for (int na = 0; na < 4; na++)
                            mma16816(acc[ma][na], fA[ma], &fB2[na >> 1][2 * (na & 1)]);
                    // pass 3: Al . Bh (overwrite fA with Al; Bh still live)
#pragma unroll
                    for (int ma = 0; ma < 4; ma++)
                        ldsm_x4(fA[ma], st + 2 * TILE_B + aoff[ks] + ma * 1024);
#pragma unroll
                    for (int ma = 0; ma < 4; ma++)
#pragma unroll
                        for (int na = 0; na < 4; na++)
                            mma16816(acc[ma][na], fA[ma], &fB[na >> 1][2 * (na & 1)]);
                }
            }
            stg = (stg == 2) ? 0 : stg + 1;
        }
    }

    // ---- epilogue ----
    float* Cfo = (EPI != EPI_RELUMULX) ? (Cf + split * splitStride + (long)bz * sC) : nullptr;
    const int gr = lane >> 2;          // 0..7
    const int gc = (lane & 3) * 2;
#pragma unroll
    for (int ma = 0; ma < 4; ma++) {
#pragma unroll
        for (int half = 0; half < 2; half++) {
            const int row = bm + wm * 64 + ma * 16 + gr + half * 8;
            float rs = 0.f;
#pragma unroll
            for (int na = 0; na < 4; na++) {
                const int col = bn + wn * 32 + na * 8 + gc;
                float v0 = acc[ma][na][half * 2 + 0];
                float v1 = acc[ma][na][half * 2 + 1];
                long off = (long)row * Nd + col;
                if (EPI == EPI_RELUMULX) {
                    ushort2 xh = *reinterpret_cast<const ushort2*>(Xh + off);
                    ushort2 xl = *reinterpret_cast<const ushort2*>(Xl + off);
                    float x0 = __bfloat162float(__ushort_as_bfloat16(xh.x)) +
                               __bfloat162float(__ushort_as_bfloat16(xl.x));
                    float x1 = __bfloat162float(__ushort_as_bfloat16(xh.y)) +
                               __bfloat162float(__ushort_as_bfloat16(xl.y));
                    v0 = fmaxf(v0, 0.f) * x0;
                    v1 = fmaxf(v1, 0.f) * x1;
                    __nv_bfloat16 h0 = __float2bfloat16(v0), h1 = __float2bfloat16(v1);
                    __nv_bfloat16 l0 = __float2bfloat16(v0 - __bfloat162float(h0));
                    __nv_bfloat16 l1 = __float2bfloat16(v1 - __bfloat162float(h1));
                    *reinterpret_cast<ushort2*>(Ch + off) =
                        make_ushort2(__bfloat16_as_ushort(h0), __bfloat16_as_ushort(h1));
                    *reinterpret_cast<ushort2*>(Cl + off) =
                        make_ushort2(__bfloat16_as_ushort(l0), __bfloat16_as_ushort(l1));
                } else {
                    if (EPI == EPI_RELU) {
                        v0 = fmaxf(v0, 0.f); v1 = fmaxf(v1, 0.f);
                        rs += v0 + v1;
                    }
                    *reinterpret_cast<float2*>(Cfo + off) = make_float2(v0, v1);
                }
            }
            if (EPI == EPI_RELU) {   // fused partial row-sum for L1 norm
                rs += __shfl_xor_sync(0xffffffffu, rs, 1);
                rs += __shfl_xor_sync(0xffffffffu, rs, 2);
                if ((lane & 3) == 0) atomicAdd(&g_CS[row], rs);
            }
        }
    }
}

// ---------------- SIMT NN GEMM: a* = (decayed S) @ U ----------------
// A tile loaded as (S0 + S1) * 0.97^(t-s), masked s<t.
#define GBM 128
#define GBN 64
#define GBK 16
#define GTM 8
#define GTN 4

__global__ __launch_bounds__(256)
void gemm_nn(const float* __restrict__ A0, const float* __restrict__ A1,
             const float* __restrict__ B, float* __restrict__ C,
             int M, int Nd, int K, long batchA, long batchB, long batchC)
{
    const int bz = blockIdx.z;
    A0 += (long)bz * batchA;
    A1 += (long)bz * batchA;
    B  += (long)bz * batchB;
    C  += (long)bz * batchC;
    const int bm = blockIdx.y * GBM;
    const int bn = blockIdx.x * GBN;

    __shared__ __align__(16) float As[GBK][GBM + 4];
    __shared__ __align__(16) float Bs[GBK][GBN + 4];

    const int tid = threadIdx.x;
    const int tx = tid & 15;
    const int ty = tid >> 4;

    float acc[GTM][GTN];
#pragma unroll
    for (int i = 0; i < GTM; i++)
#pragma unroll
        for (int j = 0; j < GTN; j++) acc[i][j] = 0.f;

    const int lr = tid >> 2;
    const int lk = (tid & 3) * 4;
    const int brow = tid >> 4;
    const int bcol = (tid & 15) * 4;

    for (int k0 = 0; k0 < K; k0 += GBK) {
#pragma unroll
        for (int i = 0; i < 2; i++) {
            int r = lr + i * 64;
            int t = bm + r;
            long ao = (long)t * K + k0 + lk;
            float4 v = *reinterpret_cast<const float4*>(A0 + ao);
            float4 w = *reinterpret_cast<const float4*>(A1 + ao);
            float vv[4] = {v.x + w.x, v.y + w.y, v.z + w.z, v.w + w.w};
#pragma unroll
            for (int j = 0; j < 4; j++) {
                int L = t - (k0 + lk + j);
                As[lk + j][r] = (L > 0) ? vv[j] * g_DEC[L] : 0.f;
            }
        }
        {
            float4 v = *reinterpret_cast<const float4*>(B + (long)(k0 + brow) * Nd + bn + bcol);
            Bs[brow][bcol + 0] = v.x; Bs[brow][bcol + 1] = v.y;
            Bs[brow][bcol + 2] = v.z; Bs[brow][bcol + 3] = v.w;
        }
        __syncthreads();
#pragma unroll
        for (int kk = 0; kk < GBK; kk++) {
            float af[GTM], bf[GTN];
#pragma unroll
            for (int i = 0; i < GTM; i++) af[i] = As[kk][ty * GTM + i];
#pragma unroll
            for (int j = 0; j < GTN; j++) bf[j] = Bs[kk][tx * GTN + j];
#pragma unroll
            for (int i = 0; i < GTM; i++)
#pragma unroll
                for (int j = 0; j < GTN; j++)
                    acc[i][j] = fmaf(af[i], bf[j], acc[i][j]);
        }
        __syncthreads();
    }
#pragma unroll
    for (int i = 0; i < GTM; i++) {
        int row = bm + ty * GTM + i;
        long cbase = (long)row * Nd + bn + tx * GTN;
        *reinterpret_cast<float4*>(C + cbase) = make_float4(acc[i][0], acc[i][1], acc[i][2], acc[i][3]);
    }
}

// ---------------- elementwise / scan / LN kernels ----------------
__device__ __forceinline__ float blockReduceSum256(float v) {
    __shared__ float sh[8];
    __syncthreads();
    int lane = threadIdx.x & 31;
    int w = threadIdx.x >> 5;
#pragma unroll
    for (int o = 16; o > 0; o >>= 1) v += __shfl_down_sync(0xffffffffu, v, o);
    if (lane == 0) sh[w] = v;
    __syncthreads();
    if (w == 0) {
        float t = (lane < 8) ? sh[lane] : 0.f;
#pragma unroll
        for (int o = 4; o > 0; o >>= 1) t += __shfl_down_sync(0xffffffffu, t, o);
        if (lane == 0) sh[0] = t;
    }
    __syncthreads();
    return sh[0];
}

// fused conversion of Dx, Dy, E + g_DEC init (single launch)
__global__ void conv_all_kernel(const float* __restrict__ Dx, const float* __restrict__ Dy,
                                const float* __restrict__ E)
{
    int blk = blockIdx.x;
    const float* src;
    __nv_bfloat16 *hi, *lo;
    int local;
    if (blk < 1024)      { src = Dx; hi = g_Dxh; lo = g_Dxl; local = blk; }
    else if (blk < 2048) { src = Dy; hi = g_Dyh; lo = g_Dyl; local = blk - 1024; }
    else                 { src = E;  hi = g_Eh;  lo = g_El;  local = blk - 2048; }
    long i = (long)local * 256 + threadIdx.x;
    float4 v = reinterpret_cast<const float4*>(src)[i];
    float vv[4] = {v.x, v.y, v.z, v.w};
    unsigned short hs[4], ls[4];
#pragma unroll
    for (int j = 0; j < 4; j++) {
        __nv_bfloat16 h = __float2bfloat16(vv[j]);
        __nv_bfloat16 l = __float2bfloat16(vv[j] - __bfloat162float(h));
        hs[j] = __bfloat16_as_ushort(h);
        ls[j] = __bfloat16_as_ushort(l);
    }
    reinterpret_cast<ushort4*>(hi)[i] = make_ushort4(hs[0], hs[1], hs[2], hs[3]);
    reinterpret_cast<ushort4*>(lo)[i] = make_ushort4(ls[0], ls[1], ls[2], ls[3]);
    if (blk == 0 && threadIdx.x == 0) {
        float d = 1.f;
        for (int t = 0; t < T_; t++) { g_DEC[t] = d; d *= DECF; }
    }
}

// gather emb[idx] -> bf16 hi/lo, and zero g_CS
__global__ void gatherconv_kernel(const float* __restrict__ emb, const int* __restrict__ idx)
{
    int m = blockIdx.x;
    int t = threadIdx.x;   // 64 threads, float4 each
    if (t == 0) g_CS[m] = 0.f;
    float4 v = *reinterpret_cast<const float4*>(emb + (long)idx[m] * D_ + t * 4);
    float vv[4] = {v.x, v.y, v.z, v.w};
    unsigned short hs[4], ls[4];
#pragma unroll
    for (int j = 0; j < 4; j++) {
        __nv_bfloat16 h = __float2bfloat16(vv[j]);
        __nv_bfloat16 l = __float2bfloat16(vv[j] - __bfloat162float(h));
        hs[j] = __bfloat16_as_ushort(h);
        ls[j] = __bfloat16_as_ushort(l);
    }
    long o4 = (long)m * (D_ / 4) + t;
    reinterpret_cast<ushort4*>(g_Vh)[o4] = make_ushort4(hs[0], hs[1], hs[2], hs[3]);
    reinterpret_cast<ushort4*>(g_Vl)[o4] = make_ushort4(ls[0], ls[1], ls[2], ls[3]);
}

__global__ void screc_kernel() {
    __shared__ float cs[B_ * T_];     // [t][b] layout, conflict-free
    for (int i = threadIdx.x; i < B_ * T_; i += 256) {
        int t = i >> 5, b = i & 31;
        cs[t * 32 + b] = g_CS[b * T_ + t];
    }
    __syncthreads();
    if (threadIdx.x < B_) {
        int b = threadIdx.x;
        float sprev = 0.f;
        for (int t = 0; t < T_; t++) {
            float sumx = __fdividef(sprev, sprev + EPSF);
            float s = DECF * sumx + cs[t * 32 + b];
            g_Cc[b * T_ + t] = __fdividef(1.f, s + EPSF);
            sprev = s;
        }
    }
}

__global__ void xrecur_kernel() {
    int b = blockIdx.y;
    int n = blockIdx.x * 256 + threadIdx.x;
    __shared__ float sc[T_];
    sc[threadIdx.x] = g_Cc[b * T_ + threadIdx.x];
    __syncthreads();
    float x = 0.f;
    long base = (long)b * T_ * N_ + n;
    for (int t = 0; t < T_; t++) {
        float p = g_X[base + (long)t * N_];
        x = (DECF * x + p) * sc[t];
        __nv_bfloat16 h = __float2bfloat16(x);
        g_Xh[base + (long)t * N_] = h;
        g_Xl[base + (long)t * N_] = __float2bfloat16(x - __bfloat162float(h));
    }
}

template <int HILO, int NPART>
__global__ void ln_rows(const float* __restrict__ in, float* __restrict__ outf,
                        __nv_bfloat16* __restrict__ oh, __nv_bfloat16* __restrict__ ol,
                        const int* __restrict__ gidx)
{
    int m = blockIdx.x;
    long r = gidx ? (long)gidx[m] : (long)m;
    float z = in[r * D_ + threadIdx.x];
#pragma unroll
    for (int p = 1; p < NPART; p++)
        z += in[(long)p * M_ * D_ + r * D_ + threadIdx.x];
    float mean = blockReduceSum256(z) * (1.f / D_);
    float d = z - mean;
    float var = blockReduceSum256(d * d) * (1.f / (D_ - 1));
    float v = d / (sqrtf(var) + EPSF);
    long o = (long)m * D_ + threadIdx.x;
    if (HILO) {
        __nv_bfloat16 h = __float2bfloat16(v);
        oh[o] = h;
        ol[o] = __float2bfloat16(v - __bfloat162float(h));
    } else {
        outf[o] = v;
    }
}

// ---------------- launch ----------------
extern "C" void kernel_launch(void* const* d_in, const int* in_sizes, int n_in,
                              void* d_out, int out_size)
{
    (void)in_sizes; (void)n_in; (void)out_size;
    const int*   idx  = (const int*)d_in[0];
    const float* temb = (const float*)d_in[1];
    const float* E    = (const float*)d_in[2];
    const float* Dx   = (const float*)d_in[3];
    const float* Dy   = (const float*)d_in[4];
    float* out = (float*)d_out;

    float *pX, *pU, *pS, *pA, *pO;
    __nv_bfloat16 *pVh, *pVl, *pDxh, *pDxl, *pDyh, *pDyl, *pEh, *pEl;
    __nv_bfloat16 *pXh, *pXl, *pAh, *pAl, *pYh, *pYl;
    cudaGetSymbolAddress((void**)&pX,  g_X);
    cudaGetSymbolAddress((void**)&pU,  g_U);
    cudaGetSymbolAddress((void**)&pS,  g_S);
    cudaGetSymbolAddress((void**)&pA,  g_A);
    cudaGetSymbolAddress((void**)&pO,  g_O);
    cudaGetSymbolAddress((void**)&pVh, g_Vh);  cudaGetSymbolAddress((void**)&pVl, g_Vl);
    cudaGetSymbolAddress((void**)&pDxh, g_Dxh); cudaGetSymbolAddress((void**)&pDxl, g_Dxl);
    cudaGetSymbolAddress((void**)&pDyh, g_Dyh); cudaGetSymbolAddress((void**)&pDyl, g_Dyl);
    cudaGetSymbolAddress((void**)&pEh, g_Eh);  cudaGetSymbolAddress((void**)&pEl, g_El);
    cudaGetSymbolAddress((void**)&pXh, g_Xh);  cudaGetSymbolAddress((void**)&pXl, g_Xl);
    cudaGetSymbolAddress((void**)&pAh, g_Ah);  cudaGetSymbolAddress((void**)&pAl, g_Al);
    cudaGetSymbolAddress((void**)&pYh, g_Yh);  cudaGetSymbolAddress((void**)&pYl, g_Yl);

    const int SM3 = 3 * 4 * TILE_B;   // 98304
    const int SM1 = 3 * 2 * TILE_B;   // 49152
    cudaFuncSetAttribute(mma_nt<EPI_RELU, 3, false>,     cudaFuncAttributeMaxDynamicSharedMemorySize, SM3);
    cudaFuncSetAttribute(mma_nt<EPI_NONE, 1, true>,      cudaFuncAttributeMaxDynamicSharedMemorySize, SM1);
    cudaFuncSetAttribute(mma_nt<EPI_RELUMULX, 3, false>, cudaFuncAttributeMaxDynamicSharedMemorySize, SM3);
    cudaFuncSetAttribute(mma_nt<EPI_NONE, 3, false>,     cudaFuncAttributeMaxDynamicSharedMemorySize, SM3);

    // launch 0: fused weight conversions (+g_DEC)
    conv_all_kernel<<<3072, 256>>>(Dx, Dy, E);
    // launch 1: embedding gather/convert (+g_CS zero)
    gatherconv_kernel<<<M_, 64>>>(temb, idx);
    // launch 2: U = LN(emb[idx])
    ln_rows<0, 1><<<M_, 256>>>(temb, pU, nullptr, nullptr, idx);

    // G1: P = relu(emb[idx] @ Dx^T) -> g_X (fp32), fused row-sum -> g_CS
    mma_nt<EPI_RELU, 3, false><<<dim3(N_ / 128, M_ / 128, 1), 256, SM3>>>(
        pVh, pVl, pDxh, pDxl, pX, nullptr, nullptr, nullptr, nullptr,
        N_, D_, D_, 0, 0, 0, 0, 1);

    // scalar L1 recurrence + parallel x scan; emits x as bf16 hi/lo directly
    screc_kernel<<<1, 256>>>();
    xrecur_kernel<<<dim3(N_ / 256, B_, 1), 256>>>();

    // scores (raw, split-K x2): S_p[b,t,s] = <x_t, x_s> over K half p
    mma_nt<EPI_NONE, 1, true><<<dim3(T_ / 128, T_ / 128, 2 * B_), 256, SM1>>>(
        pXh, pXh, pXh, pXh, pS, nullptr, nullptr, nullptr, nullptr,
        T_, N_, N_ / 2, (long)T_ * N_, (long)T_ * N_, (long)T_ * T_,
        (long)B_ * T_ * T_, B_);

    // a* = (decayed (S0+S1)) @ U  (SIMT; decay+mask fused into A load)
    gemm_nn<<<dim3(D_ / GBN, T_ / GBM, B_), 256>>>(
        pS, pS + (long)B_ * T_ * T_, pU, pA, T_, D_, T_,
        (long)T_ * T_, (long)T_ * D_, (long)T_ * D_);

    // a* <- LN(a*) -> bf16 hi/lo directly
    ln_rows<1, 1><<<M_, 256>>>(pA, nullptr, pAh, pAl, nullptr);

    // G2: y = relu(LN(a*) @ Dy^T) * x -> bf16 hi/lo directly
    mma_nt<EPI_RELUMULX, 3, false><<<dim3(N_ / 128, M_ / 128, 1), 256, SM3>>>(
        pAh, pAl, pDyh, pDyl, nullptr, pYh, pYl, pXh, pXl,
        N_, D_, D_, 0, 0, 0, 0, 1);

    // G3 (split-K x4): o_p = y @ E^T over K quarter p -> g_O partials
    mma_nt<EPI_NONE, 3, false><<<dim3(D_ / 128, M_ / 128, 4), 256, SM3>>>(
        pYh, pYl, pEh, pEl, pO, nullptr, nullptr, nullptr, nullptr,
        D_, N_, N_ / 4, 0, 0, 0, (long)M_ * D_, 1);

    // out = LN(sum of 4 partials)
    ln_rows<0, 4><<<M_, 256>>>(pO, out, nullptr, nullptr, nullptr);
}

// round 8
// speedup vs baseline: 3.1333x; 1.1603x over previous
#include <cuda_runtime.h>
#include <cuda_bf16.h>
#include <cuda_fp16.h>
#include <cstdint>

#define B_   32
#define T_   256
#define N_   4096
#define D_   256
#define M_   (B_ * T_)
#define EPSF 1e-6f
#define DECF 0.97f

// ---------------- scratch (device globals; no allocation) ----------------
__device__ float g_X [(long long)M_ * N_];      // P (fp32 scan domain)
__device__ float g_CS[M_];
__device__ float g_Cc[M_];
__device__ float g_U [M_ * D_];
__device__ float g_S [2LL * B_ * T_ * T_];      // 2 split-K partials of raw scores
__device__ float g_A [2LL * M_ * D_];           // 2 split-K partials of a*
__device__ float g_O [4LL * M_ * D_];           // 4 split-K partials of G3
__device__ float g_DEC[T_];

// bf16 hi/lo operands (G1, scores)
__device__ __nv_bfloat16 g_Vh [M_ * D_],  g_Vl [M_ * D_];     // emb[idx]
__device__ __nv_bfloat16 g_Dxh[N_ * D_],  g_Dxl[N_ * D_];
__device__ __nv_bfloat16 g_Xh [(long long)M_ * N_], g_Xl[(long long)M_ * N_];
// fp16 operands (G2, G3); Dy,E scaled x64, y scaled x1024; final LN unscales
__device__ __half g_DyH[N_ * D_], g_DyL[N_ * D_];
__device__ __half g_EH [D_ * N_], g_EL [D_ * N_];
__device__ __half g_Af [M_ * D_];                             // LN(a*) fp16
__device__ __half g_Yf [(long long)M_ * N_];                  // y fp16 (x1024)

// ---------------- PTX helpers (baseline ISA only) ----------------
__device__ __forceinline__ uint32_t smem_u32(const void* p) {
    uint32_t a;
    asm("{ .reg .u64 t; cvta.to.shared.u64 t, %1; cvt.u32.u64 %0, t; }" : "=r"(a) : "l"(p));
    return a;
}
__device__ __forceinline__ void cp16(uint32_t so, const void* g) {
    asm volatile("cp.async.cg.shared.global [%0], [%1], 16;" :: "r"(so), "l"(g));
}
__device__ __forceinline__ void cp_commit() {
    asm volatile("cp.async.commit_group;" ::: "memory");
}
template <int NN>
__device__ __forceinline__ void cp_wait() {
    asm volatile("cp.async.wait_group %0;" :: "n"(NN) : "memory");
}
__device__ __forceinline__ void ldsm_x4(uint32_t* f, uint32_t a) {
    asm volatile("ldmatrix.sync.aligned.m8n8.x4.shared.b16 {%0,%1,%2,%3}, [%4];"
        : "=r"(f[0]), "=r"(f[1]), "=r"(f[2]), "=r"(f[3]) : "r"(a));
}
template <bool FP16>
__device__ __forceinline__ void mma_any(float* c, const uint32_t* a, const uint32_t* b) {
    if constexpr (FP16) {
        asm volatile("mma.sync.aligned.m16n8k16.row.col.f32.f16.f16.f32 "
            "{%0,%1,%2,%3}, {%4,%5,%6,%7}, {%8,%9}, {%0,%1,%2,%3};"
            : "+f"(c[0]), "+f"(c[1]), "+f"(c[2]), "+f"(c[3])
            : "r"(a[0]), "r"(a[1]), "r"(a[2]), "r"(a[3]), "r"(b[0]), "r"(b[1]));
    } else {
        asm volatile("mma.sync.aligned.m16n8k16.row.col.f32.bf16.bf16.f32 "
            "{%0,%1,%2,%3}, {%4,%5,%6,%7}, {%8,%9}, {%0,%1,%2,%3};"
            : "+f"(c[0]), "+f"(c[1]), "+f"(c[2]), "+f"(c[3])
            : "r"(a[0]), "r"(a[1]), "r"(a[2]), "r"(a[3]), "r"(b[0]), "r"(b[1]));
    }
}

// ---------------- HMMA NT GEMM: C[m,n] = sum_k A[m,k]*B[n,k] ----------------
enum { EPI_NONE = 0, EPI_RELU = 1, EPI_RELUMULX = 2 };
enum { MD_SINGLE = 0, MD_SPLITB = 2, MD_FULL = 3 };   // SPLITB: A*(Bh+Bl); FULL: 3-pass hi/lo

// swizzled tile: 128 rows x 64B (32 elts); phys 16B-slot = g ^ ((r>>1)&3)
#define TILE_B 8192

template <int EPI, int MODE, bool TRISKIP, bool FP16>
__global__ void __launch_bounds__(256, 2) mma_nt(
    const __nv_bfloat16* __restrict__ Ah, const __nv_bfloat16* __restrict__ Al,
    const __nv_bfloat16* __restrict__ Bh, const __nv_bfloat16* __restrict__ Bl,
    float* __restrict__ Cf, __nv_bfloat16* __restrict__ Ch,
    const __nv_bfloat16* __restrict__ Xh, const __nv_bfloat16* __restrict__ Xl,
    int Nd, int K, int kLen, long sA, long sB, long sC, long splitStride, int batches)
{
    constexpr int NTILES  = (MODE == MD_FULL) ? 4 : (MODE == MD_SINGLE) ? 2 : 3;
    constexpr int STAGE_B = NTILES * TILE_B;

    extern __shared__ char smem[];
    const uint32_t sb = smem_u32(smem);
    const int tid  = threadIdx.x;
    const int lane = tid & 31;
    const int wid  = tid >> 5;
    const int wm   = wid >> 2;          // 0..1  -> m offset wm*64
    const int wn   = wid & 3;           // 0..3  -> n offset wn*32
    const int zz   = blockIdx.z;
    const int split = zz / batches;
    const int bz    = zz - split * batches;
    const long kOff = (long)split * kLen;
    const int bm = blockIdx.y * 128;
    const int bn = blockIdx.x * 128;
    const bool skip = TRISKIP && (bn >= bm + 128);

    float acc[4][4][4];
#pragma unroll
    for (int i = 0; i < 4; i++)
#pragma unroll
        for (int j = 0; j < 4; j++)
#pragma unroll
            for (int v = 0; v < 4; v++) acc[i][j][v] = 0.f;

    if (!skip) {
        const __nv_bfloat16* Ahp = Ah + (long)bz * sA + (long)bm * K + kOff;
        const __nv_bfloat16* Alp = Al + (long)bz * sA + (long)bm * K + kOff;
        const __nv_bfloat16* Bhp = Bh + (long)bz * sB + (long)bn * K + kOff;
        const __nv_bfloat16* Blp = Bl + (long)bz * sB + (long)bn * K + kOff;

        const int qr0 = tid >> 2;             // row (0..63)
        const int qc0 = tid & 3;              // 16B group
        auto stage_load = [&](int stg, int k0) {
            uint32_t base = sb + stg * STAGE_B;
#pragma unroll
            for (int i = 0; i < 2; i++) {
                int r = qr0 + i * 64;
                uint32_t so = (uint32_t)(r * 64 + ((qc0 ^ ((r >> 1) & 3)) * 16));
                long gofs = (long)r * K + k0 + qc0 * 8;
                cp16(base + so, Ahp + gofs);
                cp16(base + TILE_B + so, Bhp + gofs);
                if (MODE == MD_SPLITB)
                    cp16(base + 2 * TILE_B + so, Blp + gofs);
                if (MODE == MD_FULL) {
                    cp16(base + 2 * TILE_B + so, Alp + gofs);
                    cp16(base + 3 * TILE_B + so, Blp + gofs);
                }
            }
            cp_commit();
        };

        const int nC = kLen / 32;
        stage_load(0, 0);
        stage_load(1, 32);

        // per-lane ldsm logical positions
        const uint32_t aRow  = (uint32_t)(wm * 64 + (lane & 15));
        const uint32_t aColG = (uint32_t)(lane >> 4);
        const uint32_t bRow  = (uint32_t)(wn * 32 + ((lane >> 4) << 3) + (lane & 7));
        const uint32_t bColG = (uint32_t)((lane >> 3) & 1);
        const uint32_t sa = (aRow >> 1) & 3;
        const uint32_t sbw = (bRow >> 1) & 3;
        uint32_t aoff[2], boff[2];
#pragma unroll
        for (int ks = 0; ks < 2; ks++) {
            aoff[ks] = aRow * 64 + (((ks * 2 + aColG) ^ sa) * 16);
            boff[ks] = bRow * 64 + (((ks * 2 + bColG) ^ sbw) * 16);
        }

        int stg = 0;
        for (int c = 0; c < nC; c++) {
            cp_wait<1>();
            __syncthreads();
            if (c + 2 < nC) {
                int ns = stg + 2; if (ns >= 3) ns -= 3;
                stage_load(ns, (c + 2) * 32);
            } else {
                cp_commit();   // empty group keeps wait<1> accounting uniform
            }

            const uint32_t st = sb + stg * STAGE_B;
#pragma unroll
            for (int ks = 0; ks < 2; ks++) {
                uint32_t fA[4][4], fB[2][4], fB2[2][4];
                // pass 1: A . Bh
#pragma unroll
                for (int ma = 0; ma < 4; ma++)
                    ldsm_x4(fA[ma], st + aoff[ks] + ma * 1024);
#pragma unroll
                for (int p = 0; p < 2; p++)
                    ldsm_x4(fB[p], st + TILE_B + boff[ks] + p * 1024);
#pragma unroll
                for (int ma = 0; ma < 4; ma++)
#pragma unroll
                    for (int na = 0; na < 4; na++)
                        mma_any<FP16>(acc[ma][na], fA[ma], &fB[na >> 1][2 * (na & 1)]);
                if (MODE == MD_SPLITB || MODE == MD_FULL) {
                    // pass 2: A . Bl (A stays live)
                    const uint32_t blt = (MODE == MD_FULL) ? 3 * TILE_B : 2 * TILE_B;
#pragma unroll
                    for (int p = 0; p < 2; p++)
                        ldsm_x4(fB2[p], st + blt + boff[ks] + p * 1024);
#pragma unroll
                    for (int ma = 0; ma < 4; ma++)
#pragma unroll
                        for (int na = 0; na < 4; na++)
                            mma_any<FP16>(acc[ma][na], fA[ma], &fB2[na >> 1][2 * (na & 1)]);
                }
                if (MODE == MD_FULL) {
                    // pass 3: Al . Bh (overwrite fA; Bh still live)
#pragma unroll
                    for (int ma = 0; ma < 4; ma++)
                        ldsm_x4(fA[ma], st + 2 * TILE_B + aoff[ks] + ma * 1024);
#pragma unroll
                    for (int ma = 0; ma < 4; ma++)
#pragma unroll
                        for (int na = 0; na < 4; na++)
                            mma_any<FP16>(acc[ma][na], fA[ma], &fB[na >> 1][2 * (na & 1)]);
                }
            }
            stg = (stg == 2) ? 0 : stg + 1;
        }
    }

    // ---- epilogue ----
    float* Cfo = (EPI != EPI_RELUMULX) ? (Cf + split * splitStride + (long)bz * sC) : nullptr;
    unsigned short* Yo = (EPI == EPI_RELUMULX) ? reinterpret_cast<unsigned short*>(Ch) : nullptr;
    const int gr = lane >> 2;          // 0..7
    const int gc = (lane & 3) * 2;
#pragma unroll
    for (int ma = 0; ma < 4; ma++) {
#pragma unroll
        for (int half = 0; half < 2; half++) {
            const int row = bm + wm * 64 + ma * 16 + gr + half * 8;
            float rs = 0.f;
#pragma unroll
            for (int na = 0; na < 4; na++) {
                const int col = bn + wn * 32 + na * 8 + gc;
                float v0 = acc[ma][na][half * 2 + 0];
                float v1 = acc[ma][na][half * 2 + 1];
                long off = (long)row * Nd + col;
                if (EPI == EPI_RELUMULX) {
                    // y = relu(g_acc) * x * 16  (g_acc = 64*g; stored y = 1024*y_true)
                    ushort2 xh = *reinterpret_cast<const ushort2*>(Xh + off);
                    ushort2 xl = *reinterpret_cast<const ushort2*>(Xl + off);
                    float x0 = __bfloat162float(__ushort_as_bfloat16(xh.x)) +
                               __bfloat162float(__ushort_as_bfloat16(xl.x));
                    float x1 = __bfloat162float(__ushort_as_bfloat16(xh.y)) +
                               __bfloat162float(__ushort_as_bfloat16(xl.y));
                    v0 = fmaxf(v0, 0.f) * x0 * 16.f;
                    v1 = fmaxf(v1, 0.f) * x1 * 16.f;
                    ushort2 o = make_ushort2(__half_as_ushort(__float2half_rn(v0)),
                                             __half_as_ushort(__float2half_rn(v1)));
                    *reinterpret_cast<ushort2*>(Yo + off) = o;
                } else {
                    if (EPI == EPI_RELU) {
                        v0 = fmaxf(v0, 0.f); v1 = fmaxf(v1, 0.f);
                        rs += v0 + v1;
                    }
                    *reinterpret_cast<float2*>(Cfo + off) = make_float2(v0, v1);
                }
            }
            if (EPI == EPI_RELU) {   // fused partial row-sum for L1 norm
                rs += __shfl_xor_sync(0xffffffffu, rs, 1);
                rs += __shfl_xor_sync(0xffffffffu, rs, 2);
                if ((lane & 3) == 0) atomicAdd(&g_CS[row], rs);
            }
        }
    }
}

// ---------------- SIMT NN GEMM: a* = (decayed S) @ U, split-K x2 ----------------
#define GBM 128
#define GBN 64
#define GBK 16
#define GTM 8
#define GTN 4

__global__ __launch_bounds__(256)
void gemm_nn(const float* __restrict__ A0, const float* __restrict__ A1,
             const float* __restrict__ B, float* __restrict__ C)
{
    const int zz = blockIdx.z;
    const int bz = zz & 31;          // batch
    const int split = zz >> 5;       // 0..1
    A0 += (long)bz * T_ * T_;
    A1 += (long)bz * T_ * T_;
    B  += (long)bz * T_ * D_;
    C  += (long)split * M_ * D_ + (long)bz * T_ * D_;
    const int bm = blockIdx.y * GBM;
    const int bn = blockIdx.x * GBN;

    __shared__ __align__(16) float As[GBK][GBM + 4];
    __shared__ __align__(16) float Bs[GBK][GBN + 4];

    const int tid = threadIdx.x;
    const int tx = tid & 15;
    const int ty = tid >> 4;

    float acc[GTM][GTN];
#pragma unroll
    for (int i = 0; i < GTM; i++)
#pragma unroll
        for (int j = 0; j < GTN; j++) acc[i][j] = 0.f;

    const int lr = tid >> 2;
    const int lk = (tid & 3) * 4;
    const int brow = tid >> 4;
    const int bcol = (tid & 15) * 4;

    const int kBeg = split * (T_ / 2);
    for (int k0 = kBeg; k0 < kBeg + T_ / 2; k0 += GBK) {
#pragma unroll
        for (int i = 0; i < 2; i++) {
            int r = lr + i * 64;
            int t = bm + r;
            long ao = (long)t * T_ + k0 + lk;
            float4 v = *reinterpret_cast<const float4*>(A0 + ao);
            float4 w = *reinterpret_cast<const float4*>(A1 + ao);
            float vv[4] = {v.x + w.x, v.y + w.y, v.z + w.z, v.w + w.w};
#pragma unroll
            for (int j = 0; j < 4; j++) {
                int L = t - (k0 + lk + j);
                As[lk + j][r] = (L > 0) ? vv[j] * g_DEC[L] : 0.f;
            }
        }
        {
            float4 v = *reinterpret_cast<const float4*>(B + (long)(k0 + brow) * D_ + bn + bcol);
            Bs[brow][bcol + 0] = v.x; Bs[brow][bcol + 1] = v.y;
            Bs[brow][bcol + 2] = v.z; Bs[brow][bcol + 3] = v.w;
        }
        __syncthreads();
#pragma unroll
        for (int kk = 0; kk < GBK; kk++) {
            float af[GTM], bf[GTN];
#pragma unroll
            for (int i = 0; i < GTM; i++) af[i] = As[kk][ty * GTM + i];
#pragma unroll
            for (int j = 0; j < GTN; j++) bf[j] = Bs[kk][tx * GTN + j];
#pragma unroll
            for (int i = 0; i < GTM; i++)
#pragma unroll
                for (int j = 0; j < GTN; j++)
                    acc[i][j] = fmaf(af[i], bf[j], acc[i][j]);
        }
        __syncthreads();
    }
#pragma unroll
    for (int i = 0; i < GTM; i++) {
        int row = bm + ty * GTM + i;
        long cbase = (long)row * D_ + bn + tx * GTN;
        *reinterpret_cast<float4*>(C + cbase) = make_float4(acc[i][0], acc[i][1], acc[i][2], acc[i][3]);
    }
}

// ---------------- elementwise / scan / LN kernels ----------------
__device__ __forceinline__ float blockReduceSum256(float v) {
    __shared__ float sh[8];
    __syncthreads();
    int lane = threadIdx.x & 31;
    int w = threadIdx.x >> 5;
#pragma unroll
    for (int o = 16; o > 0; o >>= 1) v += __shfl_down_sync(0xffffffffu, v, o);
    if (lane == 0) sh[w] = v;
    __syncthreads();
    if (w == 0) {
        float t = (lane < 8) ? sh[lane] : 0.f;
#pragma unroll
        for (int o = 4; o > 0; o >>= 1) t += __shfl_down_sync(0xffffffffu, t, o);
        if (lane == 0) sh[0] = t;
    }
    __syncthreads();
    return sh[0];
}

// fused conversions: Dx -> bf16 hi/lo; Dy,E -> fp16 hi/lo (x64); + g_DEC init
__global__ void conv_all_kernel(const float* __restrict__ Dx, const float* __restrict__ Dy,
                                const float* __restrict__ E)
{
    int blk = blockIdx.x;
    if (blk < 1024) {
        long i = (long)blk * 256 + threadIdx.x;
        float4 v = reinterpret_cast<const float4*>(Dx)[i];
        float vv[4] = {v.x, v.y, v.z, v.w};
        unsigned short hs[4], ls[4];
#pragma unroll
        for (int j = 0; j < 4; j++) {
            __nv_bfloat16 h = __float2bfloat16(vv[j]);
            __nv_bfloat16 l = __float2bfloat16(vv[j] - __bfloat162float(h));
            hs[j] = __bfloat16_as_ushort(h);
            ls[j] = __bfloat16_as_ushort(l);
        }
        reinterpret_cast<ushort4*>(g_Dxh)[i] = make_ushort4(hs[0], hs[1], hs[2], hs[3]);
        reinterpret_cast<ushort4*>(g_Dxl)[i] = make_ushort4(ls[0], ls[1], ls[2], ls[3]);
    } else {
        const float* src = (blk < 2048) ? Dy : E;
        __half* hi = (blk < 2048) ? g_DyH : g_EH;
        __half* lo = (blk < 2048) ? g_DyL : g_EL;
        long i = (long)((blk < 2048) ? blk - 1024 : blk - 2048) * 256 + threadIdx.x;
        float4 v = reinterpret_cast<const float4*>(src)[i];
        float vv[4] = {v.x * 64.f, v.y * 64.f, v.z * 64.f, v.w * 64.f};
        unsigned short hs[4], ls[4];
#pragma unroll
        for (int j = 0; j < 4; j++) {
            __half h = __float2half_rn(vv[j]);
            __half l = __float2half_rn(vv[j] - __half2float(h));
            hs[j] = __half_as_ushort(h);
            ls[j] = __half_as_ushort(l);
        }
        reinterpret_cast<ushort4*>(hi)[i] = make_ushort4(hs[0], hs[1], hs[2], hs[3]);
        reinterpret_cast<ushort4*>(lo)[i] = make_ushort4(ls[0], ls[1], ls[2], ls[3]);
    }
    if (blk == 0 && threadIdx.x == 0) {
        float d = 1.f;
        for (int t = 0; t < T_; t++) { g_DEC[t] = d; d *= DECF; }
    }
}

// gather emb[idx] -> bf16 hi/lo, and zero g_CS
__global__ void gatherconv_kernel(const float* __restrict__ emb, const int* __restrict__ idx)
{
    int m = blockIdx.x;
    int t = threadIdx.x;   // 64 threads, float4 each
    if (t == 0) g_CS[m] = 0.f;
    float4 v = *reinterpret_cast<const float4*>(emb + (long)idx[m] * D_ + t * 4);
    float vv[4] = {v.x, v.y, v.z, v.w};
    unsigned short hs[4], ls[4];
#pragma unroll
    for (int j = 0; j < 4; j++) {
        __nv_bfloat16 h = __float2bfloat16(vv[j]);
        __nv_bfloat16 l = __float2bfloat16(vv[j] - __bfloat162float(h));
        hs[j] = __bfloat16_as_ushort(h);
        ls[j] = __bfloat16_as_ushort(l);
    }
    long o4 = (long)m * (D_ / 4) + t;
    reinterpret_cast<ushort4*>(g_Vh)[o4] = make_ushort4(hs[0], hs[1], hs[2], hs[3]);
    reinterpret_cast<ushort4*>(g_Vl)[o4] = make_ushort4(ls[0], ls[1], ls[2], ls[3]);
}

__global__ void screc_kernel() {
    __shared__ float cs[B_ * T_];     // [t][b] layout, conflict-free
    for (int i = threadIdx.x; i < B_ * T_; i += 256) {
        int t = i >> 5, b = i & 31;
        cs[t * 32 + b] = g_CS[b * T_ + t];
    }
    __syncthreads();
    if (threadIdx.x < B_) {
        int b = threadIdx.x;
        float sprev = 0.f;
        for (int t = 0; t < T_; t++) {
            float sumx = __fdividef(sprev, sprev + EPSF);
            float s = DECF * sumx + cs[t * 32 + b];
            g_Cc[b * T_ + t] = __fdividef(1.f, s + EPSF);
            sprev = s;
        }
    }
}

__global__ void xrecur_kernel() {
    int b = blockIdx.y;
    int n = blockIdx.x * 256 + threadIdx.x;
    __shared__ float sc[T_];
    sc[threadIdx.x] = g_Cc[b * T_ + threadIdx.x];
    __syncthreads();
    float x = 0.f;
    long base = (long)b * T_ * N_ + n;
    for (int t = 0; t < T_; t++) {
        float p = g_X[base + (long)t * N_];
        x = (DECF * x + p) * sc[t];
        __nv_bfloat16 h = __float2bfloat16(x);
        g_Xh[base + (long)t * N_] = h;
        g_Xl[base + (long)t * N_] = __float2bfloat16(x - __bfloat162float(h));
    }
}

// OUT: 0 = fp32, 1 = fp16 single
template <int OUT, int NPART>
__global__ void ln_rows(const float* __restrict__ in, float* __restrict__ outf,
                        unsigned short* __restrict__ oh,
                        const int* __restrict__ gidx, float inscale)
{
    int m = blockIdx.x;
    long r = gidx ? (long)gidx[m] : (long)m;
    float z = in[r * D_ + threadIdx.x];
#pragma unroll
    for (int p = 1; p < NPART; p++)
        z += in[(long)p * M_ * D_ + r * D_ + threadIdx.x];
    z *= inscale;
    float mean = blockReduceSum256(z) * (1.f / D_);
    float d = z - mean;
    float var = blockReduceSum256(d * d) * (1.f / (D_ - 1));
    float v = d / (sqrtf(var) + EPSF);
    long o = (long)m * D_ + threadIdx.x;
    if (OUT == 1) {
        oh[o] = __half_as_ushort(__float2half_rn(v));
    } else {
        outf[o] = v;
    }
}

// ---------------- launch ----------------
extern "C" void kernel_launch(void* const* d_in, const int* in_sizes, int n_in,
                              void* d_out, int out_size)
{
    (void)in_sizes; (void)n_in; (void)out_size;
    const int*   idx  = (const int*)d_in[0];
    const float* temb = (const float*)d_in[1];
    const float* E    = (const float*)d_in[2];
    const float* Dx   = (const float*)d_in[3];
    const float* Dy   = (const float*)d_in[4];
    float* out = (float*)d_out;

    float *pX, *pU, *pS, *pA, *pO;
    __nv_bfloat16 *pVh, *pVl, *pDxh, *pDxl, *pXh, *pXl;
    __half *pDyH, *pDyL, *pEH, *pEL, *pAf, *pYf;
    cudaGetSymbolAddress((void**)&pX,  g_X);
    cudaGetSymbolAddress((void**)&pU,  g_U);
    cudaGetSymbolAddress((void**)&pS,  g_S);
    cudaGetSymbolAddress((void**)&pA,  g_A);
    cudaGetSymbolAddress((void**)&pO,  g_O);
    cudaGetSymbolAddress((void**)&pVh, g_Vh);  cudaGetSymbolAddress((void**)&pVl, g_Vl);
    cudaGetSymbolAddress((void**)&pDxh, g_Dxh); cudaGetSymbolAddress((void**)&pDxl, g_Dxl);
    cudaGetSymbolAddress((void**)&pXh, g_Xh);  cudaGetSymbolAddress((void**)&pXl, g_Xl);
    cudaGetSymbolAddress((void**)&pDyH, g_DyH); cudaGetSymbolAddress((void**)&pDyL, g_DyL);
    cudaGetSymbolAddress((void**)&pEH, g_EH);  cudaGetSymbolAddress((void**)&pEL, g_EL);
    cudaGetSymbolAddress((void**)&pAf, g_Af);  cudaGetSymbolAddress((void**)&pYf, g_Yf);

    const int SM3 = 3 * 4 * TILE_B;   // 98304
    const int SM2 = 3 * 3 * TILE_B;   // 73728
    const int SM1 = 3 * 2 * TILE_B;   // 49152
    cudaFuncSetAttribute(mma_nt<EPI_RELU, MD_FULL, false, false>,
                         cudaFuncAttributeMaxDynamicSharedMemorySize, SM3);
    cudaFuncSetAttribute(mma_nt<EPI_NONE, MD_SINGLE, true, false>,
                         cudaFuncAttributeMaxDynamicSharedMemorySize, SM1);
    cudaFuncSetAttribute(mma_nt<EPI_RELUMULX, MD_SPLITB, false, true>,
                         cudaFuncAttributeMaxDynamicSharedMemorySize, SM2);
    cudaFuncSetAttribute(mma_nt<EPI_NONE, MD_SPLITB, false, true>,
                         cudaFuncAttributeMaxDynamicSharedMemorySize, SM2);

    // fused conversions (+g_DEC)
    conv_all_kernel<<<3072, 256>>>(Dx, Dy, E);
    // embedding gather/convert (+g_CS zero)
    gatherconv_kernel<<<M_, 64>>>(temb, idx);
    // U = LN(emb[idx])
    ln_rows<0, 1><<<M_, 256>>>(temb, pU, nullptr, idx, 1.f);

    // G1: P = relu(emb[idx] @ Dx^T) -> g_X (fp32), fused row-sum -> g_CS (bf16 3-pass)
    mma_nt<EPI_RELU, MD_FULL, false, false><<<dim3(N_ / 128, M_ / 128, 1), 256, SM3>>>(
        pVh, pVl, pDxh, pDxl, pX, nullptr, nullptr, nullptr,
        N_, D_, D_, 0, 0, 0, 0, 1);

    // scalar L1 recurrence + parallel x scan; emits x as bf16 hi/lo
    screc_kernel<<<1, 256>>>();
    xrecur_kernel<<<dim3(N_ / 256, B_, 1), 256>>>();

    // scores (raw, split-K x2, single-pass bf16; positive sums)
    mma_nt<EPI_NONE, MD_SINGLE, true, false><<<dim3(T_ / 128, T_ / 128, 2 * B_), 256, SM1>>>(
        pXh, nullptr, pXh, nullptr, pS, nullptr, nullptr, nullptr,
        T_, N_, N_ / 2, (long)T_ * N_, (long)T_ * N_, (long)T_ * T_,
        (long)B_ * T_ * T_, B_);

    // a* = (decayed (S0+S1)) @ U  (SIMT fp32, split-K x2; decay+mask fused into A load)
    gemm_nn<<<dim3(D_ / GBN, T_ / GBM, 2 * B_), 256>>>(
        pS, pS + (long)B_ * T_ * T_, pU, pA);

    // a* <- LN(sum of 2 partials) -> fp16 single
    ln_rows<1, 2><<<M_, 256>>>(pA, nullptr, (unsigned short*)pAf, nullptr, 1.f);

    // G2: y = relu(LN(a*) @ (64*Dy)^T) * x * 16 -> fp16 (stored y = 1024*y_true)
    mma_nt<EPI_RELUMULX, MD_SPLITB, false, true><<<dim3(N_ / 128, M_ / 128, 1), 256, SM2>>>(
        (const __nv_bfloat16*)pAf, nullptr,
        (const __nv_bfloat16*)pDyH, (const __nv_bfloat16*)pDyL,
        nullptr, (__nv_bfloat16*)pYf, pXh, pXl,
        N_, D_, D_, 0, 0, 0, 0, 1);

    // G3 (split-K x4, fp16 2-pass): o_p = (1024*y) @ (64*E)^T -> g_O partials (65536*o)
    mma_nt<EPI_NONE, MD_SPLITB, false, true><<<dim3(D_ / 128, M_ / 128, 4), 256, SM2>>>(
        (const __nv_bfloat16*)pYf, nullptr,
        (const __nv_bfloat16*)pEH, (const __nv_bfloat16*)pEL,
        pO, nullptr, nullptr, nullptr,
        D_, N_, N_ / 4, 0, 0, 0, (long)M_ * D_, 1);

    // out = LN((sum of 4 partials) / 65536)
    ln_rows<0, 4><<<M_, 256>>>(pO, out, nullptr, nullptr, 1.f / 65536.f);
}

// round 9
// speedup vs baseline: 3.2987x; 1.0528x over previous
#include <cuda_runtime.h>
#include <cuda_bf16.h>
#include <cuda_fp16.h>
#include <cstdint>

#define B_   32
#define T_   256
#define N_   4096
#define D_   256
#define M_   (B_ * T_)
#define EPSF 1e-6f
#define DECF 0.97f

// ---------------- scratch (device globals; no allocation) ----------------
__device__ float g_X [(long long)M_ * N_];      // 256*P (fp32 scan domain)
__device__ float g_CS[M_];
__device__ float g_Cc[M_];
__device__ float g_U [M_ * D_];
__device__ float g_S [2LL * B_ * T_ * T_];      // 2 split-K partials of raw scores
__device__ float g_A [2LL * M_ * D_];           // 2 split-K partials of a*
__device__ float g_O [2LL * M_ * D_];           // 2 split-K partials of G3
__device__ float g_DEC[T_];

// bf16 hi/lo operands (scores)
__device__ __nv_bfloat16 g_Xh [(long long)M_ * N_], g_Xl[(long long)M_ * N_];
// fp16 operands; scalings: v,Dx x16; Dy,E x64; y x1024 — unscaled exactly later
__device__ __half g_Vf [M_ * D_];                             // 16*emb[idx]
__device__ __half g_DxH[N_ * D_], g_DxL[N_ * D_];             // 16*Dx hi/lo
__device__ __half g_DyH[N_ * D_], g_DyL[N_ * D_];             // 64*Dy hi/lo
__device__ __half g_EH [D_ * N_], g_EL [D_ * N_];             // 64*E hi/lo
__device__ __half g_Af [M_ * D_];                             // LN(a*) fp16
__device__ __half g_Yf [(long long)M_ * N_];                  // 1024*y fp16

// ---------------- PTX helpers (baseline ISA only) ----------------
__device__ __forceinline__ uint32_t smem_u32(const void* p) {
    uint32_t a;
    asm("{ .reg .u64 t; cvta.to.shared.u64 t, %1; cvt.u32.u64 %0, t; }" : "=r"(a) : "l"(p));
    return a;
}
__device__ __forceinline__ void cp16(uint32_t so, const void* g) {
    asm volatile("cp.async.cg.shared.global [%0], [%1], 16;" :: "r"(so), "l"(g));
}
__device__ __forceinline__ void cp_commit() {
    asm volatile("cp.async.commit_group;" ::: "memory");
}
template <int NN>
__device__ __forceinline__ void cp_wait() {
    asm volatile("cp.async.wait_group %0;" :: "n"(NN) : "memory");
}
__device__ __forceinline__ void ldsm_x4(uint32_t* f, uint32_t a) {
    asm volatile("ldmatrix.sync.aligned.m8n8.x4.shared.b16 {%0,%1,%2,%3}, [%4];"
        : "=r"(f[0]), "=r"(f[1]), "=r"(f[2]), "=r"(f[3]) : "r"(a));
}
template <bool FP16>
__device__ __forceinline__ void mma_any(float* c, const uint32_t* a, const uint32_t* b) {
    if constexpr (FP16) {
        asm volatile("mma.sync.aligned.m16n8k16.row.col.f32.f16.f16.f32 "
            "{%0,%1,%2,%3}, {%4,%5,%6,%7}, {%8,%9}, {%0,%1,%2,%3};"
            : "+f"(c[0]), "+f"(c[1]), "+f"(c[2]), "+f"(c[3])
            : "r"(a[0]), "r"(a[1]), "r"(a[2]), "r"(a[3]), "r"(b[0]), "r"(b[1]));
    } else {
        asm volatile("mma.sync.aligned.m16n8k16.row.col.f32.bf16.bf16.f32 "
            "{%0,%1,%2,%3}, {%4,%5,%6,%7}, {%8,%9}, {%0,%1,%2,%3};"
            : "+f"(c[0]), "+f"(c[1]), "+f"(c[2]), "+f"(c[3])
            : "r"(a[0]), "r"(a[1]), "r"(a[2]), "r"(a[3]), "r"(b[0]), "r"(b[1]));
    }
}

// ---------------- HMMA NT GEMM: C[m,n] = sum_k A[m,k]*B[n,k] ----------------
enum { EPI_NONE = 0, EPI_RELU = 1, EPI_RELUMULX = 2 };
enum { MD_SINGLE = 0, MD_SPLITB = 2 };   // SPLITB: A*(Bh+Bl) 2-pass

// swizzled tile: 128 rows x 64B (32 elts); phys 16B-slot = g ^ ((r>>1)&3)
#define TILE_B 8192

template <int EPI, int MODE, bool TRISKIP, bool FP16>
__global__ void __launch_bounds__(256, 2) mma_nt(
    const __nv_bfloat16* __restrict__ Ah,
    const __nv_bfloat16* __restrict__ Bh, const __nv_bfloat16* __restrict__ Bl,
    float* __restrict__ Cf, __nv_bfloat16* __restrict__ Ch,
    const __nv_bfloat16* __restrict__ Xh, const __nv_bfloat16* __restrict__ Xl,
    int Nd, int K, int kLen, long sA, long sB, long sC, long splitStride, int batches)
{
    constexpr int NTILES  = (MODE == MD_SINGLE) ? 2 : 3;
    constexpr int STAGE_B = NTILES * TILE_B;

    extern __shared__ char smem[];
    const uint32_t sb = smem_u32(smem);
    const int tid  = threadIdx.x;
    const int lane = tid & 31;
    const int wid  = tid >> 5;
    const int wm   = wid >> 2;          // 0..1  -> m offset wm*64
    const int wn   = wid & 3;           // 0..3  -> n offset wn*32
    const int zz   = blockIdx.z;
    const int split = zz / batches;
    const int bz    = zz - split * batches;
    const long kOff = (long)split * kLen;
    const int bm = blockIdx.y * 128;
    const int bn = blockIdx.x * 128;
    const bool skip = TRISKIP && (bn >= bm + 128);

    float acc[4][4][4];
#pragma unroll
    for (int i = 0; i < 4; i++)
#pragma unroll
        for (int j = 0; j < 4; j++)
#pragma unroll
            for (int v = 0; v < 4; v++) acc[i][j][v] = 0.f;

    if (!skip) {
        const __nv_bfloat16* Ahp = Ah + (long)bz * sA + (long)bm * K + kOff;
        const __nv_bfloat16* Bhp = Bh + (long)bz * sB + (long)bn * K + kOff;
        const __nv_bfloat16* Blp = Bl + (long)bz * sB + (long)bn * K + kOff;

        const int qr0 = tid >> 2;             // row (0..63)
        const int qc0 = tid & 3;              // 16B group
        auto stage_load = [&](int stg, int k0) {
            uint32_t base = sb + stg * STAGE_B;
#pragma unroll
            for (int i = 0; i < 2; i++) {
                int r = qr0 + i * 64;
                uint32_t so = (uint32_t)(r * 64 + ((qc0 ^ ((r >> 1) & 3)) * 16));
                long gofs = (long)r * K + k0 + qc0 * 8;
                cp16(base + so, Ahp + gofs);
                cp16(base + TILE_B + so, Bhp + gofs);
                if (MODE == MD_SPLITB)
                    cp16(base + 2 * TILE_B + so, Blp + gofs);
            }
            cp_commit();
        };

        const int nC = kLen / 32;
        stage_load(0, 0);
        stage_load(1, 32);

        // per-lane ldsm logical positions
        const uint32_t aRow  = (uint32_t)(wm * 64 + (lane & 15));
        const uint32_t aColG = (uint32_t)(lane >> 4);
        const uint32_t bRow  = (uint32_t)(wn * 32 + ((lane >> 4) << 3) + (lane & 7));
        const uint32_t bColG = (uint32_t)((lane >> 3) & 1);
        const uint32_t sa = (aRow >> 1) & 3;
        const uint32_t sbw = (bRow >> 1) & 3;
        uint32_t aoff[2], boff[2];
#pragma unroll
        for (int ks = 0; ks < 2; ks++) {
            aoff[ks] = aRow * 64 + (((ks * 2 + aColG) ^ sa) * 16);
            boff[ks] = bRow * 64 + (((ks * 2 + bColG) ^ sbw) * 16);
        }

        int stg = 0;
        for (int c = 0; c < nC; c++) {
            cp_wait<1>();
            __syncthreads();
            if (c + 2 < nC) {
                int ns = stg + 2; if (ns >= 3) ns -= 3;
                stage_load(ns, (c + 2) * 32);
            } else {
                cp_commit();   // empty group keeps wait<1> accounting uniform
            }

            const uint32_t st = sb + stg * STAGE_B;
#pragma unroll
            for (int ks = 0; ks < 2; ks++) {
                uint32_t fA[4][4], fB[2][4], fB2[2][4];
                // pass 1: A . Bh
#pragma unroll
                for (int ma = 0; ma < 4; ma++)
                    ldsm_x4(fA[ma], st + aoff[ks] + ma * 1024);
#pragma unroll
                for (int p = 0; p < 2; p++)
                    ldsm_x4(fB[p], st + TILE_B + boff[ks] + p * 1024);
#pragma unroll
                for (int ma = 0; ma < 4; ma++)
#pragma unroll
                    for (int na = 0; na < 4; na++)
                        mma_any<FP16>(acc[ma][na], fA[ma], &fB[na >> 1][2 * (na & 1)]);
                if (MODE == MD_SPLITB) {
                    // pass 2: A . Bl (A stays live)
#pragma unroll
                    for (int p = 0; p < 2; p++)
                        ldsm_x4(fB2[p], st + 2 * TILE_B + boff[ks] + p * 1024);
#pragma unroll
                    for (int ma = 0; ma < 4; ma++)
#pragma unroll
                        for (int na = 0; na < 4; na++)
                            mma_any<FP16>(acc[ma][na], fA[ma], &fB2[na >> 1][2 * (na & 1)]);
                }
            }
            stg = (stg == 2) ? 0 : stg + 1;
        }
    }

    // ---- epilogue ----
    float* Cfo = (EPI != EPI_RELUMULX) ? (Cf + split * splitStride + (long)bz * sC) : nullptr;
    unsigned short* Yo = (EPI == EPI_RELUMULX) ? reinterpret_cast<unsigned short*>(Ch) : nullptr;
    const int gr = lane >> 2;          // 0..7
    const int gc = (lane & 3) * 2;
#pragma unroll
    for (int ma = 0; ma < 4; ma++) {
#pragma unroll
        for (int half = 0; half < 2; half++) {
            const int row = bm + wm * 64 + ma * 16 + gr + half * 8;
            float rs = 0.f;
#pragma unroll
            for (int na = 0; na < 4; na++) {
                const int col = bn + wn * 32 + na * 8 + gc;
                float v0 = acc[ma][na][half * 2 + 0];
                float v1 = acc[ma][na][half * 2 + 1];
                long off = (long)row * Nd + col;
                if (EPI == EPI_RELUMULX) {
                    // y = relu(64g) * x * 16  (stored y = 1024*y_true)
                    ushort2 xh = *reinterpret_cast<const ushort2*>(Xh + off);
                    ushort2 xl = *reinterpret_cast<const ushort2*>(Xl + off);
                    float x0 = __bfloat162float(__ushort_as_bfloat16(xh.x)) +
                               __bfloat162float(__ushort_as_bfloat16(xl.x));
                    float x1 = __bfloat162float(__ushort_as_bfloat16(xh.y)) +
                               __bfloat162float(__ushort_as_bfloat16(xl.y));
                    v0 = fmaxf(v0, 0.f) * x0 * 16.f;
                    v1 = fmaxf(v1, 0.f) * x1 * 16.f;
                    ushort2 o = make_ushort2(__half_as_ushort(__float2half_rn(v0)),
                                             __half_as_ushort(__float2half_rn(v1)));
                    *reinterpret_cast<ushort2*>(Yo + off) = o;
                } else {
                    if (EPI == EPI_RELU) {
                        v0 = fmaxf(v0, 0.f); v1 = fmaxf(v1, 0.f);
                        rs += v0 + v1;
                    }
                    *reinterpret_cast<float2*>(Cfo + off) = make_float2(v0, v1);
                }
            }
            if (EPI == EPI_RELU) {   // fused partial row-sum for L1 norm
                rs += __shfl_xor_sync(0xffffffffu, rs, 1);
                rs += __shfl_xor_sync(0xffffffffu, rs, 2);
                if ((lane & 3) == 0) atomicAdd(&g_CS[row], rs);
            }
        }
    }
}

// ---------------- SIMT NN GEMM: a* = (decayed S) @ U, split-K x2 ----------------
#define GBM 128
#define GBN 64
#define GBK 16
#define GTM 8
#define GTN 4

__global__ __launch_bounds__(256)
void gemm_nn(const float* __restrict__ A0, const float* __restrict__ A1,
             const float* __restrict__ B, float* __restrict__ C)
{
    const int zz = blockIdx.z;
    const int bz = zz & 31;          // batch
    const int split = zz >> 5;       // 0..1
    A0 += (long)bz * T_ * T_;
    A1 += (long)bz * T_ * T_;
    B  += (long)bz * T_ * D_;
    C  += (long)split * M_ * D_ + (long)bz * T_ * D_;
    const int bm = blockIdx.y * GBM;
    const int bn = blockIdx.x * GBN;

    __shared__ __align__(16) float As[GBK][GBM + 4];
    __shared__ __align__(16) float Bs[GBK][GBN + 4];

    const int tid = threadIdx.x;
    const int tx = tid & 15;
    const int ty = tid >> 4;

    float acc[GTM][GTN];
#pragma unroll
    for (int i = 0; i < GTM; i++)
#pragma unroll
        for (int j = 0; j < GTN; j++) acc[i][j] = 0.f;

    const int lr = tid >> 2;
    const int lk = (tid & 3) * 4;
    const int brow = tid >> 4;
    const int bcol = (tid & 15) * 4;

    const int kBeg = split * (T_ / 2);
    for (int k0 = kBeg; k0 < kBeg + T_ / 2; k0 += GBK) {
#pragma unroll
        for (int i = 0; i < 2; i++) {
            int r = lr + i * 64;
            int t = bm + r;
            long ao = (long)t * T_ + k0 + lk;
            float4 v = *reinterpret_cast<const float4*>(A0 + ao);
            float4 w = *reinterpret_cast<const float4*>(A1 + ao);
            float vv[4] = {v.x + w.x, v.y + w.y, v.z + w.z, v.w + w.w};
#pragma unroll
            for (int j = 0; j < 4; j++) {
                int L = t - (k0 + lk + j);
                As[lk + j][r] = (L > 0) ? vv[j] * g_DEC[L] : 0.f;
            }
        }
        {
            float4 v = *reinterpret_cast<const float4*>(B + (long)(k0 + brow) * D_ + bn + bcol);
            Bs[brow][bcol + 0] = v.x; Bs[brow][bcol + 1] = v.y;
            Bs[brow][bcol + 2] = v.z; Bs[brow][bcol + 3] = v.w;
        }
        __syncthreads();
#pragma unroll
        for (int kk = 0; kk < GBK; kk++) {
            float af[GTM], bf[GTN];
#pragma unroll
            for (int i = 0; i < GTM; i++) af[i] = As[kk][ty * GTM + i];
#pragma unroll
            for (int j = 0; j < GTN; j++) bf[j] = Bs[kk][tx * GTN + j];
#pragma unroll
            for (int i = 0; i < GTM; i++)
#pragma unroll
                for (int j = 0; j < GTN; j++)
                    acc[i][j] = fmaf(af[i], bf[j], acc[i][j]);
        }
        __syncthreads();
    }
#pragma unroll
    for (int i = 0; i < GTM; i++) {
        int row = bm + ty * GTM + i;
        long cbase = (long)row * D_ + bn + tx * GTN;
        *reinterpret_cast<float4*>(C + cbase) = make_float4(acc[i][0], acc[i][1], acc[i][2], acc[i][3]);
    }
}

// ---------------- elementwise / scan / LN kernels ----------------
__device__ __forceinline__ float blockReduceSum256(float v) {
    __shared__ float sh[8];
    __syncthreads();
    int lane = threadIdx.x & 31;
    int w = threadIdx.x >> 5;
#pragma unroll
    for (int o = 16; o > 0; o >>= 1) v += __shfl_down_sync(0xffffffffu, v, o);
    if (lane == 0) sh[w] = v;
    __syncthreads();
    if (w == 0) {
        float t = (lane < 8) ? sh[lane] : 0.f;
#pragma unroll
        for (int o = 4; o > 0; o >>= 1) t += __shfl_down_sync(0xffffffffu, t, o);
        if (lane == 0) sh[0] = t;
    }
    __syncthreads();
    return sh[0];
}

// fused conversions: Dx -> fp16 hi/lo (x16); Dy,E -> fp16 hi/lo (x64); + g_DEC init
__global__ void conv_all_kernel(const float* __restrict__ Dx, const float* __restrict__ Dy,
                                const float* __restrict__ E)
{
    int blk = blockIdx.x;
    const float* src;
    __half *hi, *lo;
    float scale;
    int local;
    if (blk < 1024)      { src = Dx; hi = g_DxH; lo = g_DxL; scale = 16.f; local = blk; }
    else if (blk < 2048) { src = Dy; hi = g_DyH; lo = g_DyL; scale = 64.f; local = blk - 1024; }
    else                 { src = E;  hi = g_EH;  lo = g_EL;  scale = 64.f; local = blk - 2048; }
    long i = (long)local * 256 + threadIdx.x;
    float4 v = reinterpret_cast<const float4*>(src)[i];
    float vv[4] = {v.x * scale, v.y * scale, v.z * scale, v.w * scale};
    unsigned short hs[4], ls[4];
#pragma unroll
    for (int j = 0; j < 4; j++) {
        __half h = __float2half_rn(vv[j]);
        __half l = __float2half_rn(vv[j] - __half2float(h));
        hs[j] = __half_as_ushort(h);
        ls[j] = __half_as_ushort(l);
    }
    reinterpret_cast<ushort4*>(hi)[i] = make_ushort4(hs[0], hs[1], hs[2], hs[3]);
    reinterpret_cast<ushort4*>(lo)[i] = make_ushort4(ls[0], ls[1], ls[2], ls[3]);
    if (blk == 0 && threadIdx.x == 0) {
        float d = 1.f;
        for (int t = 0; t < T_; t++) { g_DEC[t] = d; d *= DECF; }
    }
}

// gather 16*emb[idx] -> fp16 single, and zero g_CS
__global__ void gatherconv_kernel(const float* __restrict__ emb, const int* __restrict__ idx)
{
    int m = blockIdx.x;
    int t = threadIdx.x;   // 64 threads, float4 each
    if (t == 0) g_CS[m] = 0.f;
    float4 v = *reinterpret_cast<const float4*>(emb + (long)idx[m] * D_ + t * 4);
    ushort4 o = make_ushort4(
        __half_as_ushort(__float2half_rn(v.x * 16.f)),
        __half_as_ushort(__float2half_rn(v.y * 16.f)),
        __half_as_ushort(__float2half_rn(v.z * 16.f)),
        __half_as_ushort(__float2half_rn(v.w * 16.f)));
    reinterpret_cast<ushort4*>(g_Vf)[(long)m * (D_ / 4) + t] = o;
}

__global__ void screc_kernel() {
    __shared__ float cs[B_ * T_];     // [t][b] layout, conflict-free
    for (int i = threadIdx.x; i < B_ * T_; i += 256) {
        int t = i >> 5, b = i & 31;
        cs[t * 32 + b] = g_CS[b * T_ + t] * (1.f / 256.f);   // unscale 256*P
    }
    __syncthreads();
    if (threadIdx.x < B_) {
        int b = threadIdx.x;
        float sprev = 0.f;
        for (int t = 0; t < T_; t++) {
            float sumx = __fdividef(sprev, sprev + EPSF);
            float s = DECF * sumx + cs[t * 32 + b];
            g_Cc[b * T_ + t] = __fdividef(1.f, s + EPSF);
            sprev = s;
        }
    }
}

__global__ void xrecur_kernel() {
    int b = blockIdx.y;
    int n = blockIdx.x * 256 + threadIdx.x;
    __shared__ float sc[T_];
    sc[threadIdx.x] = g_Cc[b * T_ + threadIdx.x];
    __syncthreads();
    float x = 0.f;
    long base = (long)b * T_ * N_ + n;
    for (int t = 0; t < T_; t++) {
        float p = g_X[base + (long)t * N_] * (1.f / 256.f);   // unscale 256*P
        x = (DECF * x + p) * sc[t];
        __nv_bfloat16 h = __float2bfloat16(x);
        g_Xh[base + (long)t * N_] = h;
        g_Xl[base + (long)t * N_] = __float2bfloat16(x - __bfloat162float(h));
    }
}

// OUT: 0 = fp32, 1 = fp16 single
template <int OUT, int NPART>
__global__ void ln_rows(const float* __restrict__ in, float* __restrict__ outf,
                        unsigned short* __restrict__ oh,
                        const int* __restrict__ gidx, float inscale)
{
    int m = blockIdx.x;
    long r = gidx ? (long)gidx[m] : (long)m;
    float z = in[r * D_ + threadIdx.x];
#pragma unroll
    for (int p = 1; p < NPART; p++)
        z += in[(long)p * M_ * D_ + r * D_ + threadIdx.x];
    z *= inscale;
    float mean = blockReduceSum256(z) * (1.f / D_);
    float d = z - mean;
    float var = blockReduceSum256(d * d) * (1.f / (D_ - 1));
    float v = d / (sqrtf(var) + EPSF);
    long o = (long)m * D_ + threadIdx.x;
    if (OUT == 1) {
        oh[o] = __half_as_ushort(__float2half_rn(v));
    } else {
        outf[o] = v;
    }
}

// ---------------- launch ----------------
extern "C" void kernel_launch(void* const* d_in, const int* in_sizes, int n_in,
                              void* d_out, int out_size)
{
    (void)in_sizes; (void)n_in; (void)out_size;
    const int*   idx  = (const int*)d_in[0];
    const float* temb = (const float*)d_in[1];
    const float* E    = (const float*)d_in[2];
    const float* Dx   = (const float*)d_in[3];
    const float* Dy   = (const float*)d_in[4];
    float* out = (float*)d_out;

    float *pX, *pU, *pS, *pA, *pO;
    __nv_bfloat16 *pXh, *pXl;
    __half *pVf, *pDxH, *pDxL, *pDyH, *pDyL, *pEH, *pEL, *pAf, *pYf;
    cudaGetSymbolAddress((void**)&pX,  g_X);
    cudaGetSymbolAddress((void**)&pU,  g_U);
    cudaGetSymbolAddress((void**)&pS,  g_S);
    cudaGetSymbolAddress((void**)&pA,  g_A);
    cudaGetSymbolAddress((void**)&pO,  g_O);
    cudaGetSymbolAddress((void**)&pXh, g_Xh);  cudaGetSymbolAddress((void**)&pXl, g_Xl);
    cudaGetSymbolAddress((void**)&pVf, g_Vf);
    cudaGetSymbolAddress((void**)&pDxH, g_DxH); cudaGetSymbolAddress((void**)&pDxL, g_DxL);
    cudaGetSymbolAddress((void**)&pDyH, g_DyH); cudaGetSymbolAddress((void**)&pDyL, g_DyL);
    cudaGetSymbolAddress((void**)&pEH, g_EH);  cudaGetSymbolAddress((void**)&pEL, g_EL);
    cudaGetSymbolAddress((void**)&pAf, g_Af);  cudaGetSymbolAddress((void**)&pYf, g_Yf);

    const int SM2 = 3 * 3 * TILE_B;   // 73728
    const int SM1 = 3 * 2 * TILE_B;   // 49152
    cudaFuncSetAttribute(mma_nt<EPI_RELU, MD_SPLITB, false, true>,
                         cudaFuncAttributeMaxDynamicSharedMemorySize, SM2);
    cudaFuncSetAttribute(mma_nt<EPI_NONE, MD_SINGLE, true, false>,
                         cudaFuncAttributeMaxDynamicSharedMemorySize, SM1);
    cudaFuncSetAttribute(mma_nt<EPI_RELUMULX, MD_SPLITB, false, true>,
                         cudaFuncAttributeMaxDynamicSharedMemorySize, SM2);
    cudaFuncSetAttribute(mma_nt<EPI_NONE, MD_SPLITB, false, true>,
                         cudaFuncAttributeMaxDynamicSharedMemorySize, SM2);

    // fused conversions (+g_DEC)
    conv_all_kernel<<<3072, 256>>>(Dx, Dy, E);
    // embedding gather/convert (+g_CS zero)
    gatherconv_kernel<<<M_, 64>>>(temb, idx);
    // U = LN(emb[idx])
    ln_rows<0, 1><<<M_, 256>>>(temb, pU, nullptr, idx, 1.f);

    // G1 (fp16 2-pass): 256*P = relu((16v) @ (16Dx)^T) -> g_X, fused row-sum -> g_CS
    mma_nt<EPI_RELU, MD_SPLITB, false, true><<<dim3(N_ / 128, M_ / 128, 1), 256, SM2>>>(
        (const __nv_bfloat16*)pVf, (const __nv_bfloat16*)pDxH, (const __nv_bfloat16*)pDxL,
        pX, nullptr, nullptr, nullptr,
        N_, D_, D_, 0, 0, 0, 0, 1);

    // scalar L1 recurrence + parallel x scan; emits x as bf16 hi/lo
    screc_kernel<<<1, 256>>>();
    xrecur_kernel<<<dim3(N_ / 256, B_, 1), 256>>>();

    // scores (raw, split-K x2, single-pass bf16; positive sums)
    mma_nt<EPI_NONE, MD_SINGLE, true, false><<<dim3(T_ / 128, T_ / 128, 2 * B_), 256, SM1>>>(
        pXh, pXh, nullptr, pS, nullptr, nullptr, nullptr,
        T_, N_, N_ / 2, (long)T_ * N_, (long)T_ * N_, (long)T_ * T_,
        (long)B_ * T_ * T_, B_);

    // a* = (decayed (S0+S1)) @ U  (SIMT fp32, split-K x2; decay+mask fused)
    gemm_nn<<<dim3(D_ / GBN, T_ / GBM, 2 * B_), 256>>>(
        pS, pS + (long)B_ * T_ * T_, pU, pA);

    // a* <- LN(sum of 2 partials) -> fp16 single
    ln_rows<1, 2><<<M_, 256>>>(pA, nullptr, (unsigned short*)pAf, nullptr, 1.f);

    // G2 (fp16 2-pass): y = relu(LN(a*) @ (64Dy)^T) * x * 16 -> fp16 (1024*y)
    mma_nt<EPI_RELUMULX, MD_SPLITB, false, true><<<dim3(N_ / 128, M_ / 128, 1), 256, SM2>>>(
        (const __nv_bfloat16*)pAf, (const __nv_bfloat16*)pDyH, (const __nv_bfloat16*)pDyL,
        nullptr, (__nv_bfloat16*)pYf, pXh, pXl,
        N_, D_, D_, 0, 0, 0, 0, 1);

    // G3 (fp16 2-pass, split-K x2): o_p = (1024y) @ (64E)^T -> g_O partials (65536*o)
    mma_nt<EPI_NONE, MD_SPLITB, false, true><<<dim3(D_ / 128, M_ / 128, 2), 256, SM2>>>(
        (const __nv_bfloat16*)pYf, (const __nv_bfloat16*)pEH, (const __nv_bfloat16*)pEL,
        pO, nullptr, nullptr, nullptr,
        D_, N_, N_ / 2, 0, 0, 0, (long)M_ * D_, 1);

    // out = LN((sum of 2 partials) / 65536)
    ln_rows<0, 2><<<M_, 256>>>(pO, out, nullptr, nullptr, 1.f / 65536.f);
}

// round 10
// speedup vs baseline: 3.8104x; 1.1551x over previous
#include <cuda_runtime.h>
#include <cuda_bf16.h>
#include <cuda_fp16.h>
#include <cstdint>

#define B_   32
#define T_   256
#define N_   4096
#define D_   256
#define M_   (B_ * T_)
#define EPSF 1e-6f
#define DECF 0.97f

// ---------------- scratch (device globals; no allocation) ----------------
__device__ float g_X [(long long)M_ * N_];      // 256*P (fp32 scan domain)
__device__ float g_CS[M_];
__device__ float g_Cc[M_];
__device__ float g_U [M_ * D_];
__device__ float g_S [2LL * B_ * T_ * T_];      // 2 split-K partials of 65536*scores
__device__ float g_A [2LL * M_ * D_];           // 2 split-K partials of a*
__device__ float g_O [2LL * M_ * D_];           // 2 split-K partials of G3
__device__ float g_DEC[T_];                     // 0.97^L / 65536 (gemm_nn only)

// fp16 operands; scalings: v,Dx x16; Dy,E x64; x x256; y x1024
__device__ __half g_Vf [M_ * D_];                             // 16*emb[idx]
__device__ __half g_DxH[N_ * D_], g_DxL[N_ * D_];             // 16*Dx hi/lo
__device__ __half g_DyH[N_ * D_];                             // 64*Dy
__device__ __half g_EH [D_ * N_];                             // 64*E
__device__ __half g_Af [M_ * D_];                             // LN(a*) fp16
__device__ __half g_Xf [(long long)M_ * N_];                  // 256*x fp16
__device__ __half g_Yf [(long long)M_ * N_];                  // 1024*y fp16

// ---------------- PTX helpers (baseline ISA only) ----------------
__device__ __forceinline__ uint32_t smem_u32(const void* p) {
    uint32_t a;
    asm("{ .reg .u64 t; cvta.to.shared.u64 t, %1; cvt.u32.u64 %0, t; }" : "=r"(a) : "l"(p));
    return a;
}
__device__ __forceinline__ void cp16(uint32_t so, const void* g) {
    asm volatile("cp.async.cg.shared.global [%0], [%1], 16;" :: "r"(so), "l"(g));
}
__device__ __forceinline__ void cp_commit() {
    asm volatile("cp.async.commit_group;" ::: "memory");
}
template <int NN>
__device__ __forceinline__ void cp_wait() {
    asm volatile("cp.async.wait_group %0;" :: "n"(NN) : "memory");
}
__device__ __forceinline__ void ldsm_x4(uint32_t* f, uint32_t a) {
    asm volatile("ldmatrix.sync.aligned.m8n8.x4.shared.b16 {%0,%1,%2,%3}, [%4];"
        : "=r"(f[0]), "=r"(f[1]), "=r"(f[2]), "=r"(f[3]) : "r"(a));
}
__device__ __forceinline__ void mma_f16(float* c, const uint32_t* a, const uint32_t* b) {
    asm volatile("mma.sync.aligned.m16n8k16.row.col.f32.f16.f16.f32 "
        "{%0,%1,%2,%3}, {%4,%5,%6,%7}, {%8,%9}, {%0,%1,%2,%3};"
        : "+f"(c[0]), "+f"(c[1]), "+f"(c[2]), "+f"(c[3])
        : "r"(a[0]), "r"(a[1]), "r"(a[2]), "r"(a[3]), "r"(b[0]), "r"(b[1]));
}

// ---------------- HMMA NT GEMM: C[m,n] = sum_k A[m,k]*B[n,k] (fp16) -----------
enum { EPI_NONE = 0, EPI_RELU = 1, EPI_RELUMULX = 2 };
enum { MD_SINGLE = 0, MD_SPLITB = 2 };   // SPLITB: A*(Bh+Bl) 2-pass

// swizzled tile: 128 rows x 64B (32 elts); phys 16B-slot = g ^ ((r>>1)&3)
#define TILE_B 8192

template <int EPI, int MODE, bool TRISKIP>
__global__ void __launch_bounds__(256, 2) mma_nt(
    const __half* __restrict__ Ah,
    const __half* __restrict__ Bh, const __half* __restrict__ Bl,
    float* __restrict__ Cf, __half* __restrict__ Ch,
    const __half* __restrict__ Xf,
    int Nd, int K, int kLen, long sA, long sB, long sC, long splitStride, int batches)
{
    constexpr int NTILES  = (MODE == MD_SINGLE) ? 2 : 3;
    constexpr int STAGE_B = NTILES * TILE_B;

    extern __shared__ char smem[];
    const uint32_t sb = smem_u32(smem);
    const int tid  = threadIdx.x;
    const int lane = tid & 31;
    const int wid  = tid >> 5;
    const int wm   = wid >> 2;          // 0..1  -> m offset wm*64
    const int wn   = wid & 3;           // 0..3  -> n offset wn*32
    const int zz   = blockIdx.z;
    const int split = zz / batches;
    const int bz    = zz - split * batches;
    const long kOff = (long)split * kLen;
    const int bm = blockIdx.y * 128;
    const int bn = blockIdx.x * 128;
    const bool skip = TRISKIP && (bn >= bm + 128);

    float acc[4][4][4];
#pragma unroll
    for (int i = 0; i < 4; i++)
#pragma unroll
        for (int j = 0; j < 4; j++)
#pragma unroll
            for (int v = 0; v < 4; v++) acc[i][j][v] = 0.f;

    if (!skip) {
        const __half* Ahp = Ah + (long)bz * sA + (long)bm * K + kOff;
        const __half* Bhp = Bh + (long)bz * sB + (long)bn * K + kOff;
        const __half* Blp = Bl + (long)bz * sB + (long)bn * K + kOff;

        const int qr0 = tid >> 2;             // row (0..63)
        const int qc0 = tid & 3;              // 16B group
        auto stage_load = [&](int stg, int k0) {
            uint32_t base = sb + stg * STAGE_B;
#pragma unroll
            for (int i = 0; i < 2; i++) {
                int r = qr0 + i * 64;
                uint32_t so = (uint32_t)(r * 64 + ((qc0 ^ ((r >> 1) & 3)) * 16));
                long gofs = (long)r * K + k0 + qc0 * 8;
                cp16(base + so, Ahp + gofs);
                cp16(base + TILE_B + so, Bhp + gofs);
                if (MODE == MD_SPLITB)
                    cp16(base + 2 * TILE_B + so, Blp + gofs);
            }
            cp_commit();
        };

        const int nC = kLen / 32;
        stage_load(0, 0);
        stage_load(1, 32);

        // per-lane ldsm logical positions
        const uint32_t aRow  = (uint32_t)(wm * 64 + (lane & 15));
        const uint32_t aColG = (uint32_t)(lane >> 4);
        const uint32_t bRow  = (uint32_t)(wn * 32 + ((lane >> 4) << 3) + (lane & 7));
        const uint32_t bColG = (uint32_t)((lane >> 3) & 1);
        const uint32_t sa = (aRow >> 1) & 3;
        const uint32_t sbw = (bRow >> 1) & 3;
        uint32_t aoff[2], boff[2];
#pragma unroll
        for (int ks = 0; ks < 2; ks++) {
            aoff[ks] = aRow * 64 + (((ks * 2 + aColG) ^ sa) * 16);
            boff[ks] = bRow * 64 + (((ks * 2 + bColG) ^ sbw) * 16);
        }

        int stg = 0;
        for (int c = 0; c < nC; c++) {
            cp_wait<1>();
            __syncthreads();
            if (c + 2 < nC) {
                int ns = stg + 2; if (ns >= 3) ns -= 3;
                stage_load(ns, (c + 2) * 32);
            } else {
                cp_commit();   // empty group keeps wait<1> accounting uniform
            }

            const uint32_t st = sb + stg * STAGE_B;
#pragma unroll
            for (int ks = 0; ks < 2; ks++) {
                uint32_t fA[4][4], fB[2][4], fB2[2][4];
                // pass 1: A . Bh
#pragma unroll
                for (int ma = 0; ma < 4; ma++)
                    ldsm_x4(fA[ma], st + aoff[ks] + ma * 1024);
#pragma unroll
                for (int p = 0; p < 2; p++)
                    ldsm_x4(fB[p], st + TILE_B + boff[ks] + p * 1024);
#pragma unroll
                for (int ma = 0; ma < 4; ma++)
#pragma unroll
                    for (int na = 0; na < 4; na++)
                        mma_f16(acc[ma][na], fA[ma], &fB[na >> 1][2 * (na & 1)]);
                if (MODE == MD_SPLITB) {
                    // pass 2: A . Bl (A stays live)
#pragma unroll
                    for (int p = 0; p < 2; p++)
                        ldsm_x4(fB2[p], st + 2 * TILE_B + boff[ks] + p * 1024);
#pragma unroll
                    for (int ma = 0; ma < 4; ma++)
#pragma unroll
                        for (int na = 0; na < 4; na++)
                            mma_f16(acc[ma][na], fA[ma], &fB2[na >> 1][2 * (na & 1)]);
                }
            }
            stg = (stg == 2) ? 0 : stg + 1;
        }
    }

    // ---- epilogue ----
    float* Cfo = (EPI != EPI_RELUMULX) ? (Cf + split * splitStride + (long)bz * sC) : nullptr;
    const int gr = lane >> 2;          // 0..7
    const int gc = (lane & 3) * 2;
#pragma unroll
    for (int ma = 0; ma < 4; ma++) {
#pragma unroll
        for (int half = 0; half < 2; half++) {
            const int row = bm + wm * 64 + ma * 16 + gr + half * 8;
            float rs = 0.f;
#pragma unroll
            for (int na = 0; na < 4; na++) {
                const int col = bn + wn * 32 + na * 8 + gc;
                float v0 = acc[ma][na][half * 2 + 0];
                float v1 = acc[ma][na][half * 2 + 1];
                long off = (long)row * Nd + col;
                if (EPI == EPI_RELUMULX) {
                    // stored y = relu(64g) * (256x) / 16 = 1024*y_true
                    ushort2 xf = *reinterpret_cast<const ushort2*>(Xf + off);
                    float x0 = __half2float(__ushort_as_half(xf.x));
                    float x1 = __half2float(__ushort_as_half(xf.y));
                    v0 = fmaxf(v0, 0.f) * x0 * (1.f / 16.f);
                    v1 = fmaxf(v1, 0.f) * x1 * (1.f / 16.f);
                    ushort2 o = make_ushort2(__half_as_ushort(__float2half_rn(v0)),
                                             __half_as_ushort(__float2half_rn(v1)));
                    *reinterpret_cast<ushort2*>(reinterpret_cast<unsigned short*>(Ch) + off) = o;
                } else {
                    if (EPI == EPI_RELU) {
                        v0 = fmaxf(v0, 0.f); v1 = fmaxf(v1, 0.f);
                        rs += v0 + v1;
                    }
                    *reinterpret_cast<float2*>(Cfo + off) = make_float2(v0, v1);
                }
            }
            if (EPI == EPI_RELU) {   // fused partial row-sum for L1 norm
                rs += __shfl_xor_sync(0xffffffffu, rs, 1);
                rs += __shfl_xor_sync(0xffffffffu, rs, 2);
                if ((lane & 3) == 0) atomicAdd(&g_CS[row], rs);
            }
        }
    }
}

// ---------------- SIMT NN GEMM: a* = (decayed S) @ U, split-K x2 ----------------
#define GBM 128
#define GBN 64
#define GBK 16
#define GTM 8
#define GTN 4

__global__ __launch_bounds__(256)
void gemm_nn(const float* __restrict__ A0, const float* __restrict__ A1,
             const float* __restrict__ B, float* __restrict__ C)
{
    const int zz = blockIdx.z;
    const int bz = zz & 31;          // batch
    const int split = zz >> 5;       // 0..1
    A0 += (long)bz * T_ * T_;
    A1 += (long)bz * T_ * T_;
    B  += (long)bz * T_ * D_;
    C  += (long)split * M_ * D_ + (long)bz * T_ * D_;
    const int bm = blockIdx.y * GBM;
    const int bn = blockIdx.x * GBN;

    __shared__ __align__(16) float As[GBK][GBM + 4];
    __shared__ __align__(16) float Bs[GBK][GBN + 4];

    const int tid = threadIdx.x;
    const int tx = tid & 15;
    const int ty = tid >> 4;

    float acc[GTM][GTN];
#pragma unroll
    for (int i = 0; i < GTM; i++)
#pragma unroll
        for (int j = 0; j < GTN; j++) acc[i][j] = 0.f;

    const int lr = tid >> 2;
    const int lk = (tid & 3) * 4;
    const int brow = tid >> 4;
    const int bcol = (tid & 15) * 4;

    const int kBeg = split * (T_ / 2);
    for (int k0 = kBeg; k0 < kBeg + T_ / 2; k0 += GBK) {
#pragma unroll
        for (int i = 0; i < 2; i++) {
            int r = lr + i * 64;
            int t = bm + r;
            long ao = (long)t * T_ + k0 + lk;
            float4 v = *reinterpret_cast<const float4*>(A0 + ao);
            float4 w = *reinterpret_cast<const float4*>(A1 + ao);
            float vv[4] = {v.x + w.x, v.y + w.y, v.z + w.z, v.w + w.w};
#pragma unroll
            for (int j = 0; j < 4; j++) {
                int L = t - (k0 + lk + j);
                As[lk + j][r] = (L > 0) ? vv[j] * g_DEC[L] : 0.f;   // g_DEC has /65536 baked in
            }
        }
        {
            float4 v = *reinterpret_cast<const float4*>(B + (long)(k0 + brow) * D_ + bn + bcol);
            Bs[brow][bcol + 0] = v.x; Bs[brow][bcol + 1] = v.y;
            Bs[brow][bcol + 2] = v.z; Bs[brow][bcol + 3] = v.w;
        }
        __syncthreads();
#pragma unroll
        for (int kk = 0; kk < GBK; kk++) {
            float af[GTM], bf[GTN];
#pragma unroll
            for (int i = 0; i < GTM; i++) af[i] = As[kk][ty * GTM + i];
#pragma unroll
            for (int j = 0; j < GTN; j++) bf[j] = Bs[kk][tx * GTN + j];
#pragma unroll
            for (int i = 0; i < GTM; i++)
#pragma unroll
                for (int j = 0; j < GTN; j++)
                    acc[i][j] = fmaf(af[i], bf[j], acc[i][j]);
        }
        __syncthreads();
    }
#pragma unroll
    for (int i = 0; i < GTM; i++) {
        int row = bm + ty * GTM + i;
        long cbase = (long)row * D_ + bn + tx * GTN;
        *reinterpret_cast<float4*>(C + cbase) = make_float4(acc[i][0], acc[i][1], acc[i][2], acc[i][3]);
    }
}

// ---------------- elementwise / scan / LN kernels ----------------
__device__ __forceinline__ float blockReduceSum256(float v) {
    __shared__ float sh[8];
    __syncthreads();
    int lane = threadIdx.x & 31;
    int w = threadIdx.x >> 5;
#pragma unroll
    for (int o = 16; o > 0; o >>= 1) v += __shfl_down_sync(0xffffffffu, v, o);
    if (lane == 0) sh[w] = v;
    __syncthreads();
    if (w == 0) {
        float t = (lane < 8) ? sh[lane] : 0.f;
#pragma unroll
        for (int o = 4; o > 0; o >>= 1) t += __shfl_down_sync(0xffffffffu, t, o);
        if (lane == 0) sh[0] = t;
    }
    __syncthreads();
    return sh[0];
}

// fused conversions: Dx -> fp16 hi/lo (x16); Dy,E -> fp16 hi (x64); + g_DEC init
__global__ void conv_all_kernel(const float* __restrict__ Dx, const float* __restrict__ Dy,
                                const float* __restrict__ E)
{
    int blk = blockIdx.x;
    if (blk < 1024) {
        long i = (long)blk * 256 + threadIdx.x;
        float4 v = reinterpret_cast<const float4*>(Dx)[i];
        float vv[4] = {v.x * 16.f, v.y * 16.f, v.z * 16.f, v.w * 16.f};
        unsigned short hs[4], ls[4];
#pragma unroll
        for (int j = 0; j < 4; j++) {
            __half h = __float2half_rn(vv[j]);
            __half l = __float2half_rn(vv[j] - __half2float(h));
            hs[j] = __half_as_ushort(h);
            ls[j] = __half_as_ushort(l);
        }
        reinterpret_cast<ushort4*>(g_DxH)[i] = make_ushort4(hs[0], hs[1], hs[2], hs[3]);
        reinterpret_cast<ushort4*>(g_DxL)[i] = make_ushort4(ls[0], ls[1], ls[2], ls[3]);
    } else {
        const float* src = (blk < 2048) ? Dy : E;
        __half* hi = (blk < 2048) ? g_DyH : g_EH;
        long i = (long)((blk < 2048) ? blk - 1024 : blk - 2048) * 256 + threadIdx.x;
        float4 v = reinterpret_cast<const float4*>(src)[i];
        ushort4 o = make_ushort4(
            __half_as_ushort(__float2half_rn(v.x * 64.f)),
            __half_as_ushort(__float2half_rn(v.y * 64.f)),
            __half_as_ushort(__float2half_rn(v.z * 64.f)),
            __half_as_ushort(__float2half_rn(v.w * 64.f)));
        reinterpret_cast<ushort4*>(hi)[i] = o;
    }
    if (blk == 0 && threadIdx.x == 0) {
        float d = 1.f;
        for (int t = 0; t < T_; t++) { g_DEC[t] = d * (1.f / 65536.f); d *= DECF; }
    }
}

// gather 16*emb[idx] -> fp16 single, and zero g_CS
__global__ void gatherconv_kernel(const float* __restrict__ emb, const int* __restrict__ idx)
{
    int m = blockIdx.x;
    int t = threadIdx.x;   // 64 threads, float4 each
    if (t == 0) g_CS[m] = 0.f;
    float4 v = *reinterpret_cast<const float4*>(emb + (long)idx[m] * D_ + t * 4);
    ushort4 o = make_ushort4(
        __half_as_ushort(__float2half_rn(v.x * 16.f)),
        __half_as_ushort(__float2half_rn(v.y * 16.f)),
        __half_as_ushort(__float2half_rn(v.z * 16.f)),
        __half_as_ushort(__float2half_rn(v.w * 16.f)));
    reinterpret_cast<ushort4*>(g_Vf)[(long)m * (D_ / 4) + t] = o;
}

__global__ void screc_kernel() {
    __shared__ float cs[B_ * T_];     // [t][b] layout, conflict-free
    for (int i = threadIdx.x; i < B_ * T_; i += 256) {
        int t = i >> 5, b = i & 31;
        cs[t * 32 + b] = g_CS[b * T_ + t] * (1.f / 256.f);   // unscale 256*P
    }
    __syncthreads();
    if (threadIdx.x < B_) {
        int b = threadIdx.x;
        float sprev = 0.f;
        for (int t = 0; t < T_; t++) {
            float sumx = __fdividef(sprev, sprev + EPSF);
            float s = DECF * sumx + cs[t * 32 + b];
            g_Cc[b * T_ + t] = __fdividef(1.f, s + EPSF);
            sprev = s;
        }
    }
}

__global__ void xrecur_kernel() {
    int b = blockIdx.y;
    int n = blockIdx.x * 256 + threadIdx.x;
    __shared__ float sc[T_];
    sc[threadIdx.x] = g_Cc[b * T_ + threadIdx.x];
    __syncthreads();
    float x = 0.f;
    long base = (long)b * T_ * N_ + n;
    for (int t = 0; t < T_; t++) {
        float p = g_X[base + (long)t * N_] * (1.f / 256.f);   // unscale 256*P
        x = (DECF * x + p) * sc[t];
        g_Xf[base + (long)t * N_] = __float2half_rn(x * 256.f);
    }
}

// OUT: 0 = fp32, 1 = fp16 single
template <int OUT, int NPART>
__global__ void ln_rows(const float* __restrict__ in, float* __restrict__ outf,
                        unsigned short* __restrict__ oh,
                        const int* __restrict__ gidx, float inscale)
{
    int m = blockIdx.x;
    long r = gidx ? (long)gidx[m] : (long)m;
    float z = in[r * D_ + threadIdx.x];
#pragma unroll
    for (int p = 1; p < NPART; p++)
        z += in[(long)p * M_ * D_ + r * D_ + threadIdx.x];
    z *= inscale;
    float mean = blockReduceSum256(z) * (1.f / D_);
    float d = z - mean;
    float var = blockReduceSum256(d * d) * (1.f / (D_ - 1));
    float v = d / (sqrtf(var) + EPSF);
    long o = (long)m * D_ + threadIdx.x;
    if (OUT == 1) {
        oh[o] = __half_as_ushort(__float2half_rn(v));
    } else {
        outf[o] = v;
    }
}

// ---------------- launch ----------------
extern "C" void kernel_launch(void* const* d_in, const int* in_sizes, int n_in,
                              void* d_out, int out_size)
{
    (void)in_sizes; (void)n_in; (void)out_size;
    const int*   idx  = (const int*)d_in[0];
    const float* temb = (const float*)d_in[1];
    const float* E    = (const float*)d_in[2];
    const float* Dx   = (const float*)d_in[3];
    const float* Dy   = (const float*)d_in[4];
    float* out = (float*)d_out;

    float *pX, *pU, *pS, *pA, *pO;
    __half *pVf, *pDxH, *pDxL, *pDyH, *pEH, *pAf, *pXf, *pYf;
    cudaGetSymbolAddress((void**)&pX,  g_X);
    cudaGetSymbolAddress((void**)&pU,  g_U);
    cudaGetSymbolAddress((void**)&pS,  g_S);
    cudaGetSymbolAddress((void**)&pA,  g_A);
    cudaGetSymbolAddress((void**)&pO,  g_O);
    cudaGetSymbolAddress((void**)&pVf, g_Vf);
    cudaGetSymbolAddress((void**)&pDxH, g_DxH); cudaGetSymbolAddress((void**)&pDxL, g_DxL);
    cudaGetSymbolAddress((void**)&pDyH, g_DyH);
    cudaGetSymbolAddress((void**)&pEH, g_EH);
    cudaGetSymbolAddress((void**)&pAf, g_Af);
    cudaGetSymbolAddress((void**)&pXf, g_Xf);
    cudaGetSymbolAddress((void**)&pYf, g_Yf);

    const int SM2 = 3 * 3 * TILE_B;   // 73728
    const int SM1 = 3 * 2 * TILE_B;   // 49152
    cudaFuncSetAttribute(mma_nt<EPI_RELU, MD_SPLITB, false>,
                         cudaFuncAttributeMaxDynamicSharedMemorySize, SM2);
    cudaFuncSetAttribute(mma_nt<EPI_NONE, MD_SINGLE, true>,
                         cudaFuncAttributeMaxDynamicSharedMemorySize, SM1);
    cudaFuncSetAttribute(mma_nt<EPI_RELUMULX, MD_SINGLE, false>,
                         cudaFuncAttributeMaxDynamicSharedMemorySize, SM1);
    cudaFuncSetAttribute(mma_nt<EPI_NONE, MD_SINGLE, false>,
                         cudaFuncAttributeMaxDynamicSharedMemorySize, SM1);

    // fused conversions (+g_DEC)
    conv_all_kernel<<<3072, 256>>>(Dx, Dy, E);
    // embedding gather/convert (+g_CS zero)
    gatherconv_kernel<<<M_, 64>>>(temb, idx);
    // U = LN(emb[idx])
    ln_rows<0, 1><<<M_, 256>>>(temb, pU, nullptr, idx, 1.f);

    // G1 (fp16 2-pass): 256*P = relu((16v) @ (16Dx)^T) -> g_X, fused row-sum -> g_CS
    mma_nt<EPI_RELU, MD_SPLITB, false><<<dim3(N_ / 128, M_ / 128, 1), 256, SM2>>>(
        pVf, pDxH, pDxL, pX, nullptr, nullptr,
        N_, D_, D_, 0, 0, 0, 0, 1);

    // scalar L1 recurrence + parallel x scan; emits x as fp16 (x256)
    screc_kernel<<<1, 256>>>();
    xrecur_kernel<<<dim3(N_ / 256, B_, 1), 256>>>();

    // scores (65536*raw, split-K x2, single-pass fp16; positive sums)
    mma_nt<EPI_NONE, MD_SINGLE, true><<<dim3(T_ / 128, T_ / 128, 2 * B_), 256, SM1>>>(
        pXf, pXf, nullptr, pS, nullptr, nullptr,
        T_, N_, N_ / 2, (long)T_ * N_, (long)T_ * N_, (long)T_ * T_,
        (long)B_ * T_ * T_, B_);

    // a* = (decayed (S0+S1)/65536) @ U  (SIMT fp32, split-K x2; decay+mask+unscale fused)
    gemm_nn<<<dim3(D_ / GBN, T_ / GBM, 2 * B_), 256>>>(
        pS, pS + (long)B_ * T_ * T_, pU, pA);

    // a* <- LN(sum of 2 partials) -> fp16 single
    ln_rows<1, 2><<<M_, 256>>>(pA, nullptr, (unsigned short*)pAf, nullptr, 1.f);

    // G2 (fp16 single-pass): 1024y = relu(LN(a*) @ (64Dy)^T) * (256x) / 16 -> fp16
    mma_nt<EPI_RELUMULX, MD_SINGLE, false><<<dim3(N_ / 128, M_ / 128, 1), 256, SM1>>>(
        pAf, pDyH, nullptr, nullptr, pYf, pXf,
        N_, D_, D_, 0, 0, 0, 0, 1);

    // G3 (fp16 single-pass, split-K x2): o_p = (1024y) @ (64E)^T -> g_O partials (65536*o)
    mma_nt<EPI_NONE, MD_SINGLE, false><<<dim3(D_ / 128, M_ / 128, 2), 256, SM1>>>(
        pYf, pEH, nullptr, pO, nullptr, nullptr,
        D_, N_, N_ / 2, 0, 0, 0, (long)M_ * D_, 1);

    // out = LN((sum of 2 partials) / 65536)
    ln_rows<0, 2><<<M_, 256>>>(pO, out, nullptr, nullptr, 1.f / 65536.f);
}

// round 11
// speedup vs baseline: 4.2748x; 1.1219x over previous
#include <cuda_runtime.h>
#include <cuda_fp16.h>
#include <cstdint>

#define B_   32
#define T_   256
#define N_   4096
#define D_   256
#define M_   (B_ * T_)
#define EPSF 1e-6f
#define DECF 0.97f

// ---------------- scratch (device globals; no allocation) ----------------
__device__ float g_CS[M_];
__device__ float g_Cc[M_];
__device__ float g_U [M_ * D_];
__device__ float g_S [2LL * B_ * T_ * T_];      // 2 split-K partials of 65536*scores
__device__ float g_A [2LL * M_ * D_];           // 2 split-K partials of a*
__device__ float g_O [2LL * M_ * D_];           // 2 split-K partials of G3
__device__ float g_DEC[T_];                     // 0.97^L / 65536 (gemm_nn only)

// fp16 operands; scalings: v,Dx x16; Dy,E x64; P,x x256; y x1024
__device__ __half g_Vf [M_ * D_];                             // 16*emb[idx]
__device__ __half g_DxH[N_ * D_];                             // 16*Dx
__device__ __half g_DyH[N_ * D_];                             // 64*Dy
__device__ __half g_EH [D_ * N_];                             // 64*E
__device__ __half g_Af [M_ * D_];                             // LN(a*) fp16
__device__ __half g_Xf [(long long)M_ * N_];                  // 256*x fp16
__device__ __half g_Yf [(long long)M_ * N_];                  // 256*P, then 1024*y fp16

// ---------------- PTX helpers (baseline ISA only) ----------------
__device__ __forceinline__ uint32_t smem_u32(const void* p) {
    uint32_t a;
    asm("{ .reg .u64 t; cvta.to.shared.u64 t, %1; cvt.u32.u64 %0, t; }" : "=r"(a) : "l"(p));
    return a;
}
__device__ __forceinline__ void cp16(uint32_t so, const void* g) {
    asm volatile("cp.async.cg.shared.global [%0], [%1], 16;" :: "r"(so), "l"(g));
}
__device__ __forceinline__ void cp_commit() {
    asm volatile("cp.async.commit_group;" ::: "memory");
}
template <int NN>
__device__ __forceinline__ void cp_wait() {
    asm volatile("cp.async.wait_group %0;" :: "n"(NN) : "memory");
}
__device__ __forceinline__ void ldsm_x4(uint32_t* f, uint32_t a) {
    asm volatile("ldmatrix.sync.aligned.m8n8.x4.shared.b16 {%0,%1,%2,%3}, [%4];"
        : "=r"(f[0]), "=r"(f[1]), "=r"(f[2]), "=r"(f[3]) : "r"(a));
}
__device__ __forceinline__ void mma_f16(float* c, const uint32_t* a, const uint32_t* b) {
    asm volatile("mma.sync.aligned.m16n8k16.row.col.f32.f16.f16.f32 "
        "{%0,%1,%2,%3}, {%4,%5,%6,%7}, {%8,%9}, {%0,%1,%2,%3};"
        : "+f"(c[0]), "+f"(c[1]), "+f"(c[2]), "+f"(c[3])
        : "r"(a[0]), "r"(a[1]), "r"(a[2]), "r"(a[3]), "r"(b[0]), "r"(b[1]));
}

// ---------------- HMMA NT GEMM (single-pass fp16, 4-stage pipeline) -----------
enum { EPI_NONE = 0, EPI_RELUH = 1, EPI_RELUMULX = 2 };

// swizzled tile: 128 rows x 64B (32 elts); phys 16B-slot = g ^ ((r>>1)&3)
#define TILE_B  8192
#define STAGE_B (2 * TILE_B)     // A tile + B tile
#define NSTG    4
#define SMEM_SZ (NSTG * STAGE_B) // 65536

template <int EPI, bool TRISKIP>
__global__ void __launch_bounds__(256, 2) mma_nt(
    const __half* __restrict__ Ah, const __half* __restrict__ Bh,
    float* __restrict__ Cf, __half* __restrict__ Ch,
    const __half* __restrict__ Xf,
    int Nd, int K, int kLen, long sA, long sB, long sC, long splitStride, int batches)
{
    extern __shared__ char smem[];
    const uint32_t sb = smem_u32(smem);
    const int tid  = threadIdx.x;
    const int lane = tid & 31;
    const int wid  = tid >> 5;
    const int wm   = wid >> 2;          // 0..1  -> m offset wm*64
    const int wn   = wid & 3;           // 0..3  -> n offset wn*32
    const int zz   = blockIdx.z;
    const int split = zz / batches;
    const int bz    = zz - split * batches;
    const long kOff = (long)split * kLen;
    const int bm = blockIdx.y * 128;
    const int bn = blockIdx.x * 128;
    const bool skip = TRISKIP && (bn >= bm + 128);

    float acc[4][4][4];
#pragma unroll
    for (int i = 0; i < 4; i++)
#pragma unroll
        for (int j = 0; j < 4; j++)
#pragma unroll
            for (int v = 0; v < 4; v++) acc[i][j][v] = 0.f;

    if (!skip) {
        const __half* Ahp = Ah + (long)bz * sA + (long)bm * K + kOff;
        const __half* Bhp = Bh + (long)bz * sB + (long)bn * K + kOff;

        const int qr0 = tid >> 2;             // row (0..63)
        const int qc0 = tid & 3;              // 16B group
        auto stage_load = [&](int stg, int k0) {
            uint32_t base = sb + stg * STAGE_B;
#pragma unroll
            for (int i = 0; i < 2; i++) {
                int r = qr0 + i * 64;
                uint32_t so = (uint32_t)(r * 64 + ((qc0 ^ ((r >> 1) & 3)) * 16));
                long gofs = (long)r * K + k0 + qc0 * 8;
                cp16(base + so, Ahp + gofs);
                cp16(base + TILE_B + so, Bhp + gofs);
            }
            cp_commit();
        };

        const int nC = kLen / 32;             // all callers have nC >= 3
        stage_load(0, 0);
        stage_load(1, 32);
        stage_load(2, 64);

        // per-lane ldsm logical positions
        const uint32_t aRow  = (uint32_t)(wm * 64 + (lane & 15));
        const uint32_t aColG = (uint32_t)(lane >> 4);
        const uint32_t bRow  = (uint32_t)(wn * 32 + ((lane >> 4) << 3) + (lane & 7));
        const uint32_t bColG = (uint32_t)((lane >> 3) & 1);
        const uint32_t sa = (aRow >> 1) & 3;
        const uint32_t sbw = (bRow >> 1) & 3;
        uint32_t aoff[2], boff[2];
#pragma unroll
        for (int ks = 0; ks < 2; ks++) {
            aoff[ks] = aRow * 64 + (((ks * 2 + aColG) ^ sa) * 16);
            boff[ks] = bRow * 64 + (((ks * 2 + bColG) ^ sbw) * 16);
        }

        int stg = 0;
        for (int c = 0; c < nC; c++) {
            cp_wait<NSTG - 2>();              // chunk c complete
            __syncthreads();
            if (c + 3 < nC) {
                int ns = stg + 3; if (ns >= NSTG) ns -= NSTG;
                stage_load(ns, (c + 3) * 32);
            } else {
                cp_commit();   // empty group keeps wait accounting uniform
            }

            const uint32_t st = sb + stg * STAGE_B;
#pragma unroll
            for (int ks = 0; ks < 2; ks++) {
                uint32_t fA[4][4], fB[2][4];
#pragma unroll
                for (int ma = 0; ma < 4; ma++)
                    ldsm_x4(fA[ma], st + aoff[ks] + ma * 1024);
#pragma unroll
                for (int p = 0; p < 2; p++)
                    ldsm_x4(fB[p], st + TILE_B + boff[ks] + p * 1024);
#pragma unroll
                for (int ma = 0; ma < 4; ma++)
#pragma unroll
                    for (int na = 0; na < 4; na++)
                        mma_f16(acc[ma][na], fA[ma], &fB[na >> 1][2 * (na & 1)]);
            }
            stg = (stg == NSTG - 1) ? 0 : stg + 1;
        }
    }

    // ---- epilogue ----
    float* Cfo = (EPI == EPI_NONE) ? (Cf + split * splitStride + (long)bz * sC) : nullptr;
    unsigned short* Ho = (EPI != EPI_NONE) ? reinterpret_cast<unsigned short*>(Ch) : nullptr;
    const int gr = lane >> 2;          // 0..7
    const int gc = (lane & 3) * 2;
#pragma unroll
    for (int ma = 0; ma < 4; ma++) {
#pragma unroll
        for (int half = 0; half < 2; half++) {
            const int row = bm + wm * 64 + ma * 16 + gr + half * 8;
            float rs = 0.f;
#pragma unroll
            for (int na = 0; na < 4; na++) {
                const int col = bn + wn * 32 + na * 8 + gc;
                float v0 = acc[ma][na][half * 2 + 0];
                float v1 = acc[ma][na][half * 2 + 1];
                long off = (long)row * Nd + col;
                if (EPI == EPI_RELUH) {
                    // 256*P = relu(acc); fused row-sum (of 256*P) for L1 norm
                    v0 = fmaxf(v0, 0.f); v1 = fmaxf(v1, 0.f);
                    rs += v0 + v1;
                    ushort2 o = make_ushort2(__half_as_ushort(__float2half_rn(v0)),
                                             __half_as_ushort(__float2half_rn(v1)));
                    *reinterpret_cast<ushort2*>(Ho + off) = o;
                } else if (EPI == EPI_RELUMULX) {
                    // stored y = relu(64g) * (256x) / 16 = 1024*y_true
                    ushort2 xf = *reinterpret_cast<const ushort2*>(Xf + off);
                    float x0 = __half2float(__ushort_as_half(xf.x));
                    float x1 = __half2float(__ushort_as_half(xf.y));
                    v0 = fmaxf(v0, 0.f) * x0 * (1.f / 16.f);
                    v1 = fmaxf(v1, 0.f) * x1 * (1.f / 16.f);
                    ushort2 o = make_ushort2(__half_as_ushort(__float2half_rn(v0)),
                                             __half_as_ushort(__float2half_rn(v1)));
                    *reinterpret_cast<ushort2*>(Ho + off) = o;
                } else {
                    *reinterpret_cast<float2*>(Cfo + off) = make_float2(v0, v1);
                }
            }
            if (EPI == EPI_RELUH) {
                rs += __shfl_xor_sync(0xffffffffu, rs, 1);
                rs += __shfl_xor_sync(0xffffffffu, rs, 2);
                if ((lane & 3) == 0) atomicAdd(&g_CS[row], rs);
            }
        }
    }
}

// ---------------- SIMT NN GEMM: a* = (decayed S) @ U, split-K x2 ----------------
#define GBM 128
#define GBN 64
#define GBK 16
#define GTM 8
#define GTN 4

__global__ __launch_bounds__(256)
void gemm_nn(const float* __restrict__ A0, const float* __restrict__ A1,
             const float* __restrict__ B, float* __restrict__ C)
{
    const int zz = blockIdx.z;
    const int bz = zz & 31;          // batch
    const int split = zz >> 5;       // 0..1
    A0 += (long)bz * T_ * T_;
    A1 += (long)bz * T_ * T_;
    B  += (long)bz * T_ * D_;
    C  += (long)split * M_ * D_ + (long)bz * T_ * D_;
    const int bm = blockIdx.y * GBM;
    const int bn = blockIdx.x * GBN;

    __shared__ __align__(16) float As[GBK][GBM + 4];
    __shared__ __align__(16) float Bs[GBK][GBN + 4];

    const int tid = threadIdx.x;
    const int tx = tid & 15;
    const int ty = tid >> 4;

    float acc[GTM][GTN];
#pragma unroll
    for (int i = 0; i < GTM; i++)
#pragma unroll
        for (int j = 0; j < GTN; j++) acc[i][j] = 0.f;

    const int lr = tid >> 2;
    const int lk = (tid & 3) * 4;
    const int brow = tid >> 4;
    const int bcol = (tid & 15) * 4;

    const int kBeg = split * (T_ / 2);
    for (int k0 = kBeg; k0 < kBeg + T_ / 2; k0 += GBK) {
#pragma unroll
        for (int i = 0; i < 2; i++) {
            int r = lr + i * 64;
            int t = bm + r;
            long ao = (long)t * T_ + k0 + lk;
            float4 v = *reinterpret_cast<const float4*>(A0 + ao);
            float4 w = *reinterpret_cast<const float4*>(A1 + ao);
            float vv[4] = {v.x + w.x, v.y + w.y, v.z + w.z, v.w + w.w};
#pragma unroll
            for (int j = 0; j < 4; j++) {
                int L = t - (k0 + lk + j);
                As[lk + j][r] = (L > 0) ? vv[j] * g_DEC[L] : 0.f;   // /65536 baked into g_DEC
            }
        }
        {
            float4 v = *reinterpret_cast<const float4*>(B + (long)(k0 + brow) * D_ + bn + bcol);
            Bs[brow][bcol + 0] = v.x; Bs[brow][bcol + 1] = v.y;
            Bs[brow][bcol + 2] = v.z; Bs[brow][bcol + 3] = v.w;
        }
        __syncthreads();
#pragma unroll
        for (int kk = 0; kk < GBK; kk++) {
            float af[GTM], bf[GTN];
#pragma unroll
            for (int i = 0; i < GTM; i++) af[i] = As[kk][ty * GTM + i];
#pragma unroll
            for (int j = 0; j < GTN; j++) bf[j] = Bs[kk][tx * GTN + j];
#pragma unroll
            for (int i = 0; i < GTM; i++)
#pragma unroll
                for (int j = 0; j < GTN; j++)
                    acc[i][j] = fmaf(af[i], bf[j], acc[i][j]);
        }
        __syncthreads();
    }
#pragma unroll
    for (int i = 0; i < GTM; i++) {
        int row = bm + ty * GTM + i;
        long cbase = (long)row * D_ + bn + tx * GTN;
        *reinterpret_cast<float4*>(C + cbase) = make_float4(acc[i][0], acc[i][1], acc[i][2], acc[i][3]);
    }
}

// ---------------- elementwise / scan / LN kernels ----------------
__device__ __forceinline__ float blockReduceSum256(float v) {
    __shared__ float sh[8];
    __syncthreads();
    int lane = threadIdx.x & 31;
    int w = threadIdx.x >> 5;
#pragma unroll
    for (int o = 16; o > 0; o >>= 1) v += __shfl_down_sync(0xffffffffu, v, o);
    if (lane == 0) sh[w] = v;
    __syncthreads();
    if (w == 0) {
        float t = (lane < 8) ? sh[lane] : 0.f;
#pragma unroll
        for (int o = 4; o > 0; o >>= 1) t += __shfl_down_sync(0xffffffffu, t, o);
        if (lane == 0) sh[0] = t;
    }
    __syncthreads();
    return sh[0];
}

// fused conversions: Dx x16, Dy x64, E x64 -> fp16 single; + g_DEC init
__global__ void conv_all_kernel(const float* __restrict__ Dx, const float* __restrict__ Dy,
                                const float* __restrict__ E)
{
    int blk = blockIdx.x;
    const float* src;
    __half* hi;
    float scale;
    int local;
    if (blk < 1024)      { src = Dx; hi = g_DxH; scale = 16.f; local = blk; }
    else if (blk < 2048) { src = Dy; hi = g_DyH; scale = 64.f; local = blk - 1024; }
    else                 { src = E;  hi = g_EH;  scale = 64.f; local = blk - 2048; }
    long i = (long)local * 256 + threadIdx.x;
    float4 v = reinterpret_cast<const float4*>(src)[i];
    ushort4 o = make_ushort4(
        __half_as_ushort(__float2half_rn(v.x * scale)),
        __half_as_ushort(__float2half_rn(v.y * scale)),
        __half_as_ushort(__float2half_rn(v.z * scale)),
        __half_as_ushort(__float2half_rn(v.w * scale)));
    reinterpret_cast<ushort4*>(hi)[i] = o;
    if (blk == 0 && threadIdx.x == 0) {
        float d = 1.f;
        for (int t = 0; t < T_; t++) { g_DEC[t] = d * (1.f / 65536.f); d *= DECF; }
    }
}

// gather 16*emb[idx] -> fp16 single, and zero g_CS
__global__ void gatherconv_kernel(const float* __restrict__ emb, const int* __restrict__ idx)
{
    int m = blockIdx.x;
    int t = threadIdx.x;   // 64 threads, float4 each
    if (t == 0) g_CS[m] = 0.f;
    float4 v = *reinterpret_cast<const float4*>(emb + (long)idx[m] * D_ + t * 4);
    ushort4 o = make_ushort4(
        __half_as_ushort(__float2half_rn(v.x * 16.f)),
        __half_as_ushort(__float2half_rn(v.y * 16.f)),
        __half_as_ushort(__float2half_rn(v.z * 16.f)),
        __half_as_ushort(__float2half_rn(v.w * 16.f)));
    reinterpret_cast<ushort4*>(g_Vf)[(long)m * (D_ / 4) + t] = o;
}

__global__ void screc_kernel() {
    __shared__ float cs[B_ * T_];     // [t][b] layout, conflict-free
    for (int i = threadIdx.x; i < B_ * T_; i += 256) {
        int t = i >> 5, b = i & 31;
        cs[t * 32 + b] = g_CS[b * T_ + t] * (1.f / 256.f);   // unscale 256*P
    }
    __syncthreads();
    if (threadIdx.x < B_) {
        int b = threadIdx.x;
        float sprev = 0.f;
        for (int t = 0; t < T_; t++) {
            float sumx = __fdividef(sprev, sprev + EPSF);
            float s = DECF * sumx + cs[t * 32 + b];
            g_Cc[b * T_ + t] = __fdividef(1.f, s + EPSF);
            sprev = s;
        }
    }
}

// scan on 256-scaled values (linear in scale): X = 256*x
__global__ void xrecur_kernel() {
    int b = blockIdx.y;
    int n = blockIdx.x * 256 + threadIdx.x;
    __shared__ float sc[T_];
    sc[threadIdx.x] = g_Cc[b * T_ + threadIdx.x];
    __syncthreads();
    float X = 0.f;
    long base = (long)b * T_ * N_ + n;
    for (int t = 0; t < T_; t++) {
        float p = __half2float(g_Yf[base + (long)t * N_]);    // 256*P
        X = (DECF * X + p) * sc[t];
        g_Xf[base + (long)t * N_] = __float2half_rn(X);
    }
}

// OUT: 0 = fp32, 1 = fp16 single
template <int OUT, int NPART>
__global__ void ln_rows(const float* __restrict__ in, float* __restrict__ outf,
                        unsigned short* __restrict__ oh,
                        const int* __restrict__ gidx, float inscale)
{
    int m = blockIdx.x;
    long r = gidx ? (long)gidx[m] : (long)m;
    float z = in[r * D_ + threadIdx.x];
#pragma unroll
    for (int p = 1; p < NPART; p++)
        z += in[(long)p * M_ * D_ + r * D_ + threadIdx.x];
    z *= inscale;
    float mean = blockReduceSum256(z) * (1.f / D_);
    float d = z - mean;
    float var = blockReduceSum256(d * d) * (1.f / (D_ - 1));
    float v = d / (sqrtf(var) + EPSF);
    long o = (long)m * D_ + threadIdx.x;
    if (OUT == 1) {
        oh[o] = __half_as_ushort(__float2half_rn(v));
    } else {
        outf[o] = v;
    }
}

// ---------------- launch ----------------
extern "C" void kernel_launch(void* const* d_in, const int* in_sizes, int n_in,
                              void* d_out, int out_size)
{
    (void)in_sizes; (void)n_in; (void)out_size;
    const int*   idx  = (const int*)d_in[0];
    const float* temb = (const float*)d_in[1];
    const float* E    = (const float*)d_in[2];
    const float* Dx   = (const float*)d_in[3];
    const float* Dy   = (const float*)d_in[4];
    float* out = (float*)d_out;

    float *pU, *pS, *pA, *pO;
    __half *pVf, *pDxH, *pDyH, *pEH, *pAf, *pXf, *pYf;
    cudaGetSymbolAddress((void**)&pU,  g_U);
    cudaGetSymbolAddress((void**)&pS,  g_S);
    cudaGetSymbolAddress((void**)&pA,  g_A);
    cudaGetSymbolAddress((void**)&pO,  g_O);
    cudaGetSymbolAddress((void**)&pVf, g_Vf);
    cudaGetSymbolAddress((void**)&pDxH, g_DxH);
    cudaGetSymbolAddress((void**)&pDyH, g_DyH);
    cudaGetSymbolAddress((void**)&pEH, g_EH);
    cudaGetSymbolAddress((void**)&pAf, g_Af);
    cudaGetSymbolAddress((void**)&pXf, g_Xf);
    cudaGetSymbolAddress((void**)&pYf, g_Yf);

    cudaFuncSetAttribute(mma_nt<EPI_RELUH, false>,
                         cudaFuncAttributeMaxDynamicSharedMemorySize, SMEM_SZ);
    cudaFuncSetAttribute(mma_nt<EPI_NONE, true>,
                         cudaFuncAttributeMaxDynamicSharedMemorySize, SMEM_SZ);
    cudaFuncSetAttribute(mma_nt<EPI_RELUMULX, false>,
                         cudaFuncAttributeMaxDynamicSharedMemorySize, SMEM_SZ);
    cudaFuncSetAttribute(mma_nt<EPI_NONE, false>,
                         cudaFuncAttributeMaxDynamicSharedMemorySize, SMEM_SZ);

    // fused conversions (+g_DEC)
    conv_all_kernel<<<3072, 256>>>(Dx, Dy, E);
    // embedding gather/convert (+g_CS zero)
    gatherconv_kernel<<<M_, 64>>>(temb, idx);
    // U = LN(emb[idx])
    ln_rows<0, 1><<<M_, 256>>>(temb, pU, nullptr, idx, 1.f);

    // G1 (fp16 single-pass): 256*P = relu((16v) @ (16Dx)^T) -> g_Yf (fp16), row-sum -> g_CS
    mma_nt<EPI_RELUH, false><<<dim3(N_ / 128, M_ / 128, 1), 256, SMEM_SZ>>>(
        pVf, pDxH, nullptr, pYf, nullptr,
        N_, D_, D_, 0, 0, 0, 0, 1);

    // scalar L1 recurrence + parallel x scan (on 256-scaled P); emits 256*x fp16
    screc_kernel<<<1, 256>>>();
    xrecur_kernel<<<dim3(N_ / 256, B_, 1), 256>>>();

    // scores (65536*raw, split-K x2, single-pass fp16; positive sums)
    mma_nt<EPI_NONE, true><<<dim3(T_ / 128, T_ / 128, 2 * B_), 256, SMEM_SZ>>>(
        pXf, pXf, pS, nullptr, nullptr,
        T_, N_, N_ / 2, (long)T_ * N_, (long)T_ * N_, (long)T_ * T_,
        (long)B_ * T_ * T_, B_);

    // a* = (decayed (S0+S1)/65536) @ U  (SIMT fp32, split-K x2; decay+mask+unscale fused)
    gemm_nn<<<dim3(D_ / GBN, T_ / GBM, 2 * B_), 256>>>(
        pS, pS + (long)B_ * T_ * T_, pU, pA);

    // a* <- LN(sum of 2 partials) -> fp16 single
    ln_rows<1, 2><<<M_, 256>>>(pA, nullptr, (unsigned short*)pAf, nullptr, 1.f);

    // G2 (fp16 single-pass): 1024y = relu(LN(a*) @ (64Dy)^T) * (256x) / 16 -> g_Yf
    mma_nt<EPI_RELUMULX, false><<<dim3(N_ / 128, M_ / 128, 1), 256, SMEM_SZ>>>(
        pAf, pDyH, nullptr, pYf, pXf,
        N_, D_, D_, 0, 0, 0, 0, 1);

    // G3 (fp16 single-pass, split-K x2): o_p = (1024y) @ (64E)^T -> g_O partials (65536*o)
    mma_nt<EPI_NONE, false><<<dim3(D_ / 128, M_ / 128, 2), 256, SMEM_SZ>>>(
        pYf, pEH, pO, nullptr, nullptr,
        D_, N_, N_ / 2, 0, 0, 0, (long)M_ * D_, 1);

    // out = LN((sum of 2 partials) / 65536)
    ln_rows<0, 2><<<M_, 256>>>(pO, out, nullptr, nullptr, 1.f / 65536.f);
}